// round 5
// baseline (speedup 1.0000x reference)
#include <cuda_runtime.h>
#include <math.h>

#define B  2
#define C  128
#define C4 32
#define T  512
#define Fd 256
#define EPS 1e-5f
#define QT 128
#define NEG -1.0e30f

// ---- scratch (static device memory; no allocation allowed) ----
__device__ float g_w12s[C * 64];      // fused+scaled w1|w2, layout [c][64]
__device__ float g_b12s[64];
__device__ float g_w3s[C4 * C];       // scaled w3, layout [c][128]
__device__ float g_b3s[C];
__device__ float g_x1[B * T * Fd * C4];   // [b][t][f][c]
__device__ float g_x2[B * Fd * T * C4];   // [b][f][t][c]
__device__ float g_of[B * Fd * T * C4];   // [b][f][t][c]
__device__ float g_M [B * Fd * T * C4];   // [b][f][t][c]

// ---------------------------------------------------------------------------
// Prep: fold BatchNorm into conv weights/biases.
// ---------------------------------------------------------------------------
__global__ void prep_kernel(const float* __restrict__ w1, const float* __restrict__ g1,
                            const float* __restrict__ b1, const float* __restrict__ m1,
                            const float* __restrict__ v1,
                            const float* __restrict__ w2, const float* __restrict__ g2,
                            const float* __restrict__ b2, const float* __restrict__ m2,
                            const float* __restrict__ v2,
                            const float* __restrict__ w3, const float* __restrict__ g3,
                            const float* __restrict__ b3, const float* __restrict__ m3,
                            const float* __restrict__ v3) {
    int total = C * 64 + C4 * C + 64 + C;
    for (int i = blockIdx.x * blockDim.x + threadIdx.x; i < total;
         i += gridDim.x * blockDim.x) {
        if (i < C * 64) {
            int c = i / 64, o = i % 64;
            float s, w;
            if (o < 32) { s = g1[o] * rsqrtf(v1[o] + EPS); w = w1[o * C + c]; }
            else        { int o2 = o - 32; s = g2[o2] * rsqrtf(v2[o2] + EPS); w = w2[o2 * C + c]; }
            g_w12s[c * 64 + o] = w * s;
        } else if (i < C * 64 + C4 * C) {
            int j = i - C * 64;
            int c = j / C, o = j % C;
            float s = g3[o] * rsqrtf(v3[o] + EPS);
            g_w3s[c * C + o] = w3[o * C4 + c] * s;
        } else if (i < C * 64 + C4 * C + 64) {
            int o = i - C * 64 - C4 * C;
            if (o < 32) { float s = g1[o] * rsqrtf(v1[o] + EPS); g_b12s[o] = b1[o] - m1[o] * s; }
            else        { int o2 = o - 32; float s = g2[o2] * rsqrtf(v2[o2] + EPS); g_b12s[o] = b2[o2] - m2[o2] * s; }
        } else {
            int o = i - C * 64 - C4 * C - 64;
            float s = g3[o] * rsqrtf(v3[o] + EPS);
            g_b3s[o] = b3[o] - m3[o] * s;
        }
    }
}

// ---------------------------------------------------------------------------
// Fused pointwise conv 1+2 (+BN +PReLU)
// ---------------------------------------------------------------------------
__global__ void conv12_kernel(const float* __restrict__ x,
                              const float* __restrict__ a1p,
                              const float* __restrict__ a2p) {
    __shared__ float sw[C * 64];
    __shared__ float sb[64];
    int tid = threadIdx.x;
    for (int i = tid; i < C * 64; i += 256) sw[i] = g_w12s[i];
    if (tid < 64) sb[tid] = g_b12s[tid];
    __syncthreads();

    int idx = blockIdx.x * 256 + tid;
    int f = idx % Fd;
    int t = (idx / Fd) % T;
    int b = idx / (Fd * T);

    float acc[64];
#pragma unroll
    for (int o = 0; o < 64; o++) acc[o] = sb[o];

    const float* xp = x + (b * C) * (T * Fd) + t * Fd + f;
#pragma unroll 2
    for (int c = 0; c < C; c++) {
        float xc = xp[c * (T * Fd)];
        const float4* wp = (const float4*)(&sw[c * 64]);
#pragma unroll
        for (int o4 = 0; o4 < 16; o4++) {
            float4 w = wp[o4];
            acc[o4 * 4 + 0] += xc * w.x;
            acc[o4 * 4 + 1] += xc * w.y;
            acc[o4 * 4 + 2] += xc * w.z;
            acc[o4 * 4 + 3] += xc * w.w;
        }
    }
    float a1 = a1p[0], a2 = a2p[0];

    float4* p1 = (float4*)(&g_x1[((b * T + t) * Fd + f) * C4]);
#pragma unroll
    for (int o4 = 0; o4 < 8; o4++) {
        float4 v; float y;
        y = acc[o4 * 4 + 0]; v.x = y >= 0.f ? y : a1 * y;
        y = acc[o4 * 4 + 1]; v.y = y >= 0.f ? y : a1 * y;
        y = acc[o4 * 4 + 2]; v.z = y >= 0.f ? y : a1 * y;
        y = acc[o4 * 4 + 3]; v.w = y >= 0.f ? y : a1 * y;
        p1[o4] = v;
    }
    float4* p2 = (float4*)(&g_x2[((b * Fd + f) * T + t) * C4]);
#pragma unroll
    for (int o4 = 0; o4 < 8; o4++) {
        float4 v; float y;
        y = acc[32 + o4 * 4 + 0]; v.x = y >= 0.f ? y : a2 * y;
        y = acc[32 + o4 * 4 + 1]; v.y = y >= 0.f ? y : a2 * y;
        y = acc[32 + o4 * 4 + 2]; v.z = y >= 0.f ? y : a2 * y;
        y = acc[32 + o4 * 4 + 3]; v.w = y >= 0.f ? y : a2 * y;
        p2[o4] = v;
    }
}

// ---------------------------------------------------------------------------
// Frequency attention (non-causal), time_attn-style structure:
// block = (b*T+t, qtile of 128 queries), 128 threads, chunk-8 softmax.
// K == V == X rows, so a single smem tile serves both. No masking needed.
// ---------------------------------------------------------------------------
__global__ void freq_attn_kernel() {
    __shared__ float Ks[QT * C4];   // 16 KB
    int blk = blockIdx.x;
    int qt  = blk & 1;            // Fd/QT = 2 q-tiles
    int bt  = blk >> 1;           // b*T + t
    int tid = threadIdx.x;        // 0..127
    int f   = qt * QT + tid;
    int base1 = bt * (Fd * C4);   // g_x1 [b][t][f][c]

    float q[C4];
    const float4* qs = (const float4*)(&g_x1[base1 + f * C4]);
#pragma unroll
    for (int c4 = 0; c4 < 8; c4++) {
        float4 v = qs[c4];
        q[c4 * 4 + 0] = v.x; q[c4 * 4 + 1] = v.y;
        q[c4 * 4 + 2] = v.z; q[c4 * 4 + 3] = v.w;
    }

    float mx = -3.0e38f, l = 0.f;
    float acc[C4];
#pragma unroll
    for (int c = 0; c < C4; c++) acc[c] = 0.f;

    const float inv = 1.0f / 128.0f;   // 1/sqrt(C*F/2)

    for (int st = 0; st < Fd / QT; st++) {
        __syncthreads();
        {
            const float4* ks = (const float4*)(&g_x1[base1 + st * QT * C4]);
            float4* K4 = (float4*)Ks;
#pragma unroll
            for (int i = 0; i < 8; i++) K4[tid + i * 128] = ks[tid + i * 128];
        }
        __syncthreads();

        for (int s0 = 0; s0 < QT; s0 += 8) {
            float sc8[8];
#pragma unroll
            for (int j = 0; j < 8; j++) {
                const float4* kp = (const float4*)(&Ks[(s0 + j) * C4]);
                float sv = 0.f;
#pragma unroll
                for (int c4 = 0; c4 < 8; c4++) {
                    float4 k = kp[c4];
                    sv += q[c4 * 4 + 0] * k.x + q[c4 * 4 + 1] * k.y
                        + q[c4 * 4 + 2] * k.z + q[c4 * 4 + 3] * k.w;
                }
                sc8[j] = sv * inv;
            }
            float cm = sc8[0];
#pragma unroll
            for (int j = 1; j < 8; j++) cm = fmaxf(cm, sc8[j]);
            float nm = fmaxf(mx, cm);
            float sc = __expf(mx - nm);
            l *= sc;
#pragma unroll
            for (int c = 0; c < C4; c++) acc[c] *= sc;
            mx = nm;
#pragma unroll
            for (int j = 0; j < 8; j++) {
                float p = __expf(sc8[j] - nm);
                l += p;
                const float4* vp = (const float4*)(&Ks[(s0 + j) * C4]);
#pragma unroll
                for (int c4 = 0; c4 < 8; c4++) {
                    float4 v = vp[c4];
                    acc[c4 * 4 + 0] += p * v.x;
                    acc[c4 * 4 + 1] += p * v.y;
                    acc[c4 * 4 + 2] += p * v.z;
                    acc[c4 * 4 + 3] += p * v.w;
                }
            }
        }
    }

    int b = bt / T;
    int t = bt % T;
    float rl = 1.f / l;
    float4* dst = (float4*)(&g_of[((b * Fd + f) * T + t) * C4]);
#pragma unroll
    for (int c4 = 0; c4 < 8; c4++) {
        float4 v;
        v.x = acc[c4 * 4 + 0] * rl; v.y = acc[c4 * 4 + 1] * rl;
        v.z = acc[c4 * 4 + 2] * rl; v.w = acc[c4 * 4 + 3] * rl;
        dst[c4] = v;
    }
}

// ---------------------------------------------------------------------------
// Causal time attention, chunked softmax + q-tile blocks for load balance.
// Block = (b*Fd+f, qtile); 128 threads; thread owns query row t=qt*128+tid.
// ---------------------------------------------------------------------------
__global__ void time_attn_kernel() {
    __shared__ float Ks[(QT + 8) * C4];   // 17 KB
    __shared__ float Vs[(QT + 8) * C4];   // 17 KB
    int blk = blockIdx.x;
    int qt  = blk & 3;            // T/QT = 4 q-tiles
    int bf  = blk >> 2;           // b*Fd + f
    int tid = threadIdx.x;        // 0..127
    int t   = qt * QT + tid;
    int base = bf * (T * C4);

    if (tid < 64) {
        ((float4*)(Ks + QT * C4))[tid] = make_float4(0.f, 0.f, 0.f, 0.f);
        ((float4*)(Vs + QT * C4))[tid] = make_float4(0.f, 0.f, 0.f, 0.f);
    }

    float q[C4];
    const float4* qs = (const float4*)(&g_x2[base + t * C4]);
#pragma unroll
    for (int c4 = 0; c4 < 8; c4++) {
        float4 v = qs[c4];
        q[c4 * 4 + 0] = v.x; q[c4 * 4 + 1] = v.y;
        q[c4 * 4 + 2] = v.z; q[c4 * 4 + 3] = v.w;
    }

    float mx = -3.0e38f, l = 0.f;
    float acc[C4];
#pragma unroll
    for (int c = 0; c < C4; c++) acc[c] = 0.f;

    const float inv = 0.005524271728019903f;  // 1/sqrt(C*T/2) = 2^-7.5

    for (int st = 0; st <= qt; st++) {
        __syncthreads();
        {
            const float4* ks = (const float4*)(&g_x2[base + st * QT * C4]);
            const float4* vs = (const float4*)(&g_of[base + st * QT * C4]);
            float4* K4 = (float4*)Ks;
            float4* V4 = (float4*)Vs;
#pragma unroll
            for (int i = 0; i < 8; i++) {
                K4[tid + i * 128] = ks[tid + i * 128];
                V4[tid + i * 128] = vs[tid + i * 128];
            }
        }
        __syncthreads();

        int send = (st < qt) ? QT : (tid + 1);   // exclusive count of valid rows
        for (int s0 = 0; s0 < send; s0 += 8) {
            float sc8[8];
#pragma unroll
            for (int j = 0; j < 8; j++) {
                int sl = s0 + j;                 // may exceed send; pad rows are zero
                const float4* kp = (const float4*)(&Ks[sl * C4]);
                float sv = 0.f;
#pragma unroll
                for (int c4 = 0; c4 < 8; c4++) {
                    float4 k = kp[c4];
                    sv += q[c4 * 4 + 0] * k.x + q[c4 * 4 + 1] * k.y
                        + q[c4 * 4 + 2] * k.z + q[c4 * 4 + 3] * k.w;
                }
                sc8[j] = (sl < send) ? sv * inv : NEG;
            }
            float cm = sc8[0];
#pragma unroll
            for (int j = 1; j < 8; j++) cm = fmaxf(cm, sc8[j]);
            float nm = fmaxf(mx, cm);
            float sc = __expf(mx - nm);
            l *= sc;
#pragma unroll
            for (int c = 0; c < C4; c++) acc[c] *= sc;
            mx = nm;
#pragma unroll
            for (int j = 0; j < 8; j++) {
                float p = __expf(sc8[j] - nm);
                l += p;
                const float4* vp = (const float4*)(&Vs[(s0 + j) * C4]);
#pragma unroll
                for (int c4 = 0; c4 < 8; c4++) {
                    float4 v = vp[c4];
                    acc[c4 * 4 + 0] += p * v.x;
                    acc[c4 * 4 + 1] += p * v.y;
                    acc[c4 * 4 + 2] += p * v.z;
                    acc[c4 * 4 + 3] += p * v.w;
                }
            }
        }
    }

    float rl = 1.f / l;
    float4* dst = (float4*)(&g_M[base + t * C4]);
#pragma unroll
    for (int c4 = 0; c4 < 8; c4++) {
        float4 v;
        v.x = acc[c4 * 4 + 0] * rl; v.y = acc[c4 * 4 + 1] * rl;
        v.z = acc[c4 * 4 + 2] * rl; v.w = acc[c4 * 4 + 3] * rl;
        dst[c4] = v;
    }
}

// ---------------------------------------------------------------------------
// Final pointwise conv (+BN +PReLU) + residual. float4-vectorized over o.
// ---------------------------------------------------------------------------
__global__ void final_kernel(const float* __restrict__ x,
                             const float* __restrict__ a3p,
                             float* __restrict__ out) {
    __shared__ float sw[C4 * C];   // layout [c][128]
    __shared__ float sb[C];
    int tid = threadIdx.x;
    for (int i = tid; i < C4 * C; i += 256) sw[i] = g_w3s[i];
    if (tid < C) sb[tid] = g_b3s[tid];
    __syncthreads();

    int idx = blockIdx.x * 256 + tid;
    int f = idx % Fd;
    int t = (idx / Fd) % T;
    int b = idx / (Fd * T);

    float Ml[C4];
    const float4* ms = (const float4*)(&g_M[((b * Fd + f) * T + t) * C4]);
#pragma unroll
    for (int c4 = 0; c4 < 8; c4++) {
        float4 m = ms[c4];
        Ml[c4 * 4 + 0] = m.x; Ml[c4 * 4 + 1] = m.y;
        Ml[c4 * 4 + 2] = m.z; Ml[c4 * 4 + 3] = m.w;
    }
    float a3 = a3p[0];
    int xbase = (b * C) * (T * Fd) + t * Fd + f;
    const float4* sw4 = (const float4*)sw;     // [c][32] float4 rows
    const float4* sb4 = (const float4*)sb;
#pragma unroll 2
    for (int o4 = 0; o4 < C / 4; o4++) {
        float4 bb = sb4[o4];
        float y0 = bb.x, y1 = bb.y, y2 = bb.z, y3 = bb.w;
#pragma unroll
        for (int c = 0; c < C4; c++) {
            float4 w = sw4[c * (C / 4) + o4];
            float m = Ml[c];
            y0 += m * w.x; y1 += m * w.y; y2 += m * w.z; y3 += m * w.w;
        }
        y0 = y0 >= 0.f ? y0 : a3 * y0;
        y1 = y1 >= 0.f ? y1 : a3 * y1;
        y2 = y2 >= 0.f ? y2 : a3 * y2;
        y3 = y3 >= 0.f ? y3 : a3 * y3;
        int o = o4 * 4;
        out[xbase + (o + 0) * (T * Fd)] = y0 + x[xbase + (o + 0) * (T * Fd)];
        out[xbase + (o + 1) * (T * Fd)] = y1 + x[xbase + (o + 1) * (T * Fd)];
        out[xbase + (o + 2) * (T * Fd)] = y2 + x[xbase + (o + 2) * (T * Fd)];
        out[xbase + (o + 3) * (T * Fd)] = y3 + x[xbase + (o + 3) * (T * Fd)];
    }
}

// ---------------------------------------------------------------------------
extern "C" void kernel_launch(void* const* d_in, const int* in_sizes, int n_in,
                              void* d_out, int out_size) {
    const float* x  = (const float*)d_in[0];
    const float* w1 = (const float*)d_in[1];
    const float* g1 = (const float*)d_in[2];
    const float* b1 = (const float*)d_in[3];
    const float* m1 = (const float*)d_in[4];
    const float* v1 = (const float*)d_in[5];
    const float* a1 = (const float*)d_in[6];
    const float* w2 = (const float*)d_in[7];
    const float* g2 = (const float*)d_in[8];
    const float* b2 = (const float*)d_in[9];
    const float* m2 = (const float*)d_in[10];
    const float* v2 = (const float*)d_in[11];
    const float* a2 = (const float*)d_in[12];
    const float* w3 = (const float*)d_in[13];
    const float* g3 = (const float*)d_in[14];
    const float* b3 = (const float*)d_in[15];
    const float* m3 = (const float*)d_in[16];
    const float* v3 = (const float*)d_in[17];
    const float* a3 = (const float*)d_in[18];
    float* out = (float*)d_out;

    prep_kernel<<<16, 256>>>(w1, g1, b1, m1, v1, w2, g2, b2, m2, v2,
                             w3, g3, b3, m3, v3);
    conv12_kernel<<<(B * T * Fd) / 256, 256>>>(x, a1, a2);
    freq_attn_kernel<<<B * T * (Fd / QT), QT>>>();
    time_attn_kernel<<<B * Fd * (T / QT), QT>>>();
    final_kernel<<<(B * T * Fd) / 256, 256>>>(x, a3, out);
}

// round 6
// speedup vs baseline: 2.0125x; 2.0125x over previous
#include <cuda_runtime.h>
#include <math.h>

#define B  2
#define C  128
#define C4 32
#define T  512
#define Fd 256
#define EPS 1e-5f
#define KTP 36    // K-tile row pad (floats): bank coeff 4 -> conflict-free S B-frags
#define VTP 40    // V-tile row pad: bank coeff 8 -> conflict-free PV B-frags
#define STP 132   // S^T row pad: bank coeff 4
#define PTP 37    // P row pad: bank coeff 5

// ---- scratch (static device memory; no allocation allowed) ----
__device__ float g_w12s[C * 64];
__device__ float g_b12s[64];
__device__ float g_w3s[C4 * C];
__device__ float g_b3s[C];
__device__ float g_x1[B * T * Fd * C4];   // [b][t][f][c]
__device__ float g_x2[B * Fd * T * C4];   // [b][f][t][c]
__device__ float g_of[B * Fd * T * C4];   // [b][f][t][c]
__device__ float g_M [B * Fd * T * C4];   // [b][f][t][c]

// ---------------------------------------------------------------------------
__device__ __forceinline__ unsigned f2tf(float f) {
    unsigned u;
    asm("cvt.rna.tf32.f32 %0, %1;" : "=r"(u) : "f"(f));
    return u;
}

__device__ __forceinline__ void mma8(float d[4], const unsigned a[4], const unsigned b[2]) {
    asm volatile(
        "mma.sync.aligned.m16n8k8.row.col.f32.tf32.tf32.f32 "
        "{%0,%1,%2,%3},{%4,%5,%6,%7},{%8,%9},{%0,%1,%2,%3};"
        : "+f"(d[0]), "+f"(d[1]), "+f"(d[2]), "+f"(d[3])
        : "r"(a[0]), "r"(a[1]), "r"(a[2]), "r"(a[3]), "r"(b[0]), "r"(b[1]));
}

// ---------------------------------------------------------------------------
// Prep: fold BatchNorm into conv weights/biases.
// ---------------------------------------------------------------------------
__global__ void prep_kernel(const float* __restrict__ w1, const float* __restrict__ g1,
                            const float* __restrict__ b1, const float* __restrict__ m1,
                            const float* __restrict__ v1,
                            const float* __restrict__ w2, const float* __restrict__ g2,
                            const float* __restrict__ b2, const float* __restrict__ m2,
                            const float* __restrict__ v2,
                            const float* __restrict__ w3, const float* __restrict__ g3,
                            const float* __restrict__ b3, const float* __restrict__ m3,
                            const float* __restrict__ v3) {
    int total = C * 64 + C4 * C + 64 + C;
    for (int i = blockIdx.x * blockDim.x + threadIdx.x; i < total;
         i += gridDim.x * blockDim.x) {
        if (i < C * 64) {
            int c = i / 64, o = i % 64;
            float s, w;
            if (o < 32) { s = g1[o] * rsqrtf(v1[o] + EPS); w = w1[o * C + c]; }
            else        { int o2 = o - 32; s = g2[o2] * rsqrtf(v2[o2] + EPS); w = w2[o2 * C + c]; }
            g_w12s[c * 64 + o] = w * s;
        } else if (i < C * 64 + C4 * C) {
            int j = i - C * 64;
            int c = j / C, o = j % C;
            float s = g3[o] * rsqrtf(v3[o] + EPS);
            g_w3s[c * C + o] = w3[o * C4 + c] * s;
        } else if (i < C * 64 + C4 * C + 64) {
            int o = i - C * 64 - C4 * C;
            if (o < 32) { float s = g1[o] * rsqrtf(v1[o] + EPS); g_b12s[o] = b1[o] - m1[o] * s; }
            else        { int o2 = o - 32; float s = g2[o2] * rsqrtf(v2[o2] + EPS); g_b12s[o] = b2[o2] - m2[o2] * s; }
        } else {
            int o = i - C * 64 - C4 * C - 64;
            float s = g3[o] * rsqrtf(v3[o] + EPS);
            g_b3s[o] = b3[o] - m3[o] * s;
        }
    }
}

// ---------------------------------------------------------------------------
// Fused pointwise conv 1+2 (+BN +PReLU)  (unchanged from R4)
// ---------------------------------------------------------------------------
__global__ void conv12_kernel(const float* __restrict__ x,
                              const float* __restrict__ a1p,
                              const float* __restrict__ a2p) {
    __shared__ float sw[C * 64];
    __shared__ float sb[64];
    int tid = threadIdx.x;
    for (int i = tid; i < C * 64; i += 256) sw[i] = g_w12s[i];
    if (tid < 64) sb[tid] = g_b12s[tid];
    __syncthreads();

    int idx = blockIdx.x * 256 + tid;
    int f = idx % Fd;
    int t = (idx / Fd) % T;
    int b = idx / (Fd * T);

    float acc[64];
#pragma unroll
    for (int o = 0; o < 64; o++) acc[o] = sb[o];

    const float* xp = x + (b * C) * (T * Fd) + t * Fd + f;
#pragma unroll 2
    for (int c = 0; c < C; c++) {
        float xc = xp[c * (T * Fd)];
        const float4* wp = (const float4*)(&sw[c * 64]);
#pragma unroll
        for (int o4 = 0; o4 < 16; o4++) {
            float4 w = wp[o4];
            acc[o4 * 4 + 0] += xc * w.x;
            acc[o4 * 4 + 1] += xc * w.y;
            acc[o4 * 4 + 2] += xc * w.z;
            acc[o4 * 4 + 3] += xc * w.w;
        }
    }
    float a1 = a1p[0], a2 = a2p[0];

    float4* p1 = (float4*)(&g_x1[((b * T + t) * Fd + f) * C4]);
#pragma unroll
    for (int o4 = 0; o4 < 8; o4++) {
        float4 v; float y;
        y = acc[o4 * 4 + 0]; v.x = y >= 0.f ? y : a1 * y;
        y = acc[o4 * 4 + 1]; v.y = y >= 0.f ? y : a1 * y;
        y = acc[o4 * 4 + 2]; v.z = y >= 0.f ? y : a1 * y;
        y = acc[o4 * 4 + 3]; v.w = y >= 0.f ? y : a1 * y;
        p1[o4] = v;
    }
    float4* p2 = (float4*)(&g_x2[((b * Fd + f) * T + t) * C4]);
#pragma unroll
    for (int o4 = 0; o4 < 8; o4++) {
        float4 v; float y;
        y = acc[32 + o4 * 4 + 0]; v.x = y >= 0.f ? y : a2 * y;
        y = acc[32 + o4 * 4 + 1]; v.y = y >= 0.f ? y : a2 * y;
        y = acc[32 + o4 * 4 + 2]; v.z = y >= 0.f ? y : a2 * y;
        y = acc[32 + o4 * 4 + 3]; v.w = y >= 0.f ? y : a2 * y;
        p2[o4] = v;
    }
}

// ---------------------------------------------------------------------------
// Frequency attention via tf32 mma. Block = (b*T+t, fq-tile of 128).
// 4 warps, warp owns 32 query rows. K == V == x1 rows (one tile, dbl-buffered).
// S fragments -> smem S^T -> per-thread softmax -> P smem -> PV mma.
// Scale 1/128 folded into Q fragments (exact power of 2).
// ---------------------------------------------------------------------------
__global__ void __launch_bounds__(128) freq_attn_kernel() {
    __shared__ unsigned sKT[2][32 * KTP];
    __shared__ float    sST[32 * STP];
    __shared__ unsigned sPT[128 * PTP];
    __shared__ float    sSC[128];
    __shared__ float    sRL[128];

    int blk = blockIdx.x;
    int qt = blk & 1, bt = blk >> 1;
    int tid = threadIdx.x, w = tid >> 5, lane = tid & 31;
    int grp = lane >> 2, tig = lane & 3;
    int base = bt * (Fd * C4);
    int fbase = qt * 128;
    const float inv = 1.0f / 128.0f;

    // Q fragments (scaled)
    unsigned qf[2][4][4];
#pragma unroll
    for (int m = 0; m < 2; m++) {
        const float* q0 = &g_x1[base + (fbase + w * 32 + m * 16 + grp) * C4];
        const float* q1 = q0 + 8 * C4;
#pragma unroll
        for (int k = 0; k < 4; k++) {
            qf[m][k][0] = f2tf(q0[k * 8 + tig] * inv);
            qf[m][k][1] = f2tf(q1[k * 8 + tig] * inv);
            qf[m][k][2] = f2tf(q0[k * 8 + tig + 4] * inv);
            qf[m][k][3] = f2tf(q1[k * 8 + tig + 4] * inv);
        }
    }
    float of[2][4][4];
#pragma unroll
    for (int m = 0; m < 2; m++)
#pragma unroll
        for (int n = 0; n < 4; n++)
#pragma unroll
            for (int r = 0; r < 4; r++) of[m][n][r] = 0.f;
    float mx = -3.0e38f, l = 0.f;

    // preload chunk 0
    {
        const float4* src = (const float4*)&g_x1[base];
#pragma unroll
        for (int j = 0; j < 2; j++) {
            int i = tid + j * 128;
            float4 v = src[i];
            int row = i >> 3, c4 = i & 7;
            uint4 u;
            u.x = f2tf(v.x); u.y = f2tf(v.y); u.z = f2tf(v.z); u.w = f2tf(v.w);
            *(uint4*)&sKT[0][row * KTP + c4 * 4] = u;
        }
    }
    int buf = 0;
    for (int c = 0; c < 8; c++) {
        __syncthreads();
        if (c < 7) {
            const float4* src = (const float4*)&g_x1[base + (c + 1) * 32 * C4];
#pragma unroll
            for (int j = 0; j < 2; j++) {
                int i = tid + j * 128;
                float4 v = src[i];
                int row = i >> 3, c4 = i & 7;
                uint4 u;
                u.x = f2tf(v.x); u.y = f2tf(v.y); u.z = f2tf(v.z); u.w = f2tf(v.w);
                *(uint4*)&sKT[buf ^ 1][row * KTP + c4 * 4] = u;
            }
        }
        // S = (Q*inv) K^T
        float sf[2][4][4];
#pragma unroll
        for (int m = 0; m < 2; m++)
#pragma unroll
            for (int n = 0; n < 4; n++)
#pragma unroll
                for (int r = 0; r < 4; r++) sf[m][n][r] = 0.f;
#pragma unroll
        for (int n = 0; n < 4; n++) {
#pragma unroll
            for (int k = 0; k < 4; k++) {
                const unsigned* kb = &sKT[buf][(n * 8 + grp) * KTP + k * 8 + tig];
                unsigned bfr[2] = { kb[0], kb[4] };
                mma8(sf[0][n], qf[0][k], bfr);
                mma8(sf[1][n], qf[1][k], bfr);
            }
        }
        // S^T -> smem
#pragma unroll
        for (int m = 0; m < 2; m++) {
            int q0 = w * 32 + m * 16 + grp;
#pragma unroll
            for (int n = 0; n < 4; n++) {
                int sr = n * 8 + 2 * tig;
                sST[sr * STP + q0]           = sf[m][n][0];
                sST[(sr + 1) * STP + q0]     = sf[m][n][1];
                sST[sr * STP + q0 + 8]       = sf[m][n][2];
                sST[(sr + 1) * STP + q0 + 8] = sf[m][n][3];
            }
        }
        __syncthreads();
        // per-thread softmax, query col = tid
        float cm = -3.0e38f;
#pragma unroll
        for (int sl = 0; sl < 32; sl++) cm = fmaxf(cm, sST[sl * STP + tid]);
        float nm = fmaxf(mx, cm);
        float sc = __expf(mx - nm);
        l *= sc; mx = nm;
        sSC[tid] = sc;
#pragma unroll
        for (int sl = 0; sl < 32; sl++) {
            float p = __expf(sST[sl * STP + tid] - nm);
            l += p;
            sPT[tid * PTP + sl] = f2tf(p);
        }
        __syncthreads();
        // rescale O + PV mma
#pragma unroll
        for (int m = 0; m < 2; m++) {
            float s0v = sSC[w * 32 + m * 16 + grp];
            float s1v = sSC[w * 32 + m * 16 + grp + 8];
#pragma unroll
            for (int n = 0; n < 4; n++) {
                of[m][n][0] *= s0v; of[m][n][1] *= s0v;
                of[m][n][2] *= s1v; of[m][n][3] *= s1v;
            }
        }
        unsigned pf[2][4][4];
#pragma unroll
        for (int m = 0; m < 2; m++) {
            int q0 = w * 32 + m * 16 + grp;
#pragma unroll
            for (int k = 0; k < 4; k++) {
                pf[m][k][0] = sPT[q0 * PTP + k * 8 + tig];
                pf[m][k][1] = sPT[(q0 + 8) * PTP + k * 8 + tig];
                pf[m][k][2] = sPT[q0 * PTP + k * 8 + tig + 4];
                pf[m][k][3] = sPT[(q0 + 8) * PTP + k * 8 + tig + 4];
            }
        }
#pragma unroll
        for (int n = 0; n < 4; n++) {
#pragma unroll
            for (int k = 0; k < 4; k++) {
                unsigned vb[2];
                vb[0] = sKT[buf][(k * 8 + tig) * KTP + n * 8 + grp];
                vb[1] = sKT[buf][(k * 8 + tig + 4) * KTP + n * 8 + grp];
                mma8(of[0][n], pf[0][k], vb);
                mma8(of[1][n], pf[1][k], vb);
            }
        }
        buf ^= 1;
    }
    sRL[tid] = 1.0f / l;
    __syncthreads();
    int b = bt / T, t = bt % T;
#pragma unroll
    for (int m = 0; m < 2; m++) {
        int ql = w * 32 + m * 16 + grp;
        float r0 = sRL[ql], r1 = sRL[ql + 8];
        float* d0 = &g_of[((b * Fd + fbase + ql) * T + t) * C4];
        float* d1 = &g_of[((b * Fd + fbase + ql + 8) * T + t) * C4];
#pragma unroll
        for (int n = 0; n < 4; n++) {
            int ch = n * 8 + 2 * tig;
            *(float2*)&d0[ch] = make_float2(of[m][n][0] * r0, of[m][n][1] * r0);
            *(float2*)&d1[ch] = make_float2(of[m][n][2] * r1, of[m][n][3] * r1);
        }
    }
}

// ---------------------------------------------------------------------------
// Causal time attention via tf32 mma. Block = (b*Fd+f, q-tile of 128).
// K = x2 rows, V = of rows. Warp-level triangle skip + per-thread diag mask.
// ---------------------------------------------------------------------------
__global__ void __launch_bounds__(128) time_attn_kernel() {
    __shared__ unsigned sKT[32 * KTP];
    __shared__ unsigned sVT[32 * VTP];
    __shared__ float    sST[32 * STP];
    __shared__ unsigned sPT[128 * PTP];
    __shared__ float    sSC[128];
    __shared__ float    sRL[128];

    int blk = blockIdx.x;
    int qt = blk & 3, bf = blk >> 2;
    int tid = threadIdx.x, w = tid >> 5, lane = tid & 31;
    int grp = lane >> 2, tig = lane & 3;
    int base = bf * (T * C4);
    int qbase = qt * 128;
    const float inv = 0.005524271728019903f;  // 2^-7.5

    unsigned qf[2][4][4];
#pragma unroll
    for (int m = 0; m < 2; m++) {
        const float* q0 = &g_x2[base + (qbase + w * 32 + m * 16 + grp) * C4];
        const float* q1 = q0 + 8 * C4;
#pragma unroll
        for (int k = 0; k < 4; k++) {
            qf[m][k][0] = f2tf(q0[k * 8 + tig] * inv);
            qf[m][k][1] = f2tf(q1[k * 8 + tig] * inv);
            qf[m][k][2] = f2tf(q0[k * 8 + tig + 4] * inv);
            qf[m][k][3] = f2tf(q1[k * 8 + tig + 4] * inv);
        }
    }
    float of[2][4][4];
#pragma unroll
    for (int m = 0; m < 2; m++)
#pragma unroll
        for (int n = 0; n < 4; n++)
#pragma unroll
            for (int r = 0; r < 4; r++) of[m][n][r] = 0.f;
    float mx = -3.0e38f, l = 0.f;

    int nch = (qt + 1) * 4;
    for (int c = 0; c < nch; c++) {
        __syncthreads();   // prev-iter PV tile reads complete before overwrite
        {
            const float4* ks = (const float4*)&g_x2[base + c * 32 * C4];
            const float4* vs = (const float4*)&g_of[base + c * 32 * C4];
#pragma unroll
            for (int j = 0; j < 2; j++) {
                int i = tid + j * 128;
                float4 kv = ks[i];
                float4 vv = vs[i];
                int row = i >> 3, c4 = i & 7;
                uint4 ku, vu;
                ku.x = f2tf(kv.x); ku.y = f2tf(kv.y); ku.z = f2tf(kv.z); ku.w = f2tf(kv.w);
                vu.x = f2tf(vv.x); vu.y = f2tf(vv.y); vu.z = f2tf(vv.z); vu.w = f2tf(vv.w);
                *(uint4*)&sKT[row * KTP + c4 * 4] = ku;
                *(uint4*)&sVT[row * VTP + c4 * 4] = vu;
            }
        }
        __syncthreads();
        bool active = (c <= qt * 4 + w);
        if (active) {
            float sf[2][4][4];
#pragma unroll
            for (int m = 0; m < 2; m++)
#pragma unroll
                for (int n = 0; n < 4; n++)
#pragma unroll
                    for (int r = 0; r < 4; r++) sf[m][n][r] = 0.f;
#pragma unroll
            for (int n = 0; n < 4; n++) {
#pragma unroll
                for (int k = 0; k < 4; k++) {
                    const unsigned* kb = &sKT[(n * 8 + grp) * KTP + k * 8 + tig];
                    unsigned bfr[2] = { kb[0], kb[4] };
                    mma8(sf[0][n], qf[0][k], bfr);
                    mma8(sf[1][n], qf[1][k], bfr);
                }
            }
#pragma unroll
            for (int m = 0; m < 2; m++) {
                int q0 = w * 32 + m * 16 + grp;
#pragma unroll
                for (int n = 0; n < 4; n++) {
                    int sr = n * 8 + 2 * tig;
                    sST[sr * STP + q0]           = sf[m][n][0];
                    sST[(sr + 1) * STP + q0]     = sf[m][n][1];
                    sST[sr * STP + q0 + 8]       = sf[m][n][2];
                    sST[(sr + 1) * STP + q0 + 8] = sf[m][n][3];
                }
            }
        }
        __syncthreads();
        if (active) {
            int lim = (qbase + tid) - c * 32;     // valid sl <= lim
            float cm = -3.0e38f;
            if (lim >= 31) {
#pragma unroll
                for (int sl = 0; sl < 32; sl++) cm = fmaxf(cm, sST[sl * STP + tid]);
                float nm = fmaxf(mx, cm);
                float sc = __expf(mx - nm);
                l *= sc; mx = nm;
                sSC[tid] = sc;
#pragma unroll
                for (int sl = 0; sl < 32; sl++) {
                    float p = __expf(sST[sl * STP + tid] - nm);
                    l += p;
                    sPT[tid * PTP + sl] = f2tf(p);
                }
            } else {
#pragma unroll
                for (int sl = 0; sl < 32; sl++)
                    if (sl <= lim) cm = fmaxf(cm, sST[sl * STP + tid]);
                float nm = fmaxf(mx, cm);
                float sc = __expf(mx - nm);
                l *= sc; mx = nm;
                sSC[tid] = sc;
#pragma unroll
                for (int sl = 0; sl < 32; sl++) {
                    float p = (sl <= lim) ? __expf(sST[sl * STP + tid] - nm) : 0.f;
                    l += p;
                    sPT[tid * PTP + sl] = f2tf(p);
                }
            }
        }
        __syncthreads();
        if (active) {
#pragma unroll
            for (int m = 0; m < 2; m++) {
                float s0v = sSC[w * 32 + m * 16 + grp];
                float s1v = sSC[w * 32 + m * 16 + grp + 8];
#pragma unroll
                for (int n = 0; n < 4; n++) {
                    of[m][n][0] *= s0v; of[m][n][1] *= s0v;
                    of[m][n][2] *= s1v; of[m][n][3] *= s1v;
                }
            }
            unsigned pf[2][4][4];
#pragma unroll
            for (int m = 0; m < 2; m++) {
                int q0 = w * 32 + m * 16 + grp;
#pragma unroll
                for (int k = 0; k < 4; k++) {
                    pf[m][k][0] = sPT[q0 * PTP + k * 8 + tig];
                    pf[m][k][1] = sPT[(q0 + 8) * PTP + k * 8 + tig];
                    pf[m][k][2] = sPT[q0 * PTP + k * 8 + tig + 4];
                    pf[m][k][3] = sPT[(q0 + 8) * PTP + k * 8 + tig + 4];
                }
            }
#pragma unroll
            for (int n = 0; n < 4; n++) {
#pragma unroll
                for (int k = 0; k < 4; k++) {
                    unsigned vb[2];
                    vb[0] = sVT[(k * 8 + tig) * VTP + n * 8 + grp];
                    vb[1] = sVT[(k * 8 + tig + 4) * VTP + n * 8 + grp];
                    mma8(of[0][n], pf[0][k], vb);
                    mma8(of[1][n], pf[1][k], vb);
                }
            }
        }
    }
    sRL[tid] = 1.0f / l;
    __syncthreads();
#pragma unroll
    for (int m = 0; m < 2; m++) {
        int ql = w * 32 + m * 16 + grp;
        float r0 = sRL[ql], r1 = sRL[ql + 8];
        float* d0 = &g_M[base + (qbase + ql) * C4];
        float* d1 = &g_M[base + (qbase + ql + 8) * C4];
#pragma unroll
        for (int n = 0; n < 4; n++) {
            int ch = n * 8 + 2 * tig;
            *(float2*)&d0[ch] = make_float2(of[m][n][0] * r0, of[m][n][1] * r0);
            *(float2*)&d1[ch] = make_float2(of[m][n][2] * r1, of[m][n][3] * r1);
        }
    }
}

// ---------------------------------------------------------------------------
// Final pointwise conv (+BN +PReLU) + residual. (unchanged from R4)
// ---------------------------------------------------------------------------
__global__ void final_kernel(const float* __restrict__ x,
                             const float* __restrict__ a3p,
                             float* __restrict__ out) {
    __shared__ float sw[C4 * C];
    __shared__ float sb[C];
    int tid = threadIdx.x;
    for (int i = tid; i < C4 * C; i += 256) sw[i] = g_w3s[i];
    if (tid < C) sb[tid] = g_b3s[tid];
    __syncthreads();

    int idx = blockIdx.x * 256 + tid;
    int f = idx % Fd;
    int t = (idx / Fd) % T;
    int b = idx / (Fd * T);

    float Ml[C4];
    const float4* ms = (const float4*)(&g_M[((b * Fd + f) * T + t) * C4]);
#pragma unroll
    for (int c4 = 0; c4 < 8; c4++) {
        float4 m = ms[c4];
        Ml[c4 * 4 + 0] = m.x; Ml[c4 * 4 + 1] = m.y;
        Ml[c4 * 4 + 2] = m.z; Ml[c4 * 4 + 3] = m.w;
    }
    float a3 = a3p[0];
    int xbase = (b * C) * (T * Fd) + t * Fd + f;
    const float4* sw4 = (const float4*)sw;
    const float4* sb4 = (const float4*)sb;
#pragma unroll 2
    for (int o4 = 0; o4 < C / 4; o4++) {
        float4 bb = sb4[o4];
        float y0 = bb.x, y1 = bb.y, y2 = bb.z, y3 = bb.w;
#pragma unroll
        for (int c = 0; c < C4; c++) {
            float4 w = sw4[c * (C / 4) + o4];
            float m = Ml[c];
            y0 += m * w.x; y1 += m * w.y; y2 += m * w.z; y3 += m * w.w;
        }
        y0 = y0 >= 0.f ? y0 : a3 * y0;
        y1 = y1 >= 0.f ? y1 : a3 * y1;
        y2 = y2 >= 0.f ? y2 : a3 * y2;
        y3 = y3 >= 0.f ? y3 : a3 * y3;
        int o = o4 * 4;
        out[xbase + (o + 0) * (T * Fd)] = y0 + x[xbase + (o + 0) * (T * Fd)];
        out[xbase + (o + 1) * (T * Fd)] = y1 + x[xbase + (o + 1) * (T * Fd)];
        out[xbase + (o + 2) * (T * Fd)] = y2 + x[xbase + (o + 2) * (T * Fd)];
        out[xbase + (o + 3) * (T * Fd)] = y3 + x[xbase + (o + 3) * (T * Fd)];
    }
}

// ---------------------------------------------------------------------------
extern "C" void kernel_launch(void* const* d_in, const int* in_sizes, int n_in,
                              void* d_out, int out_size) {
    const float* x  = (const float*)d_in[0];
    const float* w1 = (const float*)d_in[1];
    const float* g1 = (const float*)d_in[2];
    const float* b1 = (const float*)d_in[3];
    const float* m1 = (const float*)d_in[4];
    const float* v1 = (const float*)d_in[5];
    const float* a1 = (const float*)d_in[6];
    const float* w2 = (const float*)d_in[7];
    const float* g2 = (const float*)d_in[8];
    const float* b2 = (const float*)d_in[9];
    const float* m2 = (const float*)d_in[10];
    const float* v2 = (const float*)d_in[11];
    const float* a2 = (const float*)d_in[12];
    const float* w3 = (const float*)d_in[13];
    const float* g3 = (const float*)d_in[14];
    const float* b3 = (const float*)d_in[15];
    const float* m3 = (const float*)d_in[16];
    const float* v3 = (const float*)d_in[17];
    const float* a3 = (const float*)d_in[18];
    float* out = (float*)d_out;

    prep_kernel<<<16, 256>>>(w1, g1, b1, m1, v1, w2, g2, b2, m2, v2,
                             w3, g3, b3, m3, v3);
    conv12_kernel<<<(B * T * Fd) / 256, 256>>>(x, a1, a2);
    freq_attn_kernel<<<B * T * 2, 128>>>();
    time_attn_kernel<<<B * Fd * 4, 128>>>();
    final_kernel<<<(B * T * Fd) / 256, 256>>>(x, a3, out);
}

// round 7
// speedup vs baseline: 3.2446x; 1.6122x over previous
#include <cuda_runtime.h>
#include <math.h>

#define B  2
#define C  128
#define C4 32
#define T  512
#define Fd 256
#define TF (T * Fd)
#define EPS 1e-5f
#define KTP 36    // K-tile row pad (floats): bank coeff 4 -> conflict-free S B-frags
#define VTP 40    // V-tile row pad: bank coeff 8 -> conflict-free PV B-frags
#define STP 132   // S^T row pad: bank coeff 4
#define PTP 37    // P row pad: bank coeff 5
#define WP  36    // conv12 weight row pad: banks 4*grp+tig distinct
#define XP  136   // conv12 x-tile row pad: banks 8*tig+grp distinct

// ---- scratch (static device memory; no allocation allowed) ----
__device__ unsigned g_w12t[64 * C];   // fused+scaled w1|w2, tf32, layout [o][c]
__device__ float g_b12s[64];
__device__ float g_w3s[C4 * C];       // scaled w3, layout [c][128]
__device__ float g_b3s[C];
__device__ float g_x1[B * T * Fd * C4];   // [b][t][f][c]
__device__ float g_x2[B * Fd * T * C4];   // [b][f][t][c]
__device__ float g_of[B * Fd * T * C4];   // [b][f][t][c]
__device__ float g_M [B * Fd * T * C4];   // [b][f][t][c]

// ---------------------------------------------------------------------------
__device__ __forceinline__ unsigned f2tf(float f) {
    unsigned u;
    asm("cvt.rna.tf32.f32 %0, %1;" : "=r"(u) : "f"(f));
    return u;
}

__device__ __forceinline__ void mma8(float d[4], const unsigned a[4], const unsigned b[2]) {
    asm volatile(
        "mma.sync.aligned.m16n8k8.row.col.f32.tf32.tf32.f32 "
        "{%0,%1,%2,%3},{%4,%5,%6,%7},{%8,%9},{%0,%1,%2,%3};"
        : "+f"(d[0]), "+f"(d[1]), "+f"(d[2]), "+f"(d[3])
        : "r"(a[0]), "r"(a[1]), "r"(a[2]), "r"(a[3]), "r"(b[0]), "r"(b[1]));
}

// ---------------------------------------------------------------------------
// Prep: fold BatchNorm into conv weights/biases. Conv12 weights are stored
// transposed [o][c] and pre-converted to tf32.
// ---------------------------------------------------------------------------
__global__ void prep_kernel(const float* __restrict__ w1, const float* __restrict__ g1,
                            const float* __restrict__ b1, const float* __restrict__ m1,
                            const float* __restrict__ v1,
                            const float* __restrict__ w2, const float* __restrict__ g2,
                            const float* __restrict__ b2, const float* __restrict__ m2,
                            const float* __restrict__ v2,
                            const float* __restrict__ w3, const float* __restrict__ g3,
                            const float* __restrict__ b3, const float* __restrict__ m3,
                            const float* __restrict__ v3) {
    int total = 64 * C + C4 * C + 64 + C;
    for (int i = blockIdx.x * blockDim.x + threadIdx.x; i < total;
         i += gridDim.x * blockDim.x) {
        if (i < 64 * C) {
            int o = i >> 7, c = i & 127;
            float s, w;
            if (o < 32) { s = g1[o] * rsqrtf(v1[o] + EPS); w = w1[o * C + c]; }
            else        { int o2 = o - 32; s = g2[o2] * rsqrtf(v2[o2] + EPS); w = w2[o2 * C + c]; }
            g_w12t[o * C + c] = f2tf(w * s);
        } else if (i < 64 * C + C4 * C) {
            int j = i - 64 * C;
            int c = j / C, o = j % C;
            float s = g3[o] * rsqrtf(v3[o] + EPS);
            g_w3s[c * C + o] = w3[o * C4 + c] * s;
        } else if (i < 64 * C + C4 * C + 64) {
            int o = i - 64 * C - C4 * C;
            if (o < 32) { float s = g1[o] * rsqrtf(v1[o] + EPS); g_b12s[o] = b1[o] - m1[o] * s; }
            else        { int o2 = o - 32; float s = g2[o2] * rsqrtf(v2[o2] + EPS); g_b12s[o] = b2[o2] - m2[o2] * s; }
        } else {
            int o = i - 64 * C - C4 * C - 64;
            float s = g3[o] * rsqrtf(v3[o] + EPS);
            g_b3s[o] = b3[o] - m3[o] * s;
        }
    }
}

// ---------------------------------------------------------------------------
// Fused pointwise conv 1+2 (+BN +PReLU) via tf32 mma.
// Block = 128 consecutive spatial positions (pos, all in one b). 4 warps,
// warp w owns output channels [w*16, w*16+16); all 128 positions.
// A = weights [64][128] (row-major), B = x tile [k=32 chunk][pos 128]
// (native col-major, no transpose). k-chunked x4.
// ---------------------------------------------------------------------------
__global__ void __launch_bounds__(128) conv12_kernel(const float* __restrict__ x,
                                                     const float* __restrict__ a1p,
                                                     const float* __restrict__ a2p) {
    __shared__ unsigned sw[64 * WP];    // weights chunk [o][32 k], pad 36
    __shared__ unsigned xs[32 * XP];    // x chunk [k][128 pos], pad 136

    int tid = threadIdx.x, w = tid >> 5, lane = tid & 31;
    int grp = lane >> 2, tig = lane & 3;
    int s0 = blockIdx.x * 128;
    int b = s0 >> 17;                   // TF = 2^17
    int sb = s0 & (TF - 1);
    const float* xb = x + (size_t)b * C * TF + sb;

    float of[16][4];
    {
        float bi0 = g_b12s[w * 16 + grp];
        float bi1 = g_b12s[w * 16 + grp + 8];
#pragma unroll
        for (int nt = 0; nt < 16; nt++) {
            of[nt][0] = bi0; of[nt][1] = bi0;
            of[nt][2] = bi1; of[nt][3] = bi1;
        }
    }

    for (int ch = 0; ch < 4; ch++) {
        __syncthreads();
        // weights chunk: g_w12t[o][ch*32 + kk], coalesced, conflict-free store
#pragma unroll
        for (int j = 0; j < 16; j++) {
            int i = tid + j * 128;
            int o = i >> 5, kk = i & 31;
            sw[o * WP + kk] = g_w12t[o * C + ch * 32 + kk];
        }
        // x chunk: 32 channels x 128 pos, float4 coalesced along pos
#pragma unroll
        for (int j = 0; j < 8; j++) {
            int i = tid + j * 128;
            int cc = i >> 5, p4 = i & 31;
            float4 v = *(const float4*)(xb + (size_t)(ch * 32 + cc) * TF + p4 * 4);
            uint4 u;
            u.x = f2tf(v.x); u.y = f2tf(v.y); u.z = f2tf(v.z); u.w = f2tf(v.w);
            *(uint4*)&xs[cc * XP + p4 * 4] = u;
        }
        __syncthreads();

#pragma unroll
        for (int ks = 0; ks < 4; ks++) {
            unsigned af[4];
            af[0] = sw[(w * 16 + grp) * WP + ks * 8 + tig];
            af[1] = sw[(w * 16 + grp + 8) * WP + ks * 8 + tig];
            af[2] = sw[(w * 16 + grp) * WP + ks * 8 + tig + 4];
            af[3] = sw[(w * 16 + grp + 8) * WP + ks * 8 + tig + 4];
#pragma unroll
            for (int nt = 0; nt < 16; nt++) {
                unsigned bf[2];
                bf[0] = xs[(ks * 8 + tig) * XP + nt * 8 + grp];
                bf[1] = xs[(ks * 8 + tig + 4) * XP + nt * 8 + grp];
                mma8(of[nt], af, bf);
            }
        }
    }

    // epilogue: PReLU + scattered stores
    float a = (w < 2) ? a1p[0] : a2p[0];
    int ch0 = w * 16 + grp;
    if (w < 2) {
        // x1 channels: g_x1[s*32 + o]
#pragma unroll
        for (int nt = 0; nt < 16; nt++) {
            int pos = s0 + nt * 8 + 2 * tig;
            float y;
            y = of[nt][0]; y = y >= 0.f ? y : a * y; g_x1[(size_t)pos * 32 + ch0] = y;
            y = of[nt][1]; y = y >= 0.f ? y : a * y; g_x1[(size_t)(pos + 1) * 32 + ch0] = y;
            y = of[nt][2]; y = y >= 0.f ? y : a * y; g_x1[(size_t)pos * 32 + ch0 + 8] = y;
            y = of[nt][3]; y = y >= 0.f ? y : a * y; g_x1[(size_t)(pos + 1) * 32 + ch0 + 8] = y;
        }
    } else {
        int o2 = ch0 - 32;
#pragma unroll
        for (int nt = 0; nt < 16; nt++) {
            int pos = s0 + nt * 8 + 2 * tig;
            int t0 = (pos >> 8) & 511, f0 = pos & 255;
            int i0 = ((b * Fd + f0) * T + t0) * 32;
            int t1 = ((pos + 1) >> 8) & 511, f1 = (pos + 1) & 255;
            int i1 = ((b * Fd + f1) * T + t1) * 32;
            float y;
            y = of[nt][0]; y = y >= 0.f ? y : a * y; g_x2[i0 + o2] = y;
            y = of[nt][1]; y = y >= 0.f ? y : a * y; g_x2[i1 + o2] = y;
            y = of[nt][2]; y = y >= 0.f ? y : a * y; g_x2[i0 + o2 + 8] = y;
            y = of[nt][3]; y = y >= 0.f ? y : a * y; g_x2[i1 + o2 + 8] = y;
        }
    }
}

// ---------------------------------------------------------------------------
// Frequency attention via tf32 mma (unchanged from R6).
// ---------------------------------------------------------------------------
__global__ void __launch_bounds__(128) freq_attn_kernel() {
    __shared__ unsigned sKT[2][32 * KTP];
    __shared__ float    sST[32 * STP];
    __shared__ unsigned sPT[128 * PTP];
    __shared__ float    sSC[128];
    __shared__ float    sRL[128];

    int blk = blockIdx.x;
    int qt = blk & 1, bt = blk >> 1;
    int tid = threadIdx.x, w = tid >> 5, lane = tid & 31;
    int grp = lane >> 2, tig = lane & 3;
    int base = bt * (Fd * C4);
    int fbase = qt * 128;
    const float inv = 1.0f / 128.0f;

    unsigned qf[2][4][4];
#pragma unroll
    for (int m = 0; m < 2; m++) {
        const float* q0 = &g_x1[base + (fbase + w * 32 + m * 16 + grp) * C4];
        const float* q1 = q0 + 8 * C4;
#pragma unroll
        for (int k = 0; k < 4; k++) {
            qf[m][k][0] = f2tf(q0[k * 8 + tig] * inv);
            qf[m][k][1] = f2tf(q1[k * 8 + tig] * inv);
            qf[m][k][2] = f2tf(q0[k * 8 + tig + 4] * inv);
            qf[m][k][3] = f2tf(q1[k * 8 + tig + 4] * inv);
        }
    }
    float of[2][4][4];
#pragma unroll
    for (int m = 0; m < 2; m++)
#pragma unroll
        for (int n = 0; n < 4; n++)
#pragma unroll
            for (int r = 0; r < 4; r++) of[m][n][r] = 0.f;
    float mx = -3.0e38f, l = 0.f;

    {
        const float4* src = (const float4*)&g_x1[base];
#pragma unroll
        for (int j = 0; j < 2; j++) {
            int i = tid + j * 128;
            float4 v = src[i];
            int row = i >> 3, c4 = i & 7;
            uint4 u;
            u.x = f2tf(v.x); u.y = f2tf(v.y); u.z = f2tf(v.z); u.w = f2tf(v.w);
            *(uint4*)&sKT[0][row * KTP + c4 * 4] = u;
        }
    }
    int buf = 0;
    for (int c = 0; c < 8; c++) {
        __syncthreads();
        if (c < 7) {
            const float4* src = (const float4*)&g_x1[base + (c + 1) * 32 * C4];
#pragma unroll
            for (int j = 0; j < 2; j++) {
                int i = tid + j * 128;
                float4 v = src[i];
                int row = i >> 3, c4 = i & 7;
                uint4 u;
                u.x = f2tf(v.x); u.y = f2tf(v.y); u.z = f2tf(v.z); u.w = f2tf(v.w);
                *(uint4*)&sKT[buf ^ 1][row * KTP + c4 * 4] = u;
            }
        }
        float sf[2][4][4];
#pragma unroll
        for (int m = 0; m < 2; m++)
#pragma unroll
            for (int n = 0; n < 4; n++)
#pragma unroll
                for (int r = 0; r < 4; r++) sf[m][n][r] = 0.f;
#pragma unroll
        for (int n = 0; n < 4; n++) {
#pragma unroll
            for (int k = 0; k < 4; k++) {
                const unsigned* kb = &sKT[buf][(n * 8 + grp) * KTP + k * 8 + tig];
                unsigned bfr[2] = { kb[0], kb[4] };
                mma8(sf[0][n], qf[0][k], bfr);
                mma8(sf[1][n], qf[1][k], bfr);
            }
        }
#pragma unroll
        for (int m = 0; m < 2; m++) {
            int q0 = w * 32 + m * 16 + grp;
#pragma unroll
            for (int n = 0; n < 4; n++) {
                int sr = n * 8 + 2 * tig;
                sST[sr * STP + q0]           = sf[m][n][0];
                sST[(sr + 1) * STP + q0]     = sf[m][n][1];
                sST[sr * STP + q0 + 8]       = sf[m][n][2];
                sST[(sr + 1) * STP + q0 + 8] = sf[m][n][3];
            }
        }
        __syncthreads();
        float cm = -3.0e38f;
#pragma unroll
        for (int sl = 0; sl < 32; sl++) cm = fmaxf(cm, sST[sl * STP + tid]);
        float nm = fmaxf(mx, cm);
        float sc = __expf(mx - nm);
        l *= sc; mx = nm;
        sSC[tid] = sc;
#pragma unroll
        for (int sl = 0; sl < 32; sl++) {
            float p = __expf(sST[sl * STP + tid] - nm);
            l += p;
            sPT[tid * PTP + sl] = f2tf(p);
        }
        __syncthreads();
#pragma unroll
        for (int m = 0; m < 2; m++) {
            float s0v = sSC[w * 32 + m * 16 + grp];
            float s1v = sSC[w * 32 + m * 16 + grp + 8];
#pragma unroll
            for (int n = 0; n < 4; n++) {
                of[m][n][0] *= s0v; of[m][n][1] *= s0v;
                of[m][n][2] *= s1v; of[m][n][3] *= s1v;
            }
        }
        unsigned pf[2][4][4];
#pragma unroll
        for (int m = 0; m < 2; m++) {
            int q0 = w * 32 + m * 16 + grp;
#pragma unroll
            for (int k = 0; k < 4; k++) {
                pf[m][k][0] = sPT[q0 * PTP + k * 8 + tig];
                pf[m][k][1] = sPT[(q0 + 8) * PTP + k * 8 + tig];
                pf[m][k][2] = sPT[q0 * PTP + k * 8 + tig + 4];
                pf[m][k][3] = sPT[(q0 + 8) * PTP + k * 8 + tig + 4];
            }
        }
#pragma unroll
        for (int n = 0; n < 4; n++) {
#pragma unroll
            for (int k = 0; k < 4; k++) {
                unsigned vb[2];
                vb[0] = sKT[buf][(k * 8 + tig) * KTP + n * 8 + grp];
                vb[1] = sKT[buf][(k * 8 + tig + 4) * KTP + n * 8 + grp];
                mma8(of[0][n], pf[0][k], vb);
                mma8(of[1][n], pf[1][k], vb);
            }
        }
        buf ^= 1;
    }
    sRL[tid] = 1.0f / l;
    __syncthreads();
    int b = bt / T, t = bt % T;
#pragma unroll
    for (int m = 0; m < 2; m++) {
        int ql = w * 32 + m * 16 + grp;
        float r0 = sRL[ql], r1 = sRL[ql + 8];
        float* d0 = &g_of[((b * Fd + fbase + ql) * T + t) * C4];
        float* d1 = &g_of[((b * Fd + fbase + ql + 8) * T + t) * C4];
#pragma unroll
        for (int n = 0; n < 4; n++) {
            int ch = n * 8 + 2 * tig;
            *(float2*)&d0[ch] = make_float2(of[m][n][0] * r0, of[m][n][1] * r0);
            *(float2*)&d1[ch] = make_float2(of[m][n][2] * r1, of[m][n][3] * r1);
        }
    }
}

// ---------------------------------------------------------------------------
// Causal time attention via tf32 mma (unchanged from R6).
// ---------------------------------------------------------------------------
__global__ void __launch_bounds__(128) time_attn_kernel() {
    __shared__ unsigned sKT[32 * KTP];
    __shared__ unsigned sVT[32 * VTP];
    __shared__ float    sST[32 * STP];
    __shared__ unsigned sPT[128 * PTP];
    __shared__ float    sSC[128];
    __shared__ float    sRL[128];

    int blk = blockIdx.x;
    int qt = blk & 3, bf = blk >> 2;
    int tid = threadIdx.x, w = tid >> 5, lane = tid & 31;
    int grp = lane >> 2, tig = lane & 3;
    int base = bf * (T * C4);
    int qbase = qt * 128;
    const float inv = 0.005524271728019903f;  // 2^-7.5

    unsigned qf[2][4][4];
#pragma unroll
    for (int m = 0; m < 2; m++) {
        const float* q0 = &g_x2[base + (qbase + w * 32 + m * 16 + grp) * C4];
        const float* q1 = q0 + 8 * C4;
#pragma unroll
        for (int k = 0; k < 4; k++) {
            qf[m][k][0] = f2tf(q0[k * 8 + tig] * inv);
            qf[m][k][1] = f2tf(q1[k * 8 + tig] * inv);
            qf[m][k][2] = f2tf(q0[k * 8 + tig + 4] * inv);
            qf[m][k][3] = f2tf(q1[k * 8 + tig + 4] * inv);
        }
    }
    float of[2][4][4];
#pragma unroll
    for (int m = 0; m < 2; m++)
#pragma unroll
        for (int n = 0; n < 4; n++)
#pragma unroll
            for (int r = 0; r < 4; r++) of[m][n][r] = 0.f;
    float mx = -3.0e38f, l = 0.f;

    int nch = (qt + 1) * 4;
    for (int c = 0; c < nch; c++) {
        __syncthreads();
        {
            const float4* ks = (const float4*)&g_x2[base + c * 32 * C4];
            const float4* vs = (const float4*)&g_of[base + c * 32 * C4];
#pragma unroll
            for (int j = 0; j < 2; j++) {
                int i = tid + j * 128;
                float4 kv = ks[i];
                float4 vv = vs[i];
                int row = i >> 3, c4 = i & 7;
                uint4 ku, vu;
                ku.x = f2tf(kv.x); ku.y = f2tf(kv.y); ku.z = f2tf(kv.z); ku.w = f2tf(kv.w);
                vu.x = f2tf(vv.x); vu.y = f2tf(vv.y); vu.z = f2tf(vv.z); vu.w = f2tf(vv.w);
                *(uint4*)&sKT[row * KTP + c4 * 4] = ku;
                *(uint4*)&sVT[row * VTP + c4 * 4] = vu;
            }
        }
        __syncthreads();
        bool active = (c <= qt * 4 + w);
        if (active) {
            float sf[2][4][4];
#pragma unroll
            for (int m = 0; m < 2; m++)
#pragma unroll
                for (int n = 0; n < 4; n++)
#pragma unroll
                    for (int r = 0; r < 4; r++) sf[m][n][r] = 0.f;
#pragma unroll
            for (int n = 0; n < 4; n++) {
#pragma unroll
                for (int k = 0; k < 4; k++) {
                    const unsigned* kb = &sKT[(n * 8 + grp) * KTP + k * 8 + tig];
                    unsigned bfr[2] = { kb[0], kb[4] };
                    mma8(sf[0][n], qf[0][k], bfr);
                    mma8(sf[1][n], qf[1][k], bfr);
                }
            }
#pragma unroll
            for (int m = 0; m < 2; m++) {
                int q0 = w * 32 + m * 16 + grp;
#pragma unroll
                for (int n = 0; n < 4; n++) {
                    int sr = n * 8 + 2 * tig;
                    sST[sr * STP + q0]           = sf[m][n][0];
                    sST[(sr + 1) * STP + q0]     = sf[m][n][1];
                    sST[sr * STP + q0 + 8]       = sf[m][n][2];
                    sST[(sr + 1) * STP + q0 + 8] = sf[m][n][3];
                }
            }
        }
        __syncthreads();
        if (active) {
            int lim = (qbase + tid) - c * 32;
            float cm = -3.0e38f;
            if (lim >= 31) {
#pragma unroll
                for (int sl = 0; sl < 32; sl++) cm = fmaxf(cm, sST[sl * STP + tid]);
                float nm = fmaxf(mx, cm);
                float sc = __expf(mx - nm);
                l *= sc; mx = nm;
                sSC[tid] = sc;
#pragma unroll
                for (int sl = 0; sl < 32; sl++) {
                    float p = __expf(sST[sl * STP + tid] - nm);
                    l += p;
                    sPT[tid * PTP + sl] = f2tf(p);
                }
            } else {
#pragma unroll
                for (int sl = 0; sl < 32; sl++)
                    if (sl <= lim) cm = fmaxf(cm, sST[sl * STP + tid]);
                float nm = fmaxf(mx, cm);
                float sc = __expf(mx - nm);
                l *= sc; mx = nm;
                sSC[tid] = sc;
#pragma unroll
                for (int sl = 0; sl < 32; sl++) {
                    float p = (sl <= lim) ? __expf(sST[sl * STP + tid] - nm) : 0.f;
                    l += p;
                    sPT[tid * PTP + sl] = f2tf(p);
                }
            }
        }
        __syncthreads();
        if (active) {
#pragma unroll
            for (int m = 0; m < 2; m++) {
                float s0v = sSC[w * 32 + m * 16 + grp];
                float s1v = sSC[w * 32 + m * 16 + grp + 8];
#pragma unroll
                for (int n = 0; n < 4; n++) {
                    of[m][n][0] *= s0v; of[m][n][1] *= s0v;
                    of[m][n][2] *= s1v; of[m][n][3] *= s1v;
                }
            }
            unsigned pf[2][4][4];
#pragma unroll
            for (int m = 0; m < 2; m++) {
                int q0 = w * 32 + m * 16 + grp;
#pragma unroll
                for (int k = 0; k < 4; k++) {
                    pf[m][k][0] = sPT[q0 * PTP + k * 8 + tig];
                    pf[m][k][1] = sPT[(q0 + 8) * PTP + k * 8 + tig];
                    pf[m][k][2] = sPT[q0 * PTP + k * 8 + tig + 4];
                    pf[m][k][3] = sPT[(q0 + 8) * PTP + k * 8 + tig + 4];
                }
            }
#pragma unroll
            for (int n = 0; n < 4; n++) {
#pragma unroll
                for (int k = 0; k < 4; k++) {
                    unsigned vb[2];
                    vb[0] = sVT[(k * 8 + tig) * VTP + n * 8 + grp];
                    vb[1] = sVT[(k * 8 + tig + 4) * VTP + n * 8 + grp];
                    mma8(of[0][n], pf[0][k], vb);
                    mma8(of[1][n], pf[1][k], vb);
                }
            }
        }
    }
    sRL[tid] = 1.0f / l;
    __syncthreads();
#pragma unroll
    for (int m = 0; m < 2; m++) {
        int ql = w * 32 + m * 16 + grp;
        float r0 = sRL[ql], r1 = sRL[ql + 8];
        float* d0 = &g_M[base + (qbase + ql) * C4];
        float* d1 = &g_M[base + (qbase + ql + 8) * C4];
#pragma unroll
        for (int n = 0; n < 4; n++) {
            int ch = n * 8 + 2 * tig;
            *(float2*)&d0[ch] = make_float2(of[m][n][0] * r0, of[m][n][1] * r0);
            *(float2*)&d1[ch] = make_float2(of[m][n][2] * r1, of[m][n][3] * r1);
        }
    }
}

// ---------------------------------------------------------------------------
// Final pointwise conv (+BN +PReLU) + residual. (unchanged from R4)
// ---------------------------------------------------------------------------
__global__ void final_kernel(const float* __restrict__ x,
                             const float* __restrict__ a3p,
                             float* __restrict__ out) {
    __shared__ float sw[C4 * C];
    __shared__ float sb[C];
    int tid = threadIdx.x;
    for (int i = tid; i < C4 * C; i += 256) sw[i] = g_w3s[i];
    if (tid < C) sb[tid] = g_b3s[tid];
    __syncthreads();

    int idx = blockIdx.x * 256 + tid;
    int f = idx % Fd;
    int t = (idx / Fd) % T;
    int b = idx / (Fd * T);

    float Ml[C4];
    const float4* ms = (const float4*)(&g_M[((b * Fd + f) * T + t) * C4]);
#pragma unroll
    for (int c4 = 0; c4 < 8; c4++) {
        float4 m = ms[c4];
        Ml[c4 * 4 + 0] = m.x; Ml[c4 * 4 + 1] = m.y;
        Ml[c4 * 4 + 2] = m.z; Ml[c4 * 4 + 3] = m.w;
    }
    float a3 = a3p[0];
    int xbase = (b * C) * (T * Fd) + t * Fd + f;
    const float4* sw4 = (const float4*)sw;
    const float4* sb4 = (const float4*)sb;
#pragma unroll 2
    for (int o4 = 0; o4 < C / 4; o4++) {
        float4 bb = sb4[o4];
        float y0 = bb.x, y1 = bb.y, y2 = bb.z, y3 = bb.w;
#pragma unroll
        for (int c = 0; c < C4; c++) {
            float4 w = sw4[c * (C / 4) + o4];
            float m = Ml[c];
            y0 += m * w.x; y1 += m * w.y; y2 += m * w.z; y3 += m * w.w;
        }
        y0 = y0 >= 0.f ? y0 : a3 * y0;
        y1 = y1 >= 0.f ? y1 : a3 * y1;
        y2 = y2 >= 0.f ? y2 : a3 * y2;
        y3 = y3 >= 0.f ? y3 : a3 * y3;
        int o = o4 * 4;
        out[xbase + (o + 0) * (T * Fd)] = y0 + x[xbase + (o + 0) * (T * Fd)];
        out[xbase + (o + 1) * (T * Fd)] = y1 + x[xbase + (o + 1) * (T * Fd)];
        out[xbase + (o + 2) * (T * Fd)] = y2 + x[xbase + (o + 2) * (T * Fd)];
        out[xbase + (o + 3) * (T * Fd)] = y3 + x[xbase + (o + 3) * (T * Fd)];
    }
}

// ---------------------------------------------------------------------------
extern "C" void kernel_launch(void* const* d_in, const int* in_sizes, int n_in,
                              void* d_out, int out_size) {
    const float* x  = (const float*)d_in[0];
    const float* w1 = (const float*)d_in[1];
    const float* g1 = (const float*)d_in[2];
    const float* b1 = (const float*)d_in[3];
    const float* m1 = (const float*)d_in[4];
    const float* v1 = (const float*)d_in[5];
    const float* a1 = (const float*)d_in[6];
    const float* w2 = (const float*)d_in[7];
    const float* g2 = (const float*)d_in[8];
    const float* b2 = (const float*)d_in[9];
    const float* m2 = (const float*)d_in[10];
    const float* v2 = (const float*)d_in[11];
    const float* a2 = (const float*)d_in[12];
    const float* w3 = (const float*)d_in[13];
    const float* g3 = (const float*)d_in[14];
    const float* b3 = (const float*)d_in[15];
    const float* m3 = (const float*)d_in[16];
    const float* v3 = (const float*)d_in[17];
    const float* a3 = (const float*)d_in[18];
    float* out = (float*)d_out;

    prep_kernel<<<16, 256>>>(w1, g1, b1, m1, v1, w2, g2, b2, m2, v2,
                             w3, g3, b3, m3, v3);
    conv12_kernel<<<(B * T * Fd) / 128, 128>>>(x, a1, a2);
    freq_attn_kernel<<<B * T * 2, 128>>>();
    time_attn_kernel<<<B * Fd * 4, 128>>>();
    final_kernel<<<(B * T * Fd) / 256, 256>>>(x, a3, out);
}

// round 8
// speedup vs baseline: 3.5886x; 1.1060x over previous
#include <cuda_runtime.h>
#include <math.h>

#define B  2
#define C  128
#define C4 32
#define T  512
#define Fd 256
#define TF (T * Fd)
#define EPS 1e-5f
#define KTP 36    // K-tile row pad: S-mma B-frag loads conflict-free
#define VTP 40    // V-tile row pad: PV B-frag loads conflict-free
#define WP  36
#define XP  136
#define NEG -1.0e30f

// ---- scratch (static device memory; no allocation allowed) ----
__device__ unsigned g_w12t[64 * C];   // fused+scaled w1|w2, tf32, layout [o][c]
__device__ float g_b12s[64];
__device__ float g_w3s[C4 * C];
__device__ float g_b3s[C];
__device__ float g_x1[B * T * Fd * C4];   // [b][t][f][c]
__device__ float g_x2[B * Fd * T * C4];   // [b][f][t][c]
__device__ float g_of[B * Fd * T * C4];   // [b][f][t][c]
__device__ float g_M [B * Fd * T * C4];   // [b][f][t][c]

// ---------------------------------------------------------------------------
__device__ __forceinline__ unsigned f2tf(float f) {
    unsigned u;
    asm("cvt.rna.tf32.f32 %0, %1;" : "=r"(u) : "f"(f));
    return u;
}

__device__ __forceinline__ void mma8(float d[4], const unsigned a[4], const unsigned b[2]) {
    asm volatile(
        "mma.sync.aligned.m16n8k8.row.col.f32.tf32.tf32.f32 "
        "{%0,%1,%2,%3},{%4,%5,%6,%7},{%8,%9},{%0,%1,%2,%3};"
        : "+f"(d[0]), "+f"(d[1]), "+f"(d[2]), "+f"(d[3])
        : "r"(a[0]), "r"(a[1]), "r"(a[2]), "r"(a[3]), "r"(b[0]), "r"(b[1]));
}

__device__ __forceinline__ float qmax(float v) {
    v = fmaxf(v, __shfl_xor_sync(0xffffffffu, v, 1));
    v = fmaxf(v, __shfl_xor_sync(0xffffffffu, v, 2));
    return v;
}
__device__ __forceinline__ float qsum(float v) {
    v += __shfl_xor_sync(0xffffffffu, v, 1);
    v += __shfl_xor_sync(0xffffffffu, v, 2);
    return v;
}

// ---------------------------------------------------------------------------
// Prep (unchanged from R7)
// ---------------------------------------------------------------------------
__global__ void prep_kernel(const float* __restrict__ w1, const float* __restrict__ g1,
                            const float* __restrict__ b1, const float* __restrict__ m1,
                            const float* __restrict__ v1,
                            const float* __restrict__ w2, const float* __restrict__ g2,
                            const float* __restrict__ b2, const float* __restrict__ m2,
                            const float* __restrict__ v2,
                            const float* __restrict__ w3, const float* __restrict__ g3,
                            const float* __restrict__ b3, const float* __restrict__ m3,
                            const float* __restrict__ v3) {
    int total = 64 * C + C4 * C + 64 + C;
    for (int i = blockIdx.x * blockDim.x + threadIdx.x; i < total;
         i += gridDim.x * blockDim.x) {
        if (i < 64 * C) {
            int o = i >> 7, c = i & 127;
            float s, w;
            if (o < 32) { s = g1[o] * rsqrtf(v1[o] + EPS); w = w1[o * C + c]; }
            else        { int o2 = o - 32; s = g2[o2] * rsqrtf(v2[o2] + EPS); w = w2[o2 * C + c]; }
            g_w12t[o * C + c] = f2tf(w * s);
        } else if (i < 64 * C + C4 * C) {
            int j = i - 64 * C;
            int c = j / C, o = j % C;
            float s = g3[o] * rsqrtf(v3[o] + EPS);
            g_w3s[c * C + o] = w3[o * C4 + c] * s;
        } else if (i < 64 * C + C4 * C + 64) {
            int o = i - 64 * C - C4 * C;
            if (o < 32) { float s = g1[o] * rsqrtf(v1[o] + EPS); g_b12s[o] = b1[o] - m1[o] * s; }
            else        { int o2 = o - 32; float s = g2[o2] * rsqrtf(v2[o2] + EPS); g_b12s[o] = b2[o2] - m2[o2] * s; }
        } else {
            int o = i - 64 * C - C4 * C - 64;
            float s = g3[o] * rsqrtf(v3[o] + EPS);
            g_b3s[o] = b3[o] - m3[o] * s;
        }
    }
}

// ---------------------------------------------------------------------------
// Fused pointwise conv 1+2 via tf32 mma (unchanged from R7)
// ---------------------------------------------------------------------------
__global__ void __launch_bounds__(128) conv12_kernel(const float* __restrict__ x,
                                                     const float* __restrict__ a1p,
                                                     const float* __restrict__ a2p) {
    __shared__ unsigned sw[64 * WP];
    __shared__ unsigned xs[32 * XP];

    int tid = threadIdx.x, w = tid >> 5, lane = tid & 31;
    int grp = lane >> 2, tig = lane & 3;
    int s0 = blockIdx.x * 128;
    int b = s0 >> 17;
    int sb = s0 & (TF - 1);
    const float* xb = x + (size_t)b * C * TF + sb;

    float of[16][4];
    {
        float bi0 = g_b12s[w * 16 + grp];
        float bi1 = g_b12s[w * 16 + grp + 8];
#pragma unroll
        for (int nt = 0; nt < 16; nt++) {
            of[nt][0] = bi0; of[nt][1] = bi0;
            of[nt][2] = bi1; of[nt][3] = bi1;
        }
    }

    for (int ch = 0; ch < 4; ch++) {
        __syncthreads();
#pragma unroll
        for (int j = 0; j < 16; j++) {
            int i = tid + j * 128;
            int o = i >> 5, kk = i & 31;
            sw[o * WP + kk] = g_w12t[o * C + ch * 32 + kk];
        }
#pragma unroll
        for (int j = 0; j < 8; j++) {
            int i = tid + j * 128;
            int cc = i >> 5, p4 = i & 31;
            float4 v = *(const float4*)(xb + (size_t)(ch * 32 + cc) * TF + p4 * 4);
            uint4 u;
            u.x = f2tf(v.x); u.y = f2tf(v.y); u.z = f2tf(v.z); u.w = f2tf(v.w);
            *(uint4*)&xs[cc * XP + p4 * 4] = u;
        }
        __syncthreads();

#pragma unroll
        for (int ks = 0; ks < 4; ks++) {
            unsigned af[4];
            af[0] = sw[(w * 16 + grp) * WP + ks * 8 + tig];
            af[1] = sw[(w * 16 + grp + 8) * WP + ks * 8 + tig];
            af[2] = sw[(w * 16 + grp) * WP + ks * 8 + tig + 4];
            af[3] = sw[(w * 16 + grp + 8) * WP + ks * 8 + tig + 4];
#pragma unroll
            for (int nt = 0; nt < 16; nt++) {
                unsigned bf[2];
                bf[0] = xs[(ks * 8 + tig) * XP + nt * 8 + grp];
                bf[1] = xs[(ks * 8 + tig + 4) * XP + nt * 8 + grp];
                mma8(of[nt], af, bf);
            }
        }
    }

    float a = (w < 2) ? a1p[0] : a2p[0];
    int ch0 = w * 16 + grp;
    if (w < 2) {
#pragma unroll
        for (int nt = 0; nt < 16; nt++) {
            int pos = s0 + nt * 8 + 2 * tig;
            float y;
            y = of[nt][0]; y = y >= 0.f ? y : a * y; g_x1[(size_t)pos * 32 + ch0] = y;
            y = of[nt][1]; y = y >= 0.f ? y : a * y; g_x1[(size_t)(pos + 1) * 32 + ch0] = y;
            y = of[nt][2]; y = y >= 0.f ? y : a * y; g_x1[(size_t)pos * 32 + ch0 + 8] = y;
            y = of[nt][3]; y = y >= 0.f ? y : a * y; g_x1[(size_t)(pos + 1) * 32 + ch0 + 8] = y;
        }
    } else {
        int o2 = ch0 - 32;
#pragma unroll
        for (int nt = 0; nt < 16; nt++) {
            int pos = s0 + nt * 8 + 2 * tig;
            int t0 = (pos >> 8) & 511, f0 = pos & 255;
            int i0 = ((b * Fd + f0) * T + t0) * 32;
            int t1 = ((pos + 1) >> 8) & 511, f1 = (pos + 1) & 255;
            int i1 = ((b * Fd + f1) * T + t1) * 32;
            float y;
            y = of[nt][0]; y = y >= 0.f ? y : a * y; g_x2[i0 + o2] = y;
            y = of[nt][1]; y = y >= 0.f ? y : a * y; g_x2[i1 + o2] = y;
            y = of[nt][2]; y = y >= 0.f ? y : a * y; g_x2[i0 + o2 + 8] = y;
            y = of[nt][3]; y = y >= 0.f ? y : a * y; g_x2[i1 + o2 + 8] = y;
        }
    }
}

// ---------------------------------------------------------------------------
// Frequency attention, tf32 mma + FRAGMENT-RESIDENT softmax (no S/P smem).
// Block = (b*T+t, fq-tile of 128). K == V == x1 tile, double-buffered.
// ---------------------------------------------------------------------------
__global__ void __launch_bounds__(128, 4) freq_attn_kernel() {
    __shared__ unsigned sKT[2][32 * KTP];

    int blk = blockIdx.x;
    int qt = blk & 1, bt = blk >> 1;
    int tid = threadIdx.x, w = tid >> 5, lane = tid & 31;
    int grp = lane >> 2, tig = lane & 3;
    int lq = lane & ~3;
    int sl0 = lq | (tig >> 1), sl1 = sl0 + 2;
    bool odd = tig & 1;
    int base = bt * (Fd * C4);
    int fbase = qt * 128;
    const float inv = 1.0f / 128.0f;

    unsigned qf[2][4][4];
#pragma unroll
    for (int m = 0; m < 2; m++) {
        const float* q0 = &g_x1[base + (fbase + w * 32 + m * 16 + grp) * C4];
        const float* q1 = q0 + 8 * C4;
#pragma unroll
        for (int k = 0; k < 4; k++) {
            qf[m][k][0] = f2tf(q0[k * 8 + tig] * inv);
            qf[m][k][1] = f2tf(q1[k * 8 + tig] * inv);
            qf[m][k][2] = f2tf(q0[k * 8 + tig + 4] * inv);
            qf[m][k][3] = f2tf(q1[k * 8 + tig + 4] * inv);
        }
    }
    float of[2][4][4];
#pragma unroll
    for (int m = 0; m < 2; m++)
#pragma unroll
        for (int n = 0; n < 4; n++)
#pragma unroll
            for (int r = 0; r < 4; r++) of[m][n][r] = 0.f;
    float mx[2][2], l[2][2];
#pragma unroll
    for (int m = 0; m < 2; m++) { mx[m][0] = -3.0e38f; mx[m][1] = -3.0e38f; l[m][0] = 0.f; l[m][1] = 0.f; }

    {
        const float4* src = (const float4*)&g_x1[base];
#pragma unroll
        for (int j = 0; j < 2; j++) {
            int i = tid + j * 128;
            float4 v = src[i];
            int row = i >> 3, c4 = i & 7;
            uint4 u;
            u.x = f2tf(v.x); u.y = f2tf(v.y); u.z = f2tf(v.z); u.w = f2tf(v.w);
            *(uint4*)&sKT[0][row * KTP + c4 * 4] = u;
        }
    }
    int buf = 0;
    for (int c = 0; c < 8; c++) {
        __syncthreads();
        if (c < 7) {
            const float4* src = (const float4*)&g_x1[base + (c + 1) * 32 * C4];
#pragma unroll
            for (int j = 0; j < 2; j++) {
                int i = tid + j * 128;
                float4 v = src[i];
                int row = i >> 3, c4 = i & 7;
                uint4 u;
                u.x = f2tf(v.x); u.y = f2tf(v.y); u.z = f2tf(v.z); u.w = f2tf(v.w);
                *(uint4*)&sKT[buf ^ 1][row * KTP + c4 * 4] = u;
            }
        }
        float sf[2][4][4];
#pragma unroll
        for (int m = 0; m < 2; m++)
#pragma unroll
            for (int n = 0; n < 4; n++)
#pragma unroll
                for (int r = 0; r < 4; r++) sf[m][n][r] = 0.f;
#pragma unroll
        for (int n = 0; n < 4; n++) {
#pragma unroll
            for (int k = 0; k < 4; k++) {
                const unsigned* kb = &sKT[buf][(n * 8 + grp) * KTP + k * 8 + tig];
                unsigned bfr[2] = { kb[0], kb[4] };
                mma8(sf[0][n], qf[0][k], bfr);
                mma8(sf[1][n], qf[1][k], bfr);
            }
        }
#pragma unroll
        for (int m = 0; m < 2; m++) {
            float cm0 = -3.0e38f, cm1 = -3.0e38f;
#pragma unroll
            for (int n = 0; n < 4; n++) {
                cm0 = fmaxf(cm0, fmaxf(sf[m][n][0], sf[m][n][1]));
                cm1 = fmaxf(cm1, fmaxf(sf[m][n][2], sf[m][n][3]));
            }
            cm0 = qmax(cm0); cm1 = qmax(cm1);
            float nm0 = fmaxf(mx[m][0], cm0), nm1 = fmaxf(mx[m][1], cm1);
            float sc0 = __expf(mx[m][0] - nm0), sc1 = __expf(mx[m][1] - nm1);
            mx[m][0] = nm0; mx[m][1] = nm1;
            float rs0 = 0.f, rs1 = 0.f;
#pragma unroll
            for (int n = 0; n < 4; n++) {
                float p0 = __expf(sf[m][n][0] - nm0);
                float p1 = __expf(sf[m][n][1] - nm0);
                float p2 = __expf(sf[m][n][2] - nm1);
                float p3 = __expf(sf[m][n][3] - nm1);
                rs0 += p0 + p1; rs1 += p2 + p3;
                sf[m][n][0] = __uint_as_float(f2tf(p0));
                sf[m][n][1] = __uint_as_float(f2tf(p1));
                sf[m][n][2] = __uint_as_float(f2tf(p2));
                sf[m][n][3] = __uint_as_float(f2tf(p3));
            }
            l[m][0] = l[m][0] * sc0 + qsum(rs0);
            l[m][1] = l[m][1] * sc1 + qsum(rs1);
#pragma unroll
            for (int n = 0; n < 4; n++) {
                of[m][n][0] *= sc0; of[m][n][1] *= sc0;
                of[m][n][2] *= sc1; of[m][n][3] *= sc1;
            }
#pragma unroll
            for (int k = 0; k < 4; k++) {
                float x0 = __shfl_sync(0xffffffffu, sf[m][k][0], sl0);
                float x1 = __shfl_sync(0xffffffffu, sf[m][k][1], sl0);
                float x2 = __shfl_sync(0xffffffffu, sf[m][k][2], sl0);
                float x3 = __shfl_sync(0xffffffffu, sf[m][k][3], sl0);
                float y0 = __shfl_sync(0xffffffffu, sf[m][k][0], sl1);
                float y1 = __shfl_sync(0xffffffffu, sf[m][k][1], sl1);
                float y2 = __shfl_sync(0xffffffffu, sf[m][k][2], sl1);
                float y3 = __shfl_sync(0xffffffffu, sf[m][k][3], sl1);
                unsigned af[4];
                af[0] = __float_as_uint(odd ? x1 : x0);
                af[1] = __float_as_uint(odd ? x3 : x2);
                af[2] = __float_as_uint(odd ? y1 : y0);
                af[3] = __float_as_uint(odd ? y3 : y2);
#pragma unroll
                for (int n = 0; n < 4; n++) {
                    unsigned vb[2];
                    vb[0] = sKT[buf][(k * 8 + tig) * KTP + n * 8 + grp];
                    vb[1] = sKT[buf][(k * 8 + tig + 4) * KTP + n * 8 + grp];
                    mma8(of[m][n], af, vb);
                }
            }
        }
        buf ^= 1;
    }
    int b = bt / T, t = bt % T;
#pragma unroll
    for (int m = 0; m < 2; m++) {
        int ql = w * 32 + m * 16 + grp;
        float r0 = 1.0f / l[m][0], r1 = 1.0f / l[m][1];
        float* d0 = &g_of[((b * Fd + fbase + ql) * T + t) * C4];
        float* d1 = &g_of[((b * Fd + fbase + ql + 8) * T + t) * C4];
#pragma unroll
        for (int n = 0; n < 4; n++) {
            int ch = n * 8 + 2 * tig;
            *(float2*)&d0[ch] = make_float2(of[m][n][0] * r0, of[m][n][1] * r0);
            *(float2*)&d1[ch] = make_float2(of[m][n][2] * r1, of[m][n][3] * r1);
        }
    }
}

// ---------------------------------------------------------------------------
// Causal time attention, tf32 mma + fragment-resident softmax.
// Block = (b*Fd+f, q-tile of 128). Warp-level triangle skip + diag mask.
// ---------------------------------------------------------------------------
__global__ void __launch_bounds__(128, 4) time_attn_kernel() {
    __shared__ unsigned sKT[2][32 * KTP];
    __shared__ unsigned sVT[2][32 * VTP];

    int blk = blockIdx.x;
    int qt = blk & 3, bf = blk >> 2;
    int tid = threadIdx.x, w = tid >> 5, lane = tid & 31;
    int grp = lane >> 2, tig = lane & 3;
    int lq = lane & ~3;
    int sl0 = lq | (tig >> 1), sl1 = sl0 + 2;
    bool odd = tig & 1;
    int base = bf * (T * C4);
    int qbase = qt * 128;
    const float inv = 0.005524271728019903f;  // 2^-7.5

    unsigned qf[2][4][4];
#pragma unroll
    for (int m = 0; m < 2; m++) {
        const float* q0 = &g_x2[base + (qbase + w * 32 + m * 16 + grp) * C4];
        const float* q1 = q0 + 8 * C4;
#pragma unroll
        for (int k = 0; k < 4; k++) {
            qf[m][k][0] = f2tf(q0[k * 8 + tig] * inv);
            qf[m][k][1] = f2tf(q1[k * 8 + tig] * inv);
            qf[m][k][2] = f2tf(q0[k * 8 + tig + 4] * inv);
            qf[m][k][3] = f2tf(q1[k * 8 + tig + 4] * inv);
        }
    }
    float of[2][4][4];
#pragma unroll
    for (int m = 0; m < 2; m++)
#pragma unroll
        for (int n = 0; n < 4; n++)
#pragma unroll
            for (int r = 0; r < 4; r++) of[m][n][r] = 0.f;
    float mx[2][2], l[2][2];
#pragma unroll
    for (int m = 0; m < 2; m++) { mx[m][0] = -3.0e38f; mx[m][1] = -3.0e38f; l[m][0] = 0.f; l[m][1] = 0.f; }

    int nch = (qt + 1) * 4;
    // preload chunk 0
    {
        const float4* ks = (const float4*)&g_x2[base];
        const float4* vs = (const float4*)&g_of[base];
#pragma unroll
        for (int j = 0; j < 2; j++) {
            int i = tid + j * 128;
            float4 kv = ks[i];
            float4 vv = vs[i];
            int row = i >> 3, c4 = i & 7;
            uint4 ku, vu;
            ku.x = f2tf(kv.x); ku.y = f2tf(kv.y); ku.z = f2tf(kv.z); ku.w = f2tf(kv.w);
            vu.x = f2tf(vv.x); vu.y = f2tf(vv.y); vu.z = f2tf(vv.z); vu.w = f2tf(vv.w);
            *(uint4*)&sKT[0][row * KTP + c4 * 4] = ku;
            *(uint4*)&sVT[0][row * VTP + c4 * 4] = vu;
        }
    }
    int buf = 0;
    for (int c = 0; c < nch; c++) {
        __syncthreads();
        if (c + 1 < nch) {
            const float4* ks = (const float4*)&g_x2[base + (c + 1) * 32 * C4];
            const float4* vs = (const float4*)&g_of[base + (c + 1) * 32 * C4];
#pragma unroll
            for (int j = 0; j < 2; j++) {
                int i = tid + j * 128;
                float4 kv = ks[i];
                float4 vv = vs[i];
                int row = i >> 3, c4 = i & 7;
                uint4 ku, vu;
                ku.x = f2tf(kv.x); ku.y = f2tf(kv.y); ku.z = f2tf(kv.z); ku.w = f2tf(kv.w);
                vu.x = f2tf(vv.x); vu.y = f2tf(vv.y); vu.z = f2tf(vv.z); vu.w = f2tf(vv.w);
                *(uint4*)&sKT[buf ^ 1][row * KTP + c4 * 4] = ku;
                *(uint4*)&sVT[buf ^ 1][row * VTP + c4 * 4] = vu;
            }
        }
        bool active = (c <= qt * 4 + w);
        if (active) {
            float sf[2][4][4];
#pragma unroll
            for (int m = 0; m < 2; m++)
#pragma unroll
                for (int n = 0; n < 4; n++)
#pragma unroll
                    for (int r = 0; r < 4; r++) sf[m][n][r] = 0.f;
#pragma unroll
            for (int n = 0; n < 4; n++) {
#pragma unroll
                for (int k = 0; k < 4; k++) {
                    const unsigned* kb = &sKT[buf][(n * 8 + grp) * KTP + k * 8 + tig];
                    unsigned bfr[2] = { kb[0], kb[4] };
                    mma8(sf[0][n], qf[0][k], bfr);
                    mma8(sf[1][n], qf[1][k], bfr);
                }
            }
            bool diag = (c == qt * 4 + w);
#pragma unroll
            for (int m = 0; m < 2; m++) {
                if (diag) {
                    int R0 = w * 32 + m * 16 + grp;       // both minus qbase, minus c*32 offset aligns
                    int R1 = R0 + 8;
#pragma unroll
                    for (int n = 0; n < 4; n++) {
                        int cb = (c - qt * 4) * 32 + n * 8 + 2 * tig;  // col rel to qbase... c*32 - qbase = (c-qt*4)*32
                        if (cb > R0)     sf[m][n][0] = NEG;
                        if (cb + 1 > R0) sf[m][n][1] = NEG;
                        if (cb > R1)     sf[m][n][2] = NEG;
                        if (cb + 1 > R1) sf[m][n][3] = NEG;
                    }
                }
                float cm0 = -3.0e38f, cm1 = -3.0e38f;
#pragma unroll
                for (int n = 0; n < 4; n++) {
                    cm0 = fmaxf(cm0, fmaxf(sf[m][n][0], sf[m][n][1]));
                    cm1 = fmaxf(cm1, fmaxf(sf[m][n][2], sf[m][n][3]));
                }
                cm0 = qmax(cm0); cm1 = qmax(cm1);
                float nm0 = fmaxf(mx[m][0], cm0), nm1 = fmaxf(mx[m][1], cm1);
                float sc0 = __expf(mx[m][0] - nm0), sc1 = __expf(mx[m][1] - nm1);
                mx[m][0] = nm0; mx[m][1] = nm1;
                float rs0 = 0.f, rs1 = 0.f;
#pragma unroll
                for (int n = 0; n < 4; n++) {
                    float p0 = __expf(sf[m][n][0] - nm0);
                    float p1 = __expf(sf[m][n][1] - nm0);
                    float p2 = __expf(sf[m][n][2] - nm1);
                    float p3 = __expf(sf[m][n][3] - nm1);
                    rs0 += p0 + p1; rs1 += p2 + p3;
                    sf[m][n][0] = __uint_as_float(f2tf(p0));
                    sf[m][n][1] = __uint_as_float(f2tf(p1));
                    sf[m][n][2] = __uint_as_float(f2tf(p2));
                    sf[m][n][3] = __uint_as_float(f2tf(p3));
                }
                l[m][0] = l[m][0] * sc0 + qsum(rs0);
                l[m][1] = l[m][1] * sc1 + qsum(rs1);
#pragma unroll
                for (int n = 0; n < 4; n++) {
                    of[m][n][0] *= sc0; of[m][n][1] *= sc0;
                    of[m][n][2] *= sc1; of[m][n][3] *= sc1;
                }
#pragma unroll
                for (int k = 0; k < 4; k++) {
                    float x0 = __shfl_sync(0xffffffffu, sf[m][k][0], sl0);
                    float x1 = __shfl_sync(0xffffffffu, sf[m][k][1], sl0);
                    float x2 = __shfl_sync(0xffffffffu, sf[m][k][2], sl0);
                    float x3 = __shfl_sync(0xffffffffu, sf[m][k][3], sl0);
                    float y0 = __shfl_sync(0xffffffffu, sf[m][k][0], sl1);
                    float y1 = __shfl_sync(0xffffffffu, sf[m][k][1], sl1);
                    float y2 = __shfl_sync(0xffffffffu, sf[m][k][2], sl1);
                    float y3 = __shfl_sync(0xffffffffu, sf[m][k][3], sl1);
                    unsigned af[4];
                    af[0] = __float_as_uint(odd ? x1 : x0);
                    af[1] = __float_as_uint(odd ? x3 : x2);
                    af[2] = __float_as_uint(odd ? y1 : y0);
                    af[3] = __float_as_uint(odd ? y3 : y2);
#pragma unroll
                    for (int n = 0; n < 4; n++) {
                        unsigned vb[2];
                        vb[0] = sVT[buf][(k * 8 + tig) * VTP + n * 8 + grp];
                        vb[1] = sVT[buf][(k * 8 + tig + 4) * VTP + n * 8 + grp];
                        mma8(of[m][n], af, vb);
                    }
                }
            }
        }
        buf ^= 1;
    }
#pragma unroll
    for (int m = 0; m < 2; m++) {
        int ql = w * 32 + m * 16 + grp;
        float r0 = 1.0f / l[m][0], r1 = 1.0f / l[m][1];
        float* d0 = &g_M[base + (qbase + ql) * C4];
        float* d1 = &g_M[base + (qbase + ql + 8) * C4];
#pragma unroll
        for (int n = 0; n < 4; n++) {
            int ch = n * 8 + 2 * tig;
            *(float2*)&d0[ch] = make_float2(of[m][n][0] * r0, of[m][n][1] * r0);
            *(float2*)&d1[ch] = make_float2(of[m][n][2] * r1, of[m][n][3] * r1);
        }
    }
}

// ---------------------------------------------------------------------------
// Final pointwise conv (+BN +PReLU) + residual (unchanged from R4)
// ---------------------------------------------------------------------------
__global__ void final_kernel(const float* __restrict__ x,
                             const float* __restrict__ a3p,
                             float* __restrict__ out) {
    __shared__ float sw[C4 * C];
    __shared__ float sb[C];
    int tid = threadIdx.x;
    for (int i = tid; i < C4 * C; i += 256) sw[i] = g_w3s[i];
    if (tid < C) sb[tid] = g_b3s[tid];
    __syncthreads();

    int idx = blockIdx.x * 256 + tid;
    int f = idx % Fd;
    int t = (idx / Fd) % T;
    int b = idx / (Fd * T);

    float Ml[C4];
    const float4* ms = (const float4*)(&g_M[((b * Fd + f) * T + t) * C4]);
#pragma unroll
    for (int c4 = 0; c4 < 8; c4++) {
        float4 m = ms[c4];
        Ml[c4 * 4 + 0] = m.x; Ml[c4 * 4 + 1] = m.y;
        Ml[c4 * 4 + 2] = m.z; Ml[c4 * 4 + 3] = m.w;
    }
    float a3 = a3p[0];
    int xbase = (b * C) * (T * Fd) + t * Fd + f;
    const float4* sw4 = (const float4*)sw;
    const float4* sb4 = (const float4*)sb;
#pragma unroll 2
    for (int o4 = 0; o4 < C / 4; o4++) {
        float4 bb = sb4[o4];
        float y0 = bb.x, y1 = bb.y, y2 = bb.z, y3 = bb.w;
#pragma unroll
        for (int c = 0; c < C4; c++) {
            float4 w = sw4[c * (C / 4) + o4];
            float m = Ml[c];
            y0 += m * w.x; y1 += m * w.y; y2 += m * w.z; y3 += m * w.w;
        }
        y0 = y0 >= 0.f ? y0 : a3 * y0;
        y1 = y1 >= 0.f ? y1 : a3 * y1;
        y2 = y2 >= 0.f ? y2 : a3 * y2;
        y3 = y3 >= 0.f ? y3 : a3 * y3;
        int o = o4 * 4;
        out[xbase + (o + 0) * (T * Fd)] = y0 + x[xbase + (o + 0) * (T * Fd)];
        out[xbase + (o + 1) * (T * Fd)] = y1 + x[xbase + (o + 1) * (T * Fd)];
        out[xbase + (o + 2) * (T * Fd)] = y2 + x[xbase + (o + 2) * (T * Fd)];
        out[xbase + (o + 3) * (T * Fd)] = y3 + x[xbase + (o + 3) * (T * Fd)];
    }
}

// ---------------------------------------------------------------------------
extern "C" void kernel_launch(void* const* d_in, const int* in_sizes, int n_in,
                              void* d_out, int out_size) {
    const float* x  = (const float*)d_in[0];
    const float* w1 = (const float*)d_in[1];
    const float* g1 = (const float*)d_in[2];
    const float* b1 = (const float*)d_in[3];
    const float* m1 = (const float*)d_in[4];
    const float* v1 = (const float*)d_in[5];
    const float* a1 = (const float*)d_in[6];
    const float* w2 = (const float*)d_in[7];
    const float* g2 = (const float*)d_in[8];
    const float* b2 = (const float*)d_in[9];
    const float* m2 = (const float*)d_in[10];
    const float* v2 = (const float*)d_in[11];
    const float* a2 = (const float*)d_in[12];
    const float* w3 = (const float*)d_in[13];
    const float* g3 = (const float*)d_in[14];
    const float* b3 = (const float*)d_in[15];
    const float* m3 = (const float*)d_in[16];
    const float* v3 = (const float*)d_in[17];
    const float* a3 = (const float*)d_in[18];
    float* out = (float*)d_out;

    prep_kernel<<<16, 256>>>(w1, g1, b1, m1, v1, w2, g2, b2, m2, v2,
                             w3, g3, b3, m3, v3);
    conv12_kernel<<<(B * T * Fd) / 128, 128>>>(x, a1, a2);
    freq_attn_kernel<<<B * T * 2, 128>>>();
    time_attn_kernel<<<B * Fd * 4, 128>>>();
    final_kernel<<<(B * T * Fd) / 256, 256>>>(x, a3, out);
}

// round 12
// speedup vs baseline: 4.2234x; 1.1769x over previous
#include <cuda_runtime.h>
#include <math.h>

#define B  2
#define C  128
#define C4 32
#define T  512
#define Fd 256
#define TF (T * Fd)
#define EPS 1e-5f
#define KBP 20    // bf16-pair tile row pad (words): banks grp*20+tig all distinct
#define WP  36
#define XP  136
#define NEG -1.0e30f

// ---- scratch (static device memory; no allocation allowed) ----
__device__ unsigned g_w12t[64 * C];   // fused+scaled w1|w2, tf32, layout [o][c]
__device__ float g_b12s[64];
__device__ float g_w3s[C4 * C];
__device__ float g_b3s[C];
__device__ float g_x1[B * T * Fd * C4];   // [b][t][f][c]
__device__ float g_x2[B * Fd * T * C4];   // [b][f][t][c]
__device__ float g_of[B * Fd * T * C4];   // [b][f][t][c]
__device__ float g_M [B * Fd * T * C4];   // [b][f][t][c]

// ---------------------------------------------------------------------------
__device__ __forceinline__ unsigned f2tf(float f) {
    unsigned u;
    asm("cvt.rna.tf32.f32 %0, %1;" : "=r"(u) : "f"(f));
    return u;
}

// pack two floats to bf16x2: lo = first element (lower k index), hi = second
__device__ __forceinline__ unsigned pk2(float lo, float hi) {
    unsigned r;
    asm("cvt.rn.bf16x2.f32 %0, %1, %2;" : "=r"(r) : "f"(hi), "f"(lo));
    return r;
}

__device__ __forceinline__ void mma8(float d[4], const unsigned a[4], const unsigned b[2]) {
    asm volatile(
        "mma.sync.aligned.m16n8k8.row.col.f32.tf32.tf32.f32 "
        "{%0,%1,%2,%3},{%4,%5,%6,%7},{%8,%9},{%0,%1,%2,%3};"
        : "+f"(d[0]), "+f"(d[1]), "+f"(d[2]), "+f"(d[3])
        : "r"(a[0]), "r"(a[1]), "r"(a[2]), "r"(a[3]), "r"(b[0]), "r"(b[1]));
}

__device__ __forceinline__ void mma16(float d[4], const unsigned a[4], const unsigned b[2]) {
    asm volatile(
        "mma.sync.aligned.m16n8k16.row.col.f32.bf16.bf16.f32 "
        "{%0,%1,%2,%3},{%4,%5,%6,%7},{%8,%9},{%0,%1,%2,%3};"
        : "+f"(d[0]), "+f"(d[1]), "+f"(d[2]), "+f"(d[3])
        : "r"(a[0]), "r"(a[1]), "r"(a[2]), "r"(a[3]), "r"(b[0]), "r"(b[1]));
}

__device__ __forceinline__ float qmax(float v) {
    v = fmaxf(v, __shfl_xor_sync(0xffffffffu, v, 1));
    v = fmaxf(v, __shfl_xor_sync(0xffffffffu, v, 2));
    return v;
}
__device__ __forceinline__ float qsum(float v) {
    v += __shfl_xor_sync(0xffffffffu, v, 1);
    v += __shfl_xor_sync(0xffffffffu, v, 2);
    return v;
}

// ---------------------------------------------------------------------------
// Prep: fold BatchNorm into conv weights/biases.
// ---------------------------------------------------------------------------
__global__ void prep_kernel(const float* __restrict__ w1, const float* __restrict__ g1,
                            const float* __restrict__ b1, const float* __restrict__ m1,
                            const float* __restrict__ v1,
                            const float* __restrict__ w2, const float* __restrict__ g2,
                            const float* __restrict__ b2, const float* __restrict__ m2,
                            const float* __restrict__ v2,
                            const float* __restrict__ w3, const float* __restrict__ g3,
                            const float* __restrict__ b3, const float* __restrict__ m3,
                            const float* __restrict__ v3) {
    int total = 64 * C + C4 * C + 64 + C;
    for (int i = blockIdx.x * blockDim.x + threadIdx.x; i < total;
         i += gridDim.x * blockDim.x) {
        if (i < 64 * C) {
            int o = i >> 7, c = i & 127;
            float s, w;
            if (o < 32) { s = g1[o] * rsqrtf(v1[o] + EPS); w = w1[o * C + c]; }
            else        { int o2 = o - 32; s = g2[o2] * rsqrtf(v2[o2] + EPS); w = w2[o2 * C + c]; }
            g_w12t[o * C + c] = f2tf(w * s);
        } else if (i < 64 * C + C4 * C) {
            int j = i - 64 * C;
            int c = j / C, o = j % C;
            float s = g3[o] * rsqrtf(v3[o] + EPS);
            g_w3s[c * C + o] = w3[o * C4 + c] * s;
        } else if (i < 64 * C + C4 * C + 64) {
            int o = i - 64 * C - C4 * C;
            if (o < 32) { float s = g1[o] * rsqrtf(v1[o] + EPS); g_b12s[o] = b1[o] - m1[o] * s; }
            else        { int o2 = o - 32; float s = g2[o2] * rsqrtf(v2[o2] + EPS); g_b12s[o] = b2[o2] - m2[o2] * s; }
        } else {
            int o = i - 64 * C - C4 * C - 64;
            float s = g3[o] * rsqrtf(v3[o] + EPS);
            g_b3s[o] = b3[o] - m3[o] * s;
        }
    }
}

// ---------------------------------------------------------------------------
// Fused pointwise conv 1+2 via tf32 mma (unchanged from R7)
// ---------------------------------------------------------------------------
__global__ void __launch_bounds__(128) conv12_kernel(const float* __restrict__ x,
                                                     const float* __restrict__ a1p,
                                                     const float* __restrict__ a2p) {
    __shared__ unsigned sw[64 * WP];
    __shared__ unsigned xs[32 * XP];

    int tid = threadIdx.x, w = tid >> 5, lane = tid & 31;
    int grp = lane >> 2, tig = lane & 3;
    int s0 = blockIdx.x * 128;
    int b = s0 >> 17;
    int sb = s0 & (TF - 1);
    const float* xb = x + (size_t)b * C * TF + sb;

    float of[16][4];
    {
        float bi0 = g_b12s[w * 16 + grp];
        float bi1 = g_b12s[w * 16 + grp + 8];
#pragma unroll
        for (int nt = 0; nt < 16; nt++) {
            of[nt][0] = bi0; of[nt][1] = bi0;
            of[nt][2] = bi1; of[nt][3] = bi1;
        }
    }

    for (int ch = 0; ch < 4; ch++) {
        __syncthreads();
#pragma unroll
        for (int j = 0; j < 16; j++) {
            int i = tid + j * 128;
            int o = i >> 5, kk = i & 31;
            sw[o * WP + kk] = g_w12t[o * C + ch * 32 + kk];
        }
#pragma unroll
        for (int j = 0; j < 8; j++) {
            int i = tid + j * 128;
            int cc = i >> 5, p4 = i & 31;
            float4 v = *(const float4*)(xb + (size_t)(ch * 32 + cc) * TF + p4 * 4);
            uint4 u;
            u.x = f2tf(v.x); u.y = f2tf(v.y); u.z = f2tf(v.z); u.w = f2tf(v.w);
            *(uint4*)&xs[cc * XP + p4 * 4] = u;
        }
        __syncthreads();

#pragma unroll
        for (int ks = 0; ks < 4; ks++) {
            unsigned af[4];
            af[0] = sw[(w * 16 + grp) * WP + ks * 8 + tig];
            af[1] = sw[(w * 16 + grp + 8) * WP + ks * 8 + tig];
            af[2] = sw[(w * 16 + grp) * WP + ks * 8 + tig + 4];
            af[3] = sw[(w * 16 + grp + 8) * WP + ks * 8 + tig + 4];
#pragma unroll
            for (int nt = 0; nt < 16; nt++) {
                unsigned bf[2];
                bf[0] = xs[(ks * 8 + tig) * XP + nt * 8 + grp];
                bf[1] = xs[(ks * 8 + tig + 4) * XP + nt * 8 + grp];
                mma8(of[nt], af, bf);
            }
        }
    }

    float a = (w < 2) ? a1p[0] : a2p[0];
    int ch0 = w * 16 + grp;
    if (w < 2) {
#pragma unroll
        for (int nt = 0; nt < 16; nt++) {
            int pos = s0 + nt * 8 + 2 * tig;
            float y;
            y = of[nt][0]; y = y >= 0.f ? y : a * y; g_x1[(size_t)pos * 32 + ch0] = y;
            y = of[nt][1]; y = y >= 0.f ? y : a * y; g_x1[(size_t)(pos + 1) * 32 + ch0] = y;
            y = of[nt][2]; y = y >= 0.f ? y : a * y; g_x1[(size_t)pos * 32 + ch0 + 8] = y;
            y = of[nt][3]; y = y >= 0.f ? y : a * y; g_x1[(size_t)(pos + 1) * 32 + ch0 + 8] = y;
        }
    } else {
        int o2 = ch0 - 32;
#pragma unroll
        for (int nt = 0; nt < 16; nt++) {
            int pos = s0 + nt * 8 + 2 * tig;
            int t0 = (pos >> 8) & 511, f0 = pos & 255;
            int i0 = ((b * Fd + f0) * T + t0) * 32;
            int t1 = ((pos + 1) >> 8) & 511, f1 = (pos + 1) & 255;
            int i1 = ((b * Fd + f1) * T + t1) * 32;
            float y;
            y = of[nt][0]; y = y >= 0.f ? y : a * y; g_x2[i0 + o2] = y;
            y = of[nt][1]; y = y >= 0.f ? y : a * y; g_x2[i1 + o2] = y;
            y = of[nt][2]; y = y >= 0.f ? y : a * y; g_x2[i0 + o2 + 8] = y;
            y = of[nt][3]; y = y >= 0.f ? y : a * y; g_x2[i1 + o2 + 8] = y;
        }
    }
}

// ---------------------------------------------------------------------------
// Frequency attention: bf16 m16n8k16, zero-shuffle P (S C-frag == PV A-frag).
// Block = (b*T+t, fq-tile of 128). K/V from x1 tile, double-buffered.
// K tile: [key][ch-pair], V tile: [ch][key-pair], pad 20 words.
// ---------------------------------------------------------------------------
__global__ void __launch_bounds__(128, 4) freq_attn_kernel() {
    __shared__ unsigned sKb[2][32 * KBP];
    __shared__ unsigned sVb[2][32 * KBP];

    int blk = blockIdx.x;
    int qt = blk & 1, bt = blk >> 1;
    int tid = threadIdx.x, w = tid >> 5, lane = tid & 31;
    int grp = lane >> 2, tig = lane & 3;
    int base = bt * (Fd * C4);
    int fbase = qt * 128;
    const float inv = 1.0f / 128.0f;

    unsigned qf[2][2][4];
#pragma unroll
    for (int m = 0; m < 2; m++) {
        const float* q0 = &g_x1[base + (fbase + w * 32 + m * 16 + grp) * C4];
        const float* q1 = q0 + 8 * C4;
#pragma unroll
        for (int ks = 0; ks < 2; ks++) {
            int cb = ks * 16 + 2 * tig;
            qf[m][ks][0] = pk2(q0[cb] * inv, q0[cb + 1] * inv);
            qf[m][ks][1] = pk2(q1[cb] * inv, q1[cb + 1] * inv);
            qf[m][ks][2] = pk2(q0[cb + 8] * inv, q0[cb + 9] * inv);
            qf[m][ks][3] = pk2(q1[cb + 8] * inv, q1[cb + 9] * inv);
        }
    }
    float of[2][4][4];
#pragma unroll
    for (int m = 0; m < 2; m++)
#pragma unroll
        for (int n = 0; n < 4; n++)
#pragma unroll
            for (int r = 0; r < 4; r++) of[m][n][r] = 0.f;
    float mx[2][2], l[2][2];
#pragma unroll
    for (int m = 0; m < 2; m++) { mx[m][0] = -3.0e38f; mx[m][1] = -3.0e38f; l[m][0] = 0.f; l[m][1] = 0.f; }

    {
        const float4* src = (const float4*)&g_x1[base];
#pragma unroll
        for (int j = 0; j < 2; j++) {
            int i = tid + j * 128;
            float4 v = src[i];
            int row = i >> 3, c4 = i & 7;
            sKb[0][row * KBP + c4 * 2]     = pk2(v.x, v.y);
            sKb[0][row * KBP + c4 * 2 + 1] = pk2(v.z, v.w);
        }
        int pr = tid & 15, cg = tid >> 4;
        const float* v0 = &g_x1[base + (2 * pr) * C4 + cg * 4];
        float4 va = *(const float4*)v0;
        float4 vb = *(const float4*)(v0 + C4);
        sVb[0][(cg * 4 + 0) * KBP + pr] = pk2(va.x, vb.x);
        sVb[0][(cg * 4 + 1) * KBP + pr] = pk2(va.y, vb.y);
        sVb[0][(cg * 4 + 2) * KBP + pr] = pk2(va.z, vb.z);
        sVb[0][(cg * 4 + 3) * KBP + pr] = pk2(va.w, vb.w);
    }
    int buf = 0;
    for (int c = 0; c < 8; c++) {
        __syncthreads();
        if (c < 7) {
            const float4* src = (const float4*)&g_x1[base + (c + 1) * 32 * C4];
#pragma unroll
            for (int j = 0; j < 2; j++) {
                int i = tid + j * 128;
                float4 v = src[i];
                int row = i >> 3, c4 = i & 7;
                sKb[buf ^ 1][row * KBP + c4 * 2]     = pk2(v.x, v.y);
                sKb[buf ^ 1][row * KBP + c4 * 2 + 1] = pk2(v.z, v.w);
            }
            int pr = tid & 15, cg = tid >> 4;
            const float* v0 = &g_x1[base + (c + 1) * 32 * C4 + (2 * pr) * C4 + cg * 4];
            float4 va = *(const float4*)v0;
            float4 vb = *(const float4*)(v0 + C4);
            sVb[buf ^ 1][(cg * 4 + 0) * KBP + pr] = pk2(va.x, vb.x);
            sVb[buf ^ 1][(cg * 4 + 1) * KBP + pr] = pk2(va.y, vb.y);
            sVb[buf ^ 1][(cg * 4 + 2) * KBP + pr] = pk2(va.z, vb.z);
            sVb[buf ^ 1][(cg * 4 + 3) * KBP + pr] = pk2(va.w, vb.w);
        }
        float sf[2][4][4];
#pragma unroll
        for (int m = 0; m < 2; m++)
#pragma unroll
            for (int n = 0; n < 4; n++)
#pragma unroll
                for (int r = 0; r < 4; r++) sf[m][n][r] = 0.f;
#pragma unroll
        for (int n = 0; n < 4; n++) {
#pragma unroll
            for (int ks = 0; ks < 2; ks++) {
                const unsigned* kb = &sKb[buf][(n * 8 + grp) * KBP + ks * 8 + tig];
                unsigned bfr[2] = { kb[0], kb[4] };
                mma16(sf[0][n], qf[0][ks], bfr);
                mma16(sf[1][n], qf[1][ks], bfr);
            }
        }
#pragma unroll
        for (int m = 0; m < 2; m++) {
            float cm0 = -3.0e38f, cm1 = -3.0e38f;
#pragma unroll
            for (int n = 0; n < 4; n++) {
                cm0 = fmaxf(cm0, fmaxf(sf[m][n][0], sf[m][n][1]));
                cm1 = fmaxf(cm1, fmaxf(sf[m][n][2], sf[m][n][3]));
            }
            cm0 = qmax(cm0); cm1 = qmax(cm1);
            float nm0 = fmaxf(mx[m][0], cm0), nm1 = fmaxf(mx[m][1], cm1);
            float sc0 = __expf(mx[m][0] - nm0), sc1 = __expf(mx[m][1] - nm1);
            mx[m][0] = nm0; mx[m][1] = nm1;
            float p[4][4];
            float rs0 = 0.f, rs1 = 0.f;
#pragma unroll
            for (int n = 0; n < 4; n++) {
                p[n][0] = __expf(sf[m][n][0] - nm0);
                p[n][1] = __expf(sf[m][n][1] - nm0);
                p[n][2] = __expf(sf[m][n][2] - nm1);
                p[n][3] = __expf(sf[m][n][3] - nm1);
                rs0 += p[n][0] + p[n][1]; rs1 += p[n][2] + p[n][3];
            }
            l[m][0] = l[m][0] * sc0 + qsum(rs0);
            l[m][1] = l[m][1] * sc1 + qsum(rs1);
#pragma unroll
            for (int n = 0; n < 4; n++) {
                of[m][n][0] *= sc0; of[m][n][1] *= sc0;
                of[m][n][2] *= sc1; of[m][n][3] *= sc1;
            }
            unsigned pa[2][4];
#pragma unroll
            for (int kk = 0; kk < 2; kk++) {
                pa[kk][0] = pk2(p[2 * kk][0], p[2 * kk][1]);
                pa[kk][1] = pk2(p[2 * kk][2], p[2 * kk][3]);
                pa[kk][2] = pk2(p[2 * kk + 1][0], p[2 * kk + 1][1]);
                pa[kk][3] = pk2(p[2 * kk + 1][2], p[2 * kk + 1][3]);
            }
#pragma unroll
            for (int n = 0; n < 4; n++) {
#pragma unroll
                for (int kk = 0; kk < 2; kk++) {
                    const unsigned* vbp = &sVb[buf][(n * 8 + grp) * KBP + kk * 8 + tig];
                    unsigned vb[2] = { vbp[0], vbp[4] };
                    mma16(of[m][n], pa[kk], vb);
                }
            }
        }
        buf ^= 1;
    }
    int b = bt / T, t = bt % T;
#pragma unroll
    for (int m = 0; m < 2; m++) {
        int ql = w * 32 + m * 16 + grp;
        float r0 = 1.0f / l[m][0], r1 = 1.0f / l[m][1];
        float* d0 = &g_of[((b * Fd + fbase + ql) * T + t) * C4];
        float* d1 = &g_of[((b * Fd + fbase + ql + 8) * T + t) * C4];
#pragma unroll
        for (int n = 0; n < 4; n++) {
            int ch = n * 8 + 2 * tig;
            *(float2*)&d0[ch] = make_float2(of[m][n][0] * r0, of[m][n][1] * r0);
            *(float2*)&d1[ch] = make_float2(of[m][n][2] * r1, of[m][n][3] * r1);
        }
    }
}

// ---------------------------------------------------------------------------
// Causal time attention: bf16 m16n8k16, zero-shuffle P, warp triangle skip.
// ---------------------------------------------------------------------------
__global__ void __launch_bounds__(128, 4) time_attn_kernel() {
    __shared__ unsigned sKb[2][32 * KBP];
    __shared__ unsigned sVb[2][32 * KBP];

    int blk = blockIdx.x;
    int qt = blk & 3, bf = blk >> 2;
    int tid = threadIdx.x, w = tid >> 5, lane = tid & 31;
    int grp = lane >> 2, tig = lane & 3;
    int base = bf * (T * C4);
    int qbase = qt * 128;
    const float inv = 0.005524271728019903f;  // 2^-7.5

    unsigned qf[2][2][4];
#pragma unroll
    for (int m = 0; m < 2; m++) {
        const float* q0 = &g_x2[base + (qbase + w * 32 + m * 16 + grp) * C4];
        const float* q1 = q0 + 8 * C4;
#pragma unroll
        for (int ks = 0; ks < 2; ks++) {
            int cb = ks * 16 + 2 * tig;
            qf[m][ks][0] = pk2(q0[cb] * inv, q0[cb + 1] * inv);
            qf[m][ks][1] = pk2(q1[cb] * inv, q1[cb + 1] * inv);
            qf[m][ks][2] = pk2(q0[cb + 8] * inv, q0[cb + 9] * inv);
            qf[m][ks][3] = pk2(q1[cb + 8] * inv, q1[cb + 9] * inv);
        }
    }
    float of[2][4][4];
#pragma unroll
    for (int m = 0; m < 2; m++)
#pragma unroll
        for (int n = 0; n < 4; n++)
#pragma unroll
            for (int r = 0; r < 4; r++) of[m][n][r] = 0.f;
    float mx[2][2], l[2][2];
#pragma unroll
    for (int m = 0; m < 2; m++) { mx[m][0] = -3.0e38f; mx[m][1] = -3.0e38f; l[m][0] = 0.f; l[m][1] = 0.f; }

    int nch = (qt + 1) * 4;
    {
        const float4* ks4 = (const float4*)&g_x2[base];
#pragma unroll
        for (int j = 0; j < 2; j++) {
            int i = tid + j * 128;
            float4 v = ks4[i];
            int row = i >> 3, c4 = i & 7;
            sKb[0][row * KBP + c4 * 2]     = pk2(v.x, v.y);
            sKb[0][row * KBP + c4 * 2 + 1] = pk2(v.z, v.w);
        }
        int pr = tid & 15, cg = tid >> 4;
        const float* v0 = &g_of[base + (2 * pr) * C4 + cg * 4];
        float4 va = *(const float4*)v0;
        float4 vb = *(const float4*)(v0 + C4);
        sVb[0][(cg * 4 + 0) * KBP + pr] = pk2(va.x, vb.x);
        sVb[0][(cg * 4 + 1) * KBP + pr] = pk2(va.y, vb.y);
        sVb[0][(cg * 4 + 2) * KBP + pr] = pk2(va.z, vb.z);
        sVb[0][(cg * 4 + 3) * KBP + pr] = pk2(va.w, vb.w);
    }
    int buf = 0;
    for (int c = 0; c < nch; c++) {
        __syncthreads();
        if (c + 1 < nch) {
            const float4* ks4 = (const float4*)&g_x2[base + (c + 1) * 32 * C4];
#pragma unroll
            for (int j = 0; j < 2; j++) {
                int i = tid + j * 128;
                float4 v = ks4[i];
                int row = i >> 3, c4 = i & 7;
                sKb[buf ^ 1][row * KBP + c4 * 2]     = pk2(v.x, v.y);
                sKb[buf ^ 1][row * KBP + c4 * 2 + 1] = pk2(v.z, v.w);
            }
            int pr = tid & 15, cg = tid >> 4;
            const float* v0 = &g_of[base + (c + 1) * 32 * C4 + (2 * pr) * C4 + cg * 4];
            float4 va = *(const float4*)v0;
            float4 vb = *(const float4*)(v0 + C4);
            sVb[buf ^ 1][(cg * 4 + 0) * KBP + pr] = pk2(va.x, vb.x);
            sVb[buf ^ 1][(cg * 4 + 1) * KBP + pr] = pk2(va.y, vb.y);
            sVb[buf ^ 1][(cg * 4 + 2) * KBP + pr] = pk2(va.z, vb.z);
            sVb[buf ^ 1][(cg * 4 + 3) * KBP + pr] = pk2(va.w, vb.w);
        }
        bool active = (c <= qt * 4 + w);
        if (active) {
            float sf[2][4][4];
#pragma unroll
            for (int m = 0; m < 2; m++)
#pragma unroll
                for (int n = 0; n < 4; n++)
#pragma unroll
                    for (int r = 0; r < 4; r++) sf[m][n][r] = 0.f;
#pragma unroll
            for (int n = 0; n < 4; n++) {
#pragma unroll
                for (int ks = 0; ks < 2; ks++) {
                    const unsigned* kb = &sKb[buf][(n * 8 + grp) * KBP + ks * 8 + tig];
                    unsigned bfr[2] = { kb[0], kb[4] };
                    mma16(sf[0][n], qf[0][ks], bfr);
                    mma16(sf[1][n], qf[1][ks], bfr);
                }
            }
            bool diag = (c == qt * 4 + w);
#pragma unroll
            for (int m = 0; m < 2; m++) {
                if (diag) {
                    int R0 = w * 32 + m * 16 + grp;
                    int R1 = R0 + 8;
#pragma unroll
                    for (int n = 0; n < 4; n++) {
                        int cb = (c - qt * 4) * 32 + n * 8 + 2 * tig;
                        if (cb > R0)     sf[m][n][0] = NEG;
                        if (cb + 1 > R0) sf[m][n][1] = NEG;
                        if (cb > R1)     sf[m][n][2] = NEG;
                        if (cb + 1 > R1) sf[m][n][3] = NEG;
                    }
                }
                float cm0 = -3.0e38f, cm1 = -3.0e38f;
#pragma unroll
                for (int n = 0; n < 4; n++) {
                    cm0 = fmaxf(cm0, fmaxf(sf[m][n][0], sf[m][n][1]));
                    cm1 = fmaxf(cm1, fmaxf(sf[m][n][2], sf[m][n][3]));
                }
                cm0 = qmax(cm0); cm1 = qmax(cm1);
                float nm0 = fmaxf(mx[m][0], cm0), nm1 = fmaxf(mx[m][1], cm1);
                float sc0 = __expf(mx[m][0] - nm0), sc1 = __expf(mx[m][1] - nm1);
                mx[m][0] = nm0; mx[m][1] = nm1;
                float p[4][4];
                float rs0 = 0.f, rs1 = 0.f;
#pragma unroll
                for (int n = 0; n < 4; n++) {
                    p[n][0] = __expf(sf[m][n][0] - nm0);
                    p[n][1] = __expf(sf[m][n][1] - nm0);
                    p[n][2] = __expf(sf[m][n][2] - nm1);
                    p[n][3] = __expf(sf[m][n][3] - nm1);
                    rs0 += p[n][0] + p[n][1]; rs1 += p[n][2] + p[n][3];
                }
                l[m][0] = l[m][0] * sc0 + qsum(rs0);
                l[m][1] = l[m][1] * sc1 + qsum(rs1);
#pragma unroll
                for (int n = 0; n < 4; n++) {
                    of[m][n][0] *= sc0; of[m][n][1] *= sc0;
                    of[m][n][2] *= sc1; of[m][n][3] *= sc1;
                }
                unsigned pa[2][4];
#pragma unroll
                for (int kk = 0; kk < 2; kk++) {
                    pa[kk][0] = pk2(p[2 * kk][0], p[2 * kk][1]);
                    pa[kk][1] = pk2(p[2 * kk][2], p[2 * kk][3]);
                    pa[kk][2] = pk2(p[2 * kk + 1][0], p[2 * kk + 1][1]);
                    pa[kk][3] = pk2(p[2 * kk + 1][2], p[2 * kk + 1][3]);
                }
#pragma unroll
                for (int n = 0; n < 4; n++) {
#pragma unroll
                    for (int kk = 0; kk < 2; kk++) {
                        const unsigned* vbp = &sVb[buf][(n * 8 + grp) * KBP + kk * 8 + tig];
                        unsigned vb[2] = { vbp[0], vbp[4] };
                        mma16(of[m][n], pa[kk], vb);
                    }
                }
            }
        }
        buf ^= 1;
    }
#pragma unroll
    for (int m = 0; m < 2; m++) {
        int ql = w * 32 + m * 16 + grp;
        float r0 = 1.0f / l[m][0], r1 = 1.0f / l[m][1];
        float* d0 = &g_M[base + (qbase + ql) * C4];
        float* d1 = &g_M[base + (qbase + ql + 8) * C4];
#pragma unroll
        for (int n = 0; n < 4; n++) {
            int ch = n * 8 + 2 * tig;
            *(float2*)&d0[ch] = make_float2(of[m][n][0] * r0, of[m][n][1] * r0);
            *(float2*)&d1[ch] = make_float2(of[m][n][2] * r1, of[m][n][3] * r1);
        }
    }
}

// ---------------------------------------------------------------------------
// Final pointwise conv (+BN +PReLU) + residual (unchanged)
// ---------------------------------------------------------------------------
__global__ void final_kernel(const float* __restrict__ x,
                             const float* __restrict__ a3p,
                             float* __restrict__ out) {
    __shared__ float sw[C4 * C];
    __shared__ float sb[C];
    int tid = threadIdx.x;
    for (int i = tid; i < C4 * C; i += 256) sw[i] = g_w3s[i];
    if (tid < C) sb[tid] = g_b3s[tid];
    __syncthreads();

    int idx = blockIdx.x * 256 + tid;
    int f = idx % Fd;
    int t = (idx / Fd) % T;
    int b = idx / (Fd * T);

    float Ml[C4];
    const float4* ms = (const float4*)(&g_M[((b * Fd + f) * T + t) * C4]);
#pragma unroll
    for (int c4 = 0; c4 < 8; c4++) {
        float4 m = ms[c4];
        Ml[c4 * 4 + 0] = m.x; Ml[c4 * 4 + 1] = m.y;
        Ml[c4 * 4 + 2] = m.z; Ml[c4 * 4 + 3] = m.w;
    }
    float a3 = a3p[0];
    int xbase = (b * C) * (T * Fd) + t * Fd + f;
    const float4* sw4 = (const float4*)sw;
    const float4* sb4 = (const float4*)sb;
#pragma unroll 2
    for (int o4 = 0; o4 < C / 4; o4++) {
        float4 bb = sb4[o4];
        float y0 = bb.x, y1 = bb.y, y2 = bb.z, y3 = bb.w;
#pragma unroll
        for (int c = 0; c < C4; c++) {
            float4 w = sw4[c * (C / 4) + o4];
            float m = Ml[c];
            y0 += m * w.x; y1 += m * w.y; y2 += m * w.z; y3 += m * w.w;
        }
        y0 = y0 >= 0.f ? y0 : a3 * y0;
        y1 = y1 >= 0.f ? y1 : a3 * y1;
        y2 = y2 >= 0.f ? y2 : a3 * y2;
        y3 = y3 >= 0.f ? y3 : a3 * y3;
        int o = o4 * 4;
        out[xbase + (o + 0) * (T * Fd)] = y0 + x[xbase + (o + 0) * (T * Fd)];
        out[xbase + (o + 1) * (T * Fd)] = y1 + x[xbase + (o + 1) * (T * Fd)];
        out[xbase + (o + 2) * (T * Fd)] = y2 + x[xbase + (o + 2) * (T * Fd)];
        out[xbase + (o + 3) * (T * Fd)] = y3 + x[xbase + (o + 3) * (T * Fd)];
    }
}

// ---------------------------------------------------------------------------
extern "C" void kernel_launch(void* const* d_in, const int* in_sizes, int n_in,
                              void* d_out, int out_size) {
    const float* x  = (const float*)d_in[0];
    const float* w1 = (const float*)d_in[1];
    const float* g1 = (const float*)d_in[2];
    const float* b1 = (const float*)d_in[3];
    const float* m1 = (const float*)d_in[4];
    const float* v1 = (const float*)d_in[5];
    const float* a1 = (const float*)d_in[6];
    const float* w2 = (const float*)d_in[7];
    const float* g2 = (const float*)d_in[8];
    const float* b2 = (const float*)d_in[9];
    const float* m2 = (const float*)d_in[10];
    const float* v2 = (const float*)d_in[11];
    const float* a2 = (const float*)d_in[12];
    const float* w3 = (const float*)d_in[13];
    const float* g3 = (const float*)d_in[14];
    const float* b3 = (const float*)d_in[15];
    const float* m3 = (const float*)d_in[16];
    const float* v3 = (const float*)d_in[17];
    const float* a3 = (const float*)d_in[18];
    float* out = (float*)d_out;

    prep_kernel<<<16, 256>>>(w1, g1, b1, m1, v1, w2, g2, b2, m2, v2,
                             w3, g3, b3, m3, v3);
    conv12_kernel<<<(B * T * Fd) / 128, 128>>>(x, a1, a2);
    freq_attn_kernel<<<B * T * 2, 128>>>();
    time_attn_kernel<<<B * Fd * 4, 128>>>();
    final_kernel<<<(B * T * Fd) / 256, 256>>>(x, a3, out);
}

// round 14
// speedup vs baseline: 4.6091x; 1.0913x over previous
#include <cuda_runtime.h>
#include <math.h>

#define B  2
#define C  128
#define C4 32
#define T  512
#define Fd 256
#define TF (T * Fd)
#define EPS 1e-5f
#define KBP 20    // bf16-pair tile row pad (words): banks grp*20+tig all distinct
#define WP  36
#define XP  136
#define NEG -1.0e30f
#define LOG2E 1.4426950408889634f

// ---- scratch (static device memory; no allocation allowed) ----
__device__ unsigned g_w12t[64 * C];   // fused+scaled w1|w2, tf32, layout [o][c]
__device__ float g_b12s[64];
__device__ unsigned g_w3t[C * C4];    // fused+scaled w3, tf32, layout [o][c]
__device__ float g_b3s[C];
__device__ float g_x1[B * T * Fd * C4];   // [b][t][f][c]
__device__ float g_x2[B * Fd * T * C4];   // [b][f][t][c]
__device__ float g_of[B * Fd * T * C4];   // [b][f][t][c]
__device__ float g_M [B * Fd * T * C4];   // [b][f][t][c]

// ---------------------------------------------------------------------------
__device__ __forceinline__ unsigned f2tf(float f) {
    unsigned u;
    asm("cvt.rna.tf32.f32 %0, %1;" : "=r"(u) : "f"(f));
    return u;
}

__device__ __forceinline__ unsigned pk2(float lo, float hi) {
    unsigned r;
    asm("cvt.rn.bf16x2.f32 %0, %1, %2;" : "=r"(r) : "f"(hi), "f"(lo));
    return r;
}

__device__ __forceinline__ float ex2(float x) {
    float r;
    asm("ex2.approx.f32 %0, %1;" : "=f"(r) : "f"(x));
    return r;
}

__device__ __forceinline__ void mma8(float d[4], const unsigned a[4], const unsigned b[2]) {
    asm volatile(
        "mma.sync.aligned.m16n8k8.row.col.f32.tf32.tf32.f32 "
        "{%0,%1,%2,%3},{%4,%5,%6,%7},{%8,%9},{%0,%1,%2,%3};"
        : "+f"(d[0]), "+f"(d[1]), "+f"(d[2]), "+f"(d[3])
        : "r"(a[0]), "r"(a[1]), "r"(a[2]), "r"(a[3]), "r"(b[0]), "r"(b[1]));
}

__device__ __forceinline__ void mma16(float d[4], const unsigned a[4], const unsigned b[2]) {
    asm volatile(
        "mma.sync.aligned.m16n8k16.row.col.f32.bf16.bf16.f32 "
        "{%0,%1,%2,%3},{%4,%5,%6,%7},{%8,%9},{%0,%1,%2,%3};"
        : "+f"(d[0]), "+f"(d[1]), "+f"(d[2]), "+f"(d[3])
        : "r"(a[0]), "r"(a[1]), "r"(a[2]), "r"(a[3]), "r"(b[0]), "r"(b[1]));
}

__device__ __forceinline__ float qmax(float v) {
    v = fmaxf(v, __shfl_xor_sync(0xffffffffu, v, 1));
    v = fmaxf(v, __shfl_xor_sync(0xffffffffu, v, 2));
    return v;
}
__device__ __forceinline__ float qsum(float v) {
    v += __shfl_xor_sync(0xffffffffu, v, 1);
    v += __shfl_xor_sync(0xffffffffu, v, 2);
    return v;
}

// ---------------------------------------------------------------------------
// Prep: fold BatchNorm into conv weights/biases. w12 and w3 stored [o][c] tf32.
// ---------------------------------------------------------------------------
__global__ void prep_kernel(const float* __restrict__ w1, const float* __restrict__ g1,
                            const float* __restrict__ b1, const float* __restrict__ m1,
                            const float* __restrict__ v1,
                            const float* __restrict__ w2, const float* __restrict__ g2,
                            const float* __restrict__ b2, const float* __restrict__ m2,
                            const float* __restrict__ v2,
                            const float* __restrict__ w3, const float* __restrict__ g3,
                            const float* __restrict__ b3, const float* __restrict__ m3,
                            const float* __restrict__ v3) {
    int total = 64 * C + C * C4 + 64 + C;
    for (int i = blockIdx.x * blockDim.x + threadIdx.x; i < total;
         i += gridDim.x * blockDim.x) {
        if (i < 64 * C) {
            int o = i >> 7, c = i & 127;
            float s, w;
            if (o < 32) { s = g1[o] * rsqrtf(v1[o] + EPS); w = w1[o * C + c]; }
            else        { int o2 = o - 32; s = g2[o2] * rsqrtf(v2[o2] + EPS); w = w2[o2 * C + c]; }
            g_w12t[o * C + c] = f2tf(w * s);
        } else if (i < 64 * C + C * C4) {
            int j = i - 64 * C;
            int o = j >> 5, c = j & 31;
            float s = g3[o] * rsqrtf(v3[o] + EPS);
            g_w3t[o * C4 + c] = f2tf(w3[o * C4 + c] * s);
        } else if (i < 64 * C + C * C4 + 64) {
            int o = i - 64 * C - C * C4;
            if (o < 32) { float s = g1[o] * rsqrtf(v1[o] + EPS); g_b12s[o] = b1[o] - m1[o] * s; }
            else        { int o2 = o - 32; float s = g2[o2] * rsqrtf(v2[o2] + EPS); g_b12s[o] = b2[o2] - m2[o2] * s; }
        } else {
            int o = i - 64 * C - C * C4 - 64;
            float s = g3[o] * rsqrtf(v3[o] + EPS);
            g_b3s[o] = b3[o] - m3[o] * s;
        }
    }
}

// ---------------------------------------------------------------------------
// Fused pointwise conv 1+2 via tf32 mma (unchanged from R7)
// ---------------------------------------------------------------------------
__global__ void __launch_bounds__(128) conv12_kernel(const float* __restrict__ x,
                                                     const float* __restrict__ a1p,
                                                     const float* __restrict__ a2p) {
    __shared__ unsigned sw[64 * WP];
    __shared__ unsigned xs[32 * XP];

    int tid = threadIdx.x, w = tid >> 5, lane = tid & 31;
    int grp = lane >> 2, tig = lane & 3;
    int s0 = blockIdx.x * 128;
    int b = s0 >> 17;
    int sb = s0 & (TF - 1);
    const float* xb = x + (size_t)b * C * TF + sb;

    float of[16][4];
    {
        float bi0 = g_b12s[w * 16 + grp];
        float bi1 = g_b12s[w * 16 + grp + 8];
#pragma unroll
        for (int nt = 0; nt < 16; nt++) {
            of[nt][0] = bi0; of[nt][1] = bi0;
            of[nt][2] = bi1; of[nt][3] = bi1;
        }
    }

    for (int ch = 0; ch < 4; ch++) {
        __syncthreads();
#pragma unroll
        for (int j = 0; j < 16; j++) {
            int i = tid + j * 128;
            int o = i >> 5, kk = i & 31;
            sw[o * WP + kk] = g_w12t[o * C + ch * 32 + kk];
        }
#pragma unroll
        for (int j = 0; j < 8; j++) {
            int i = tid + j * 128;
            int cc = i >> 5, p4 = i & 31;
            float4 v = *(const float4*)(xb + (size_t)(ch * 32 + cc) * TF + p4 * 4);
            uint4 u;
            u.x = f2tf(v.x); u.y = f2tf(v.y); u.z = f2tf(v.z); u.w = f2tf(v.w);
            *(uint4*)&xs[cc * XP + p4 * 4] = u;
        }
        __syncthreads();

#pragma unroll
        for (int ks = 0; ks < 4; ks++) {
            unsigned af[4];
            af[0] = sw[(w * 16 + grp) * WP + ks * 8 + tig];
            af[1] = sw[(w * 16 + grp + 8) * WP + ks * 8 + tig];
            af[2] = sw[(w * 16 + grp) * WP + ks * 8 + tig + 4];
            af[3] = sw[(w * 16 + grp + 8) * WP + ks * 8 + tig + 4];
#pragma unroll
            for (int nt = 0; nt < 16; nt++) {
                unsigned bf[2];
                bf[0] = xs[(ks * 8 + tig) * XP + nt * 8 + grp];
                bf[1] = xs[(ks * 8 + tig + 4) * XP + nt * 8 + grp];
                mma8(of[nt], af, bf);
            }
        }
    }

    float a = (w < 2) ? a1p[0] : a2p[0];
    int ch0 = w * 16 + grp;
    if (w < 2) {
#pragma unroll
        for (int nt = 0; nt < 16; nt++) {
            int pos = s0 + nt * 8 + 2 * tig;
            float y;
            y = of[nt][0]; y = y >= 0.f ? y : a * y; g_x1[(size_t)pos * 32 + ch0] = y;
            y = of[nt][1]; y = y >= 0.f ? y : a * y; g_x1[(size_t)(pos + 1) * 32 + ch0] = y;
            y = of[nt][2]; y = y >= 0.f ? y : a * y; g_x1[(size_t)pos * 32 + ch0 + 8] = y;
            y = of[nt][3]; y = y >= 0.f ? y : a * y; g_x1[(size_t)(pos + 1) * 32 + ch0 + 8] = y;
        }
    } else {
        int o2 = ch0 - 32;
#pragma unroll
        for (int nt = 0; nt < 16; nt++) {
            int pos = s0 + nt * 8 + 2 * tig;
            int t0 = (pos >> 8) & 511, f0 = pos & 255;
            int i0 = ((b * Fd + f0) * T + t0) * 32;
            int t1 = ((pos + 1) >> 8) & 511, f1 = (pos + 1) & 255;
            int i1 = ((b * Fd + f1) * T + t1) * 32;
            float y;
            y = of[nt][0]; y = y >= 0.f ? y : a * y; g_x2[i0 + o2] = y;
            y = of[nt][1]; y = y >= 0.f ? y : a * y; g_x2[i1 + o2] = y;
            y = of[nt][2]; y = y >= 0.f ? y : a * y; g_x2[i0 + o2 + 8] = y;
            y = of[nt][3]; y = y >= 0.f ? y : a * y; g_x2[i1 + o2 + 8] = y;
        }
    }
}

// ---------------------------------------------------------------------------
// Frequency attention: bf16 m16n8k16, zero-shuffle P, ex2-domain softmax.
// ---------------------------------------------------------------------------
__global__ void __launch_bounds__(128, 4) freq_attn_kernel() {
    __shared__ unsigned sKb[2][32 * KBP];
    __shared__ unsigned sVb[2][32 * KBP];

    int blk = blockIdx.x;
    int qt = blk & 1, bt = blk >> 1;
    int tid = threadIdx.x, w = tid >> 5, lane = tid & 31;
    int grp = lane >> 2, tig = lane & 3;
    int base = bt * (Fd * C4);
    int fbase = qt * 128;
    const float inv = (1.0f / 128.0f) * LOG2E;   // log2-domain scores

    unsigned qf[2][2][4];
#pragma unroll
    for (int m = 0; m < 2; m++) {
        const float* q0 = &g_x1[base + (fbase + w * 32 + m * 16 + grp) * C4];
        const float* q1 = q0 + 8 * C4;
#pragma unroll
        for (int ks = 0; ks < 2; ks++) {
            int cb = ks * 16 + 2 * tig;
            qf[m][ks][0] = pk2(q0[cb] * inv, q0[cb + 1] * inv);
            qf[m][ks][1] = pk2(q1[cb] * inv, q1[cb + 1] * inv);
            qf[m][ks][2] = pk2(q0[cb + 8] * inv, q0[cb + 9] * inv);
            qf[m][ks][3] = pk2(q1[cb + 8] * inv, q1[cb + 9] * inv);
        }
    }
    float of[2][4][4];
#pragma unroll
    for (int m = 0; m < 2; m++)
#pragma unroll
        for (int n = 0; n < 4; n++)
#pragma unroll
            for (int r = 0; r < 4; r++) of[m][n][r] = 0.f;
    float mx[2][2], l[2][2];
#pragma unroll
    for (int m = 0; m < 2; m++) { mx[m][0] = -3.0e38f; mx[m][1] = -3.0e38f; l[m][0] = 0.f; l[m][1] = 0.f; }

    {
        const float4* src = (const float4*)&g_x1[base];
#pragma unroll
        for (int j = 0; j < 2; j++) {
            int i = tid + j * 128;
            float4 v = src[i];
            int row = i >> 3, c4 = i & 7;
            sKb[0][row * KBP + c4 * 2]     = pk2(v.x, v.y);
            sKb[0][row * KBP + c4 * 2 + 1] = pk2(v.z, v.w);
        }
        int pr = tid & 15, cg = tid >> 4;
        const float* v0 = &g_x1[base + (2 * pr) * C4 + cg * 4];
        float4 va = *(const float4*)v0;
        float4 vb = *(const float4*)(v0 + C4);
        sVb[0][(cg * 4 + 0) * KBP + pr] = pk2(va.x, vb.x);
        sVb[0][(cg * 4 + 1) * KBP + pr] = pk2(va.y, vb.y);
        sVb[0][(cg * 4 + 2) * KBP + pr] = pk2(va.z, vb.z);
        sVb[0][(cg * 4 + 3) * KBP + pr] = pk2(va.w, vb.w);
    }
    int buf = 0;
    for (int c = 0; c < 8; c++) {
        __syncthreads();
        if (c < 7) {
            const float4* src = (const float4*)&g_x1[base + (c + 1) * 32 * C4];
#pragma unroll
            for (int j = 0; j < 2; j++) {
                int i = tid + j * 128;
                float4 v = src[i];
                int row = i >> 3, c4 = i & 7;
                sKb[buf ^ 1][row * KBP + c4 * 2]     = pk2(v.x, v.y);
                sKb[buf ^ 1][row * KBP + c4 * 2 + 1] = pk2(v.z, v.w);
            }
            int pr = tid & 15, cg = tid >> 4;
            const float* v0 = &g_x1[base + (c + 1) * 32 * C4 + (2 * pr) * C4 + cg * 4];
            float4 va = *(const float4*)v0;
            float4 vb = *(const float4*)(v0 + C4);
            sVb[buf ^ 1][(cg * 4 + 0) * KBP + pr] = pk2(va.x, vb.x);
            sVb[buf ^ 1][(cg * 4 + 1) * KBP + pr] = pk2(va.y, vb.y);
            sVb[buf ^ 1][(cg * 4 + 2) * KBP + pr] = pk2(va.z, vb.z);
            sVb[buf ^ 1][(cg * 4 + 3) * KBP + pr] = pk2(va.w, vb.w);
        }
        float sf[2][4][4];
#pragma unroll
        for (int m = 0; m < 2; m++)
#pragma unroll
            for (int n = 0; n < 4; n++)
#pragma unroll
                for (int r = 0; r < 4; r++) sf[m][n][r] = 0.f;
#pragma unroll
        for (int n = 0; n < 4; n++) {
#pragma unroll
            for (int ks = 0; ks < 2; ks++) {
                const unsigned* kb = &sKb[buf][(n * 8 + grp) * KBP + ks * 8 + tig];
                unsigned bfr[2] = { kb[0], kb[4] };
                mma16(sf[0][n], qf[0][ks], bfr);
                mma16(sf[1][n], qf[1][ks], bfr);
            }
        }
#pragma unroll
        for (int m = 0; m < 2; m++) {
            float cm0 = -3.0e38f, cm1 = -3.0e38f;
#pragma unroll
            for (int n = 0; n < 4; n++) {
                cm0 = fmaxf(cm0, fmaxf(sf[m][n][0], sf[m][n][1]));
                cm1 = fmaxf(cm1, fmaxf(sf[m][n][2], sf[m][n][3]));
            }
            cm0 = qmax(cm0); cm1 = qmax(cm1);
            float nm0 = fmaxf(mx[m][0], cm0), nm1 = fmaxf(mx[m][1], cm1);
            float sc0 = ex2(mx[m][0] - nm0), sc1 = ex2(mx[m][1] - nm1);
            mx[m][0] = nm0; mx[m][1] = nm1;
            float p[4][4];
            float rs0 = 0.f, rs1 = 0.f;
#pragma unroll
            for (int n = 0; n < 4; n++) {
                p[n][0] = ex2(sf[m][n][0] - nm0);
                p[n][1] = ex2(sf[m][n][1] - nm0);
                p[n][2] = ex2(sf[m][n][2] - nm1);
                p[n][3] = ex2(sf[m][n][3] - nm1);
                rs0 += p[n][0] + p[n][1]; rs1 += p[n][2] + p[n][3];
            }
            l[m][0] = l[m][0] * sc0 + qsum(rs0);
            l[m][1] = l[m][1] * sc1 + qsum(rs1);
#pragma unroll
            for (int n = 0; n < 4; n++) {
                of[m][n][0] *= sc0; of[m][n][1] *= sc0;
                of[m][n][2] *= sc1; of[m][n][3] *= sc1;
            }
            unsigned pa[2][4];
#pragma unroll
            for (int kk = 0; kk < 2; kk++) {
                pa[kk][0] = pk2(p[2 * kk][0], p[2 * kk][1]);
                pa[kk][1] = pk2(p[2 * kk][2], p[2 * kk][3]);
                pa[kk][2] = pk2(p[2 * kk + 1][0], p[2 * kk + 1][1]);
                pa[kk][3] = pk2(p[2 * kk + 1][2], p[2 * kk + 1][3]);
            }
#pragma unroll
            for (int n = 0; n < 4; n++) {
#pragma unroll
                for (int kk = 0; kk < 2; kk++) {
                    const unsigned* vbp = &sVb[buf][(n * 8 + grp) * KBP + kk * 8 + tig];
                    unsigned vb[2] = { vbp[0], vbp[4] };
                    mma16(of[m][n], pa[kk], vb);
                }
            }
        }
        buf ^= 1;
    }
    int b = bt / T, t = bt % T;
#pragma unroll
    for (int m = 0; m < 2; m++) {
        int ql = w * 32 + m * 16 + grp;
        float r0 = 1.0f / l[m][0], r1 = 1.0f / l[m][1];
        float* d0 = &g_of[((b * Fd + fbase + ql) * T + t) * C4];
        float* d1 = &g_of[((b * Fd + fbase + ql + 8) * T + t) * C4];
#pragma unroll
        for (int n = 0; n < 4; n++) {
            int ch = n * 8 + 2 * tig;
            *(float2*)&d0[ch] = make_float2(of[m][n][0] * r0, of[m][n][1] * r0);
            *(float2*)&d1[ch] = make_float2(of[m][n][2] * r1, of[m][n][3] * r1);
        }
    }
}

// ---------------------------------------------------------------------------
// Causal time attention: bf16 m16n8k16, zero-shuffle P, ex2-domain softmax.
// ---------------------------------------------------------------------------
__global__ void __launch_bounds__(128, 4) time_attn_kernel() {
    __shared__ unsigned sKb[2][32 * KBP];
    __shared__ unsigned sVb[2][32 * KBP];

    int blk = blockIdx.x;
    int qt = blk & 3, bf = blk >> 2;
    int tid = threadIdx.x, w = tid >> 5, lane = tid & 31;
    int grp = lane >> 2, tig = lane & 3;
    int base = bf * (T * C4);
    int qbase = qt * 128;
    const float inv = 0.005524271728019903f * LOG2E;   // 2^-7.5 * log2e

    unsigned qf[2][2][4];
#pragma unroll
    for (int m = 0; m < 2; m++) {
        const float* q0 = &g_x2[base + (qbase + w * 32 + m * 16 + grp) * C4];
        const float* q1 = q0 + 8 * C4;
#pragma unroll
        for (int ks = 0; ks < 2; ks++) {
            int cb = ks * 16 + 2 * tig;
            qf[m][ks][0] = pk2(q0[cb] * inv, q0[cb + 1] * inv);
            qf[m][ks][1] = pk2(q1[cb] * inv, q1[cb + 1] * inv);
            qf[m][ks][2] = pk2(q0[cb + 8] * inv, q0[cb + 9] * inv);
            qf[m][ks][3] = pk2(q1[cb + 8] * inv, q1[cb + 9] * inv);
        }
    }
    float of[2][4][4];
#pragma unroll
    for (int m = 0; m < 2; m++)
#pragma unroll
        for (int n = 0; n < 4; n++)
#pragma unroll
            for (int r = 0; r < 4; r++) of[m][n][r] = 0.f;
    float mx[2][2], l[2][2];
#pragma unroll
    for (int m = 0; m < 2; m++) { mx[m][0] = -3.0e38f; mx[m][1] = -3.0e38f; l[m][0] = 0.f; l[m][1] = 0.f; }

    int nch = (qt + 1) * 4;
    {
        const float4* ks4 = (const float4*)&g_x2[base];
#pragma unroll
        for (int j = 0; j < 2; j++) {
            int i = tid + j * 128;
            float4 v = ks4[i];
            int row = i >> 3, c4 = i & 7;
            sKb[0][row * KBP + c4 * 2]     = pk2(v.x, v.y);
            sKb[0][row * KBP + c4 * 2 + 1] = pk2(v.z, v.w);
        }
        int pr = tid & 15, cg = tid >> 4;
        const float* v0 = &g_of[base + (2 * pr) * C4 + cg * 4];
        float4 va = *(const float4*)v0;
        float4 vb = *(const float4*)(v0 + C4);
        sVb[0][(cg * 4 + 0) * KBP + pr] = pk2(va.x, vb.x);
        sVb[0][(cg * 4 + 1) * KBP + pr] = pk2(va.y, vb.y);
        sVb[0][(cg * 4 + 2) * KBP + pr] = pk2(va.z, vb.z);
        sVb[0][(cg * 4 + 3) * KBP + pr] = pk2(va.w, vb.w);
    }
    int buf = 0;
    for (int c = 0; c < nch; c++) {
        __syncthreads();
        if (c + 1 < nch) {
            const float4* ks4 = (const float4*)&g_x2[base + (c + 1) * 32 * C4];
#pragma unroll
            for (int j = 0; j < 2; j++) {
                int i = tid + j * 128;
                float4 v = ks4[i];
                int row = i >> 3, c4 = i & 7;
                sKb[buf ^ 1][row * KBP + c4 * 2]     = pk2(v.x, v.y);
                sKb[buf ^ 1][row * KBP + c4 * 2 + 1] = pk2(v.z, v.w);
            }
            int pr = tid & 15, cg = tid >> 4;
            const float* v0 = &g_of[base + (c + 1) * 32 * C4 + (2 * pr) * C4 + cg * 4];
            float4 va = *(const float4*)v0;
            float4 vb = *(const float4*)(v0 + C4);
            sVb[buf ^ 1][(cg * 4 + 0) * KBP + pr] = pk2(va.x, vb.x);
            sVb[buf ^ 1][(cg * 4 + 1) * KBP + pr] = pk2(va.y, vb.y);
            sVb[buf ^ 1][(cg * 4 + 2) * KBP + pr] = pk2(va.z, vb.z);
            sVb[buf ^ 1][(cg * 4 + 3) * KBP + pr] = pk2(va.w, vb.w);
        }
        bool active = (c <= qt * 4 + w);
        if (active) {
            float sf[2][4][4];
#pragma unroll
            for (int m = 0; m < 2; m++)
#pragma unroll
                for (int n = 0; n < 4; n++)
#pragma unroll
                    for (int r = 0; r < 4; r++) sf[m][n][r] = 0.f;
#pragma unroll
            for (int n = 0; n < 4; n++) {
#pragma unroll
                for (int ks = 0; ks < 2; ks++) {
                    const unsigned* kb = &sKb[buf][(n * 8 + grp) * KBP + ks * 8 + tig];
                    unsigned bfr[2] = { kb[0], kb[4] };
                    mma16(sf[0][n], qf[0][ks], bfr);
                    mma16(sf[1][n], qf[1][ks], bfr);
                }
            }
            bool diag = (c == qt * 4 + w);
#pragma unroll
            for (int m = 0; m < 2; m++) {
                if (diag) {
                    int R0 = w * 32 + m * 16 + grp;
                    int R1 = R0 + 8;
#pragma unroll
                    for (int n = 0; n < 4; n++) {
                        int cb = (c - qt * 4) * 32 + n * 8 + 2 * tig;
                        if (cb > R0)     sf[m][n][0] = NEG;
                        if (cb + 1 > R0) sf[m][n][1] = NEG;
                        if (cb > R1)     sf[m][n][2] = NEG;
                        if (cb + 1 > R1) sf[m][n][3] = NEG;
                    }
                }
                float cm0 = -3.0e38f, cm1 = -3.0e38f;
#pragma unroll
                for (int n = 0; n < 4; n++) {
                    cm0 = fmaxf(cm0, fmaxf(sf[m][n][0], sf[m][n][1]));
                    cm1 = fmaxf(cm1, fmaxf(sf[m][n][2], sf[m][n][3]));
                }
                cm0 = qmax(cm0); cm1 = qmax(cm1);
                float nm0 = fmaxf(mx[m][0], cm0), nm1 = fmaxf(mx[m][1], cm1);
                float sc0 = ex2(mx[m][0] - nm0), sc1 = ex2(mx[m][1] - nm1);
                mx[m][0] = nm0; mx[m][1] = nm1;
                float p[4][4];
                float rs0 = 0.f, rs1 = 0.f;
#pragma unroll
                for (int n = 0; n < 4; n++) {
                    p[n][0] = ex2(sf[m][n][0] - nm0);
                    p[n][1] = ex2(sf[m][n][1] - nm0);
                    p[n][2] = ex2(sf[m][n][2] - nm1);
                    p[n][3] = ex2(sf[m][n][3] - nm1);
                    rs0 += p[n][0] + p[n][1]; rs1 += p[n][2] + p[n][3];
                }
                l[m][0] = l[m][0] * sc0 + qsum(rs0);
                l[m][1] = l[m][1] * sc1 + qsum(rs1);
#pragma unroll
                for (int n = 0; n < 4; n++) {
                    of[m][n][0] *= sc0; of[m][n][1] *= sc0;
                    of[m][n][2] *= sc1; of[m][n][3] *= sc1;
                }
                unsigned pa[2][4];
#pragma unroll
                for (int kk = 0; kk < 2; kk++) {
                    pa[kk][0] = pk2(p[2 * kk][0], p[2 * kk][1]);
                    pa[kk][1] = pk2(p[2 * kk][2], p[2 * kk][3]);
                    pa[kk][2] = pk2(p[2 * kk + 1][0], p[2 * kk + 1][1]);
                    pa[kk][3] = pk2(p[2 * kk + 1][2], p[2 * kk + 1][3]);
                }
#pragma unroll
                for (int n = 0; n < 4; n++) {
#pragma unroll
                    for (int kk = 0; kk < 2; kk++) {
                        const unsigned* vbp = &sVb[buf][(n * 8 + grp) * KBP + kk * 8 + tig];
                        unsigned vb[2] = { vbp[0], vbp[4] };
                        mma16(of[m][n], pa[kk], vb);
                    }
                }
            }
        }
        buf ^= 1;
    }
#pragma unroll
    for (int m = 0; m < 2; m++) {
        int ql = w * 32 + m * 16 + grp;
        float r0 = 1.0f / l[m][0], r1 = 1.0f / l[m][1];
        float* d0 = &g_M[base + (qbase + ql) * C4];
        float* d1 = &g_M[base + (qbase + ql + 8) * C4];
#pragma unroll
        for (int n = 0; n < 4; n++) {
            int ch = n * 8 + 2 * tig;
            *(float2*)&d0[ch] = make_float2(of[m][n][0] * r0, of[m][n][1] * r0);
            *(float2*)&d1[ch] = make_float2(of[m][n][2] * r1, of[m][n][3] * r1);
        }
    }
}

// ---------------------------------------------------------------------------
// Final pointwise conv (+BN +PReLU) + residual via tf32 mma.
// Block = 128 consecutive positions. A = w3t [128 o][32 c],
// B = M tile transposed [32 c][128 pos]. Two o-passes of 64.
// NOTE: epilogue indices use batch-LOCAL position (sb + ...), b added once.
// ---------------------------------------------------------------------------
__global__ void __launch_bounds__(128) final_kernel(const float* __restrict__ x,
                                                    const float* __restrict__ a3p,
                                                    float* __restrict__ out) {
    __shared__ unsigned sw3[C * WP];    // [o][32 c], pad 36
    __shared__ unsigned sM[32 * XP];    // [c][128 pos], pad 136

    int tid = threadIdx.x, w = tid >> 5, lane = tid & 31;
    int grp = lane >> 2, tig = lane & 3;
    int s0 = blockIdx.x * 128;
    int b = s0 >> 17;
    int sb = s0 & (TF - 1);
    int t0 = sb >> 8;
    int f0 = sb & 255;

    // load w3 [o][c] (4096 words)
#pragma unroll
    for (int j = 0; j < 32; j++) {
        int i = tid + j * 128;
        int o = i >> 5, c = i & 31;
        sw3[o * WP + c] = g_w3t[i];
    }
    // load M transposed: thread tid owns local position sb+tid -> (t0, f0+tid)
    {
        const float4* ms = (const float4*)&g_M[((b * Fd + f0 + tid) * T + t0) * C4];
#pragma unroll
        for (int c4 = 0; c4 < 8; c4++) {
            float4 m = ms[c4];
            sM[(c4 * 4 + 0) * XP + tid] = f2tf(m.x);
            sM[(c4 * 4 + 1) * XP + tid] = f2tf(m.y);
            sM[(c4 * 4 + 2) * XP + tid] = f2tf(m.z);
            sM[(c4 * 4 + 3) * XP + tid] = f2tf(m.w);
        }
    }
    __syncthreads();

    float a3 = a3p[0];
#pragma unroll
    for (int op = 0; op < 2; op++) {
        int o0 = op * 64 + w * 16 + grp;
        float bi0 = g_b3s[o0];
        float bi1 = g_b3s[o0 + 8];
        float of[16][4];
#pragma unroll
        for (int nt = 0; nt < 16; nt++) {
            of[nt][0] = bi0; of[nt][1] = bi0;
            of[nt][2] = bi1; of[nt][3] = bi1;
        }
#pragma unroll
        for (int ks = 0; ks < 4; ks++) {
            unsigned af[4];
            af[0] = sw3[o0 * WP + ks * 8 + tig];
            af[1] = sw3[(o0 + 8) * WP + ks * 8 + tig];
            af[2] = sw3[o0 * WP + ks * 8 + tig + 4];
            af[3] = sw3[(o0 + 8) * WP + ks * 8 + tig + 4];
#pragma unroll
            for (int nt = 0; nt < 16; nt++) {
                unsigned bf[2];
                bf[0] = sM[(ks * 8 + tig) * XP + nt * 8 + grp];
                bf[1] = sM[(ks * 8 + tig + 4) * XP + nt * 8 + grp];
                mma8(of[nt], af, bf);
            }
        }
        // epilogue: PReLU + residual; batch-local position in index
#pragma unroll
        for (int nt = 0; nt < 16; nt++) {
            int lpos = sb + nt * 8 + 2 * tig;
            int idx0 = (b * C + o0) * TF + lpos;
            int idx1 = (b * C + o0 + 8) * TF + lpos;
            float2 x0 = *(const float2*)&x[idx0];
            float2 x1 = *(const float2*)&x[idx1];
            float y0 = of[nt][0], y1 = of[nt][1], y2 = of[nt][2], y3 = of[nt][3];
            y0 = y0 >= 0.f ? y0 : a3 * y0;
            y1 = y1 >= 0.f ? y1 : a3 * y1;
            y2 = y2 >= 0.f ? y2 : a3 * y2;
            y3 = y3 >= 0.f ? y3 : a3 * y3;
            *(float2*)&out[idx0] = make_float2(y0 + x0.x, y1 + x0.y);
            *(float2*)&out[idx1] = make_float2(y2 + x1.x, y3 + x1.y);
        }
    }
}

// ---------------------------------------------------------------------------
extern "C" void kernel_launch(void* const* d_in, const int* in_sizes, int n_in,
                              void* d_out, int out_size) {
    const float* x  = (const float*)d_in[0];
    const float* w1 = (const float*)d_in[1];
    const float* g1 = (const float*)d_in[2];
    const float* b1 = (const float*)d_in[3];
    const float* m1 = (const float*)d_in[4];
    const float* v1 = (const float*)d_in[5];
    const float* a1 = (const float*)d_in[6];
    const float* w2 = (const float*)d_in[7];
    const float* g2 = (const float*)d_in[8];
    const float* b2 = (const float*)d_in[9];
    const float* m2 = (const float*)d_in[10];
    const float* v2 = (const float*)d_in[11];
    const float* a2 = (const float*)d_in[12];
    const float* w3 = (const float*)d_in[13];
    const float* g3 = (const float*)d_in[14];
    const float* b3 = (const float*)d_in[15];
    const float* m3 = (const float*)d_in[16];
    const float* v3 = (const float*)d_in[17];
    const float* a3 = (const float*)d_in[18];
    float* out = (float*)d_out;

    prep_kernel<<<16, 256>>>(w1, g1, b1, m1, v1, w2, g2, b2, m2, v2,
                             w3, g3, b3, m3, v3);
    conv12_kernel<<<(B * T * Fd) / 128, 128>>>(x, a1, a2);
    freq_attn_kernel<<<B * T * 2, 128>>>();
    time_attn_kernel<<<B * Fd * 4, 128>>>();
    final_kernel<<<(B * T * Fd) / 128, 128>>>(x, a3, out);
}

// round 15
// speedup vs baseline: 4.7146x; 1.0229x over previous
#include <cuda_runtime.h>
#include <math.h>

#define B  2
#define C  128
#define C4 32
#define T  512
#define Fd 256
#define TF (T * Fd)
#define EPS 1e-5f
#define KBP 20    // K tile row pad (words): banks 20*grp+tig all distinct
#define WP  36
#define XP  136   // V tile / conv row pad: banks 8*tig+grp all distinct
#define NEG -1.0e30f
#define LOG2E 1.4426950408889634f

// ---- scratch (static device memory; no allocation allowed) ----
__device__ unsigned g_w12t[64 * C];   // fused+scaled w1|w2, tf32, layout [o][c]
__device__ float g_b12s[64];
__device__ unsigned g_w3t[C * C4];    // fused+scaled w3, tf32, layout [o][c]
__device__ float g_b3s[C];
__device__ float g_x1[B * T * Fd * C4];   // [b][t][f][c]
__device__ float g_x2[B * Fd * T * C4];   // [b][f][t][c]
__device__ float g_of[B * Fd * T * C4];   // [b][f][t][c]
__device__ float g_M [B * Fd * T * C4];   // [b][f][t][c]

// ---------------------------------------------------------------------------
__device__ __forceinline__ unsigned f2tf(float f) {
    unsigned u;
    asm("cvt.rna.tf32.f32 %0, %1;" : "=r"(u) : "f"(f));
    return u;
}

__device__ __forceinline__ unsigned pk2(float lo, float hi) {
    unsigned r;
    asm("cvt.rn.bf16x2.f32 %0, %1, %2;" : "=r"(r) : "f"(hi), "f"(lo));
    return r;
}

__device__ __forceinline__ float ex2(float x) {
    float r;
    asm("ex2.approx.f32 %0, %1;" : "=f"(r) : "f"(x));
    return r;
}

__device__ __forceinline__ void mma8(float d[4], const unsigned a[4], const unsigned b[2]) {
    asm volatile(
        "mma.sync.aligned.m16n8k8.row.col.f32.tf32.tf32.f32 "
        "{%0,%1,%2,%3},{%4,%5,%6,%7},{%8,%9},{%0,%1,%2,%3};"
        : "+f"(d[0]), "+f"(d[1]), "+f"(d[2]), "+f"(d[3])
        : "r"(a[0]), "r"(a[1]), "r"(a[2]), "r"(a[3]), "r"(b[0]), "r"(b[1]));
}

__device__ __forceinline__ void mma16(float d[4], const unsigned a[4], const unsigned b[2]) {
    asm volatile(
        "mma.sync.aligned.m16n8k16.row.col.f32.bf16.bf16.f32 "
        "{%0,%1,%2,%3},{%4,%5,%6,%7},{%8,%9},{%0,%1,%2,%3};"
        : "+f"(d[0]), "+f"(d[1]), "+f"(d[2]), "+f"(d[3])
        : "r"(a[0]), "r"(a[1]), "r"(a[2]), "r"(a[3]), "r"(b[0]), "r"(b[1]));
}

__device__ __forceinline__ float qmax(float v) {
    v = fmaxf(v, __shfl_xor_sync(0xffffffffu, v, 1));
    v = fmaxf(v, __shfl_xor_sync(0xffffffffu, v, 2));
    return v;
}
__device__ __forceinline__ float qsum(float v) {
    v += __shfl_xor_sync(0xffffffffu, v, 1);
    v += __shfl_xor_sync(0xffffffffu, v, 2);
    return v;
}

// ---------------------------------------------------------------------------
// Prep (unchanged from R14)
// ---------------------------------------------------------------------------
__global__ void prep_kernel(const float* __restrict__ w1, const float* __restrict__ g1,
                            const float* __restrict__ b1, const float* __restrict__ m1,
                            const float* __restrict__ v1,
                            const float* __restrict__ w2, const float* __restrict__ g2,
                            const float* __restrict__ b2, const float* __restrict__ m2,
                            const float* __restrict__ v2,
                            const float* __restrict__ w3, const float* __restrict__ g3,
                            const float* __restrict__ b3, const float* __restrict__ m3,
                            const float* __restrict__ v3) {
    int total = 64 * C + C * C4 + 64 + C;
    for (int i = blockIdx.x * blockDim.x + threadIdx.x; i < total;
         i += gridDim.x * blockDim.x) {
        if (i < 64 * C) {
            int o = i >> 7, c = i & 127;
            float s, w;
            if (o < 32) { s = g1[o] * rsqrtf(v1[o] + EPS); w = w1[o * C + c]; }
            else        { int o2 = o - 32; s = g2[o2] * rsqrtf(v2[o2] + EPS); w = w2[o2 * C + c]; }
            g_w12t[o * C + c] = f2tf(w * s);
        } else if (i < 64 * C + C * C4) {
            int j = i - 64 * C;
            int o = j >> 5, c = j & 31;
            float s = g3[o] * rsqrtf(v3[o] + EPS);
            g_w3t[o * C4 + c] = f2tf(w3[o * C4 + c] * s);
        } else if (i < 64 * C + C * C4 + 64) {
            int o = i - 64 * C - C * C4;
            if (o < 32) { float s = g1[o] * rsqrtf(v1[o] + EPS); g_b12s[o] = b1[o] - m1[o] * s; }
            else        { int o2 = o - 32; float s = g2[o2] * rsqrtf(v2[o2] + EPS); g_b12s[o] = b2[o2] - m2[o2] * s; }
        } else {
            int o = i - 64 * C - C * C4 - 64;
            float s = g3[o] * rsqrtf(v3[o] + EPS);
            g_b3s[o] = b3[o] - m3[o] * s;
        }
    }
}

// ---------------------------------------------------------------------------
// Fused pointwise conv 1+2 via tf32 mma (unchanged from R7)
// ---------------------------------------------------------------------------
__global__ void __launch_bounds__(128) conv12_kernel(const float* __restrict__ x,
                                                     const float* __restrict__ a1p,
                                                     const float* __restrict__ a2p) {
    __shared__ unsigned sw[64 * WP];
    __shared__ unsigned xs[32 * XP];

    int tid = threadIdx.x, w = tid >> 5, lane = tid & 31;
    int grp = lane >> 2, tig = lane & 3;
    int s0 = blockIdx.x * 128;
    int b = s0 >> 17;
    int sb = s0 & (TF - 1);
    const float* xb = x + (size_t)b * C * TF + sb;

    float of[16][4];
    {
        float bi0 = g_b12s[w * 16 + grp];
        float bi1 = g_b12s[w * 16 + grp + 8];
#pragma unroll
        for (int nt = 0; nt < 16; nt++) {
            of[nt][0] = bi0; of[nt][1] = bi0;
            of[nt][2] = bi1; of[nt][3] = bi1;
        }
    }

    for (int ch = 0; ch < 4; ch++) {
        __syncthreads();
#pragma unroll
        for (int j = 0; j < 16; j++) {
            int i = tid + j * 128;
            int o = i >> 5, kk = i & 31;
            sw[o * WP + kk] = g_w12t[o * C + ch * 32 + kk];
        }
#pragma unroll
        for (int j = 0; j < 8; j++) {
            int i = tid + j * 128;
            int cc = i >> 5, p4 = i & 31;
            float4 v = *(const float4*)(xb + (size_t)(ch * 32 + cc) * TF + p4 * 4);
            uint4 u;
            u.x = f2tf(v.x); u.y = f2tf(v.y); u.z = f2tf(v.z); u.w = f2tf(v.w);
            *(uint4*)&xs[cc * XP + p4 * 4] = u;
        }
        __syncthreads();

#pragma unroll
        for (int ks = 0; ks < 4; ks++) {
            unsigned af[4];
            af[0] = sw[(w * 16 + grp) * WP + ks * 8 + tig];
            af[1] = sw[(w * 16 + grp + 8) * WP + ks * 8 + tig];
            af[2] = sw[(w * 16 + grp) * WP + ks * 8 + tig + 4];
            af[3] = sw[(w * 16 + grp + 8) * WP + ks * 8 + tig + 4];
#pragma unroll
            for (int nt = 0; nt < 16; nt++) {
                unsigned bf[2];
                bf[0] = xs[(ks * 8 + tig) * XP + nt * 8 + grp];
                bf[1] = xs[(ks * 8 + tig + 4) * XP + nt * 8 + grp];
                mma8(of[nt], af, bf);
            }
        }
    }

    float a = (w < 2) ? a1p[0] : a2p[0];
    int ch0 = w * 16 + grp;
    if (w < 2) {
#pragma unroll
        for (int nt = 0; nt < 16; nt++) {
            int pos = s0 + nt * 8 + 2 * tig;
            float y;
            y = of[nt][0]; y = y >= 0.f ? y : a * y; g_x1[(size_t)pos * 32 + ch0] = y;
            y = of[nt][1]; y = y >= 0.f ? y : a * y; g_x1[(size_t)(pos + 1) * 32 + ch0] = y;
            y = of[nt][2]; y = y >= 0.f ? y : a * y; g_x1[(size_t)pos * 32 + ch0 + 8] = y;
            y = of[nt][3]; y = y >= 0.f ? y : a * y; g_x1[(size_t)(pos + 1) * 32 + ch0 + 8] = y;
        }
    } else {
        int o2 = ch0 - 32;
#pragma unroll
        for (int nt = 0; nt < 16; nt++) {
            int pos = s0 + nt * 8 + 2 * tig;
            int t0 = (pos >> 8) & 511, f0 = pos & 255;
            int i0 = ((b * Fd + f0) * T + t0) * 32;
            int t1 = ((pos + 1) >> 8) & 511, f1 = (pos + 1) & 255;
            int i1 = ((b * Fd + f1) * T + t1) * 32;
            float y;
            y = of[nt][0]; y = y >= 0.f ? y : a * y; g_x2[i0 + o2] = y;
            y = of[nt][1]; y = y >= 0.f ? y : a * y; g_x2[i1 + o2] = y;
            y = of[nt][2]; y = y >= 0.f ? y : a * y; g_x2[i0 + o2 + 8] = y;
            y = of[nt][3]; y = y >= 0.f ? y : a * y; g_x2[i1 + o2 + 8] = y;
        }
    }
}

// ---------------------------------------------------------------------------
// Frequency attention v2: whole-tile smem, 256 threads, ONE barrier.
// Block = (b*T+t); warp w owns q rows [w*32, w*32+32) over all 256 keys.
// K tile [key][ch-pair] (KBP=20), V tile [ch][key-pair] (XP=136).
// ---------------------------------------------------------------------------
__global__ void __launch_bounds__(256, 2) freq_attn_kernel() {
    __shared__ unsigned sKb[256 * KBP];   // 20 KB
    __shared__ unsigned sVb[32 * XP];     // 17.4 KB

    int blk = blockIdx.x;                 // b*T + t
    int tid = threadIdx.x, w = tid >> 5, lane = tid & 31;
    int grp = lane >> 2, tig = lane & 3;
    int base = blk * (Fd * C4);
    const float inv = (1.0f / 128.0f) * LOG2E;

    // Q fragments
    unsigned qf[2][2][4];
#pragma unroll
    for (int m = 0; m < 2; m++) {
        const float* q0 = &g_x1[base + (w * 32 + m * 16 + grp) * C4];
        const float* q1 = q0 + 8 * C4;
#pragma unroll
        for (int ks = 0; ks < 2; ks++) {
            int cb = ks * 16 + 2 * tig;
            qf[m][ks][0] = pk2(q0[cb] * inv, q0[cb + 1] * inv);
            qf[m][ks][1] = pk2(q1[cb] * inv, q1[cb + 1] * inv);
            qf[m][ks][2] = pk2(q0[cb + 8] * inv, q0[cb + 9] * inv);
            qf[m][ks][3] = pk2(q1[cb + 8] * inv, q1[cb + 9] * inv);
        }
    }
    float of[2][4][4];
#pragma unroll
    for (int m = 0; m < 2; m++)
#pragma unroll
        for (int n = 0; n < 4; n++)
#pragma unroll
            for (int r = 0; r < 4; r++) of[m][n][r] = 0.f;
    float mx[2][2], l[2][2];
#pragma unroll
    for (int m = 0; m < 2; m++) { mx[m][0] = -3.0e38f; mx[m][1] = -3.0e38f; l[m][0] = 0.f; l[m][1] = 0.f; }

    // whole-tile loaders
    {
        const float4* src = (const float4*)&g_x1[base];
#pragma unroll
        for (int j = 0; j < 8; j++) {
            int i = tid + j * 256;
            float4 v = src[i];
            int row = i >> 3, c4 = i & 7;
            sKb[row * KBP + c4 * 2]     = pk2(v.x, v.y);
            sKb[row * KBP + c4 * 2 + 1] = pk2(v.z, v.w);
        }
#pragma unroll
        for (int it = 0; it < 4; it++) {
            int idx = tid + it * 256;
            int pr = idx & 127, cg4 = idx >> 7;   // cg4 0..7 -> 4 channels each
            const float* v0 = &g_x1[base + (2 * pr) * C4 + cg4 * 4];
            float4 va = *(const float4*)v0;
            float4 vb = *(const float4*)(v0 + C4);
            sVb[(cg4 * 4 + 0) * XP + pr] = pk2(va.x, vb.x);
            sVb[(cg4 * 4 + 1) * XP + pr] = pk2(va.y, vb.y);
            sVb[(cg4 * 4 + 2) * XP + pr] = pk2(va.z, vb.z);
            sVb[(cg4 * 4 + 3) * XP + pr] = pk2(va.w, vb.w);
        }
    }
    __syncthreads();

    for (int c = 0; c < 8; c++) {
        float sf[2][4][4];
#pragma unroll
        for (int m = 0; m < 2; m++)
#pragma unroll
            for (int n = 0; n < 4; n++)
#pragma unroll
                for (int r = 0; r < 4; r++) sf[m][n][r] = 0.f;
#pragma unroll
        for (int n = 0; n < 4; n++) {
#pragma unroll
            for (int ks = 0; ks < 2; ks++) {
                const unsigned* kb = &sKb[(c * 32 + n * 8 + grp) * KBP + ks * 8 + tig];
                unsigned bfr[2] = { kb[0], kb[4] };
                mma16(sf[0][n], qf[0][ks], bfr);
                mma16(sf[1][n], qf[1][ks], bfr);
            }
        }
#pragma unroll
        for (int m = 0; m < 2; m++) {
            float cm0 = -3.0e38f, cm1 = -3.0e38f;
#pragma unroll
            for (int n = 0; n < 4; n++) {
                cm0 = fmaxf(cm0, fmaxf(sf[m][n][0], sf[m][n][1]));
                cm1 = fmaxf(cm1, fmaxf(sf[m][n][2], sf[m][n][3]));
            }
            cm0 = qmax(cm0); cm1 = qmax(cm1);
            float nm0 = fmaxf(mx[m][0], cm0), nm1 = fmaxf(mx[m][1], cm1);
            float sc0 = ex2(mx[m][0] - nm0), sc1 = ex2(mx[m][1] - nm1);
            mx[m][0] = nm0; mx[m][1] = nm1;
            float p[4][4];
            float rs0 = 0.f, rs1 = 0.f;
#pragma unroll
            for (int n = 0; n < 4; n++) {
                p[n][0] = ex2(sf[m][n][0] - nm0);
                p[n][1] = ex2(sf[m][n][1] - nm0);
                p[n][2] = ex2(sf[m][n][2] - nm1);
                p[n][3] = ex2(sf[m][n][3] - nm1);
                rs0 += p[n][0] + p[n][1]; rs1 += p[n][2] + p[n][3];
            }
            l[m][0] = l[m][0] * sc0 + qsum(rs0);
            l[m][1] = l[m][1] * sc1 + qsum(rs1);
#pragma unroll
            for (int n = 0; n < 4; n++) {
                of[m][n][0] *= sc0; of[m][n][1] *= sc0;
                of[m][n][2] *= sc1; of[m][n][3] *= sc1;
            }
            unsigned pa[2][4];
#pragma unroll
            for (int kk = 0; kk < 2; kk++) {
                pa[kk][0] = pk2(p[2 * kk][0], p[2 * kk][1]);
                pa[kk][1] = pk2(p[2 * kk][2], p[2 * kk][3]);
                pa[kk][2] = pk2(p[2 * kk + 1][0], p[2 * kk + 1][1]);
                pa[kk][3] = pk2(p[2 * kk + 1][2], p[2 * kk + 1][3]);
            }
#pragma unroll
            for (int n = 0; n < 4; n++) {
#pragma unroll
                for (int kk = 0; kk < 2; kk++) {
                    const unsigned* vbp = &sVb[(n * 8 + grp) * XP + c * 16 + kk * 8 + tig];
                    unsigned vb[2] = { vbp[0], vbp[4] };
                    mma16(of[m][n], pa[kk], vb);
                }
            }
        }
    }
    int b = blk / T, t = blk % T;
#pragma unroll
    for (int m = 0; m < 2; m++) {
        int ql = w * 32 + m * 16 + grp;
        float r0 = 1.0f / l[m][0], r1 = 1.0f / l[m][1];
        float* d0 = &g_of[((b * Fd + ql) * T + t) * C4];
        float* d1 = &g_of[((b * Fd + ql + 8) * T + t) * C4];
#pragma unroll
        for (int n = 0; n < 4; n++) {
            int ch = n * 8 + 2 * tig;
            *(float2*)&d0[ch] = make_float2(of[m][n][0] * r0, of[m][n][1] * r0);
            *(float2*)&d1[ch] = make_float2(of[m][n][2] * r1, of[m][n][3] * r1);
        }
    }
}

// ---------------------------------------------------------------------------
// Causal time attention v2: 256-key staged whole-tile smem, 256 threads.
// Block = (b*Fd+f, half): half 0 -> q 0..255 (1 stage), half 1 -> q 256..511
// (2 stages of 256 keys, 3 barriers). Warp w owns q rows half*256+w*32+...
// Causal: key-block kb = stage*8+c active iff kb <= half*8+w, diag at ==.
// ---------------------------------------------------------------------------
__global__ void __launch_bounds__(256, 2) time_attn_kernel() {
    __shared__ unsigned sKb[256 * KBP];   // 20 KB
    __shared__ unsigned sVb[32 * XP];     // 17.4 KB

    int blk = blockIdx.x;
    int half = blk & 1, bf = blk >> 1;
    int tid = threadIdx.x, w = tid >> 5, lane = tid & 31;
    int grp = lane >> 2, tig = lane & 3;
    int base = bf * (T * C4);
    int qbase = half * 256;
    int qblk = half * 8 + w;
    const float inv = 0.005524271728019903f * LOG2E;

    unsigned qf[2][2][4];
#pragma unroll
    for (int m = 0; m < 2; m++) {
        const float* q0 = &g_x2[base + (qbase + w * 32 + m * 16 + grp) * C4];
        const float* q1 = q0 + 8 * C4;
#pragma unroll
        for (int ks = 0; ks < 2; ks++) {
            int cb = ks * 16 + 2 * tig;
            qf[m][ks][0] = pk2(q0[cb] * inv, q0[cb + 1] * inv);
            qf[m][ks][1] = pk2(q1[cb] * inv, q1[cb + 1] * inv);
            qf[m][ks][2] = pk2(q0[cb + 8] * inv, q0[cb + 9] * inv);
            qf[m][ks][3] = pk2(q1[cb + 8] * inv, q1[cb + 9] * inv);
        }
    }
    float of[2][4][4];
#pragma unroll
    for (int m = 0; m < 2; m++)
#pragma unroll
        for (int n = 0; n < 4; n++)
#pragma unroll
            for (int r = 0; r < 4; r++) of[m][n][r] = 0.f;
    float mx[2][2], l[2][2];
#pragma unroll
    for (int m = 0; m < 2; m++) { mx[m][0] = -3.0e38f; mx[m][1] = -3.0e38f; l[m][0] = 0.f; l[m][1] = 0.f; }

    for (int stage = 0; stage <= half; stage++) {
        if (stage) __syncthreads();   // all reads of prior stage complete
        {
            const float4* ks4 = (const float4*)&g_x2[base + stage * 256 * C4];
#pragma unroll
            for (int j = 0; j < 8; j++) {
                int i = tid + j * 256;
                float4 v = ks4[i];
                int row = i >> 3, c4 = i & 7;
                sKb[row * KBP + c4 * 2]     = pk2(v.x, v.y);
                sKb[row * KBP + c4 * 2 + 1] = pk2(v.z, v.w);
            }
#pragma unroll
            for (int it = 0; it < 4; it++) {
                int idx = tid + it * 256;
                int pr = idx & 127, cg4 = idx >> 7;
                const float* v0 = &g_of[base + stage * 256 * C4 + (2 * pr) * C4 + cg4 * 4];
                float4 va = *(const float4*)v0;
                float4 vb = *(const float4*)(v0 + C4);
                sVb[(cg4 * 4 + 0) * XP + pr] = pk2(va.x, vb.x);
                sVb[(cg4 * 4 + 1) * XP + pr] = pk2(va.y, vb.y);
                sVb[(cg4 * 4 + 2) * XP + pr] = pk2(va.z, vb.z);
                sVb[(cg4 * 4 + 3) * XP + pr] = pk2(va.w, vb.w);
            }
        }
        __syncthreads();

        for (int c = 0; c < 8; c++) {
            int kb32 = stage * 8 + c;
            if (kb32 > qblk) continue;      // causal skip; no barriers below
            float sf[2][4][4];
#pragma unroll
            for (int m = 0; m < 2; m++)
#pragma unroll
                for (int n = 0; n < 4; n++)
#pragma unroll
                    for (int r = 0; r < 4; r++) sf[m][n][r] = 0.f;
#pragma unroll
            for (int n = 0; n < 4; n++) {
#pragma unroll
                for (int ks = 0; ks < 2; ks++) {
                    const unsigned* kb = &sKb[(c * 32 + n * 8 + grp) * KBP + ks * 8 + tig];
                    unsigned bfr[2] = { kb[0], kb[4] };
                    mma16(sf[0][n], qf[0][ks], bfr);
                    mma16(sf[1][n], qf[1][ks], bfr);
                }
            }
            bool diag = (kb32 == qblk);
#pragma unroll
            for (int m = 0; m < 2; m++) {
                if (diag) {
                    int R0 = qbase + w * 32 + m * 16 + grp;
                    int R1 = R0 + 8;
#pragma unroll
                    for (int n = 0; n < 4; n++) {
                        int cb = stage * 256 + c * 32 + n * 8 + 2 * tig;
                        if (cb > R0)     sf[m][n][0] = NEG;
                        if (cb + 1 > R0) sf[m][n][1] = NEG;
                        if (cb > R1)     sf[m][n][2] = NEG;
                        if (cb + 1 > R1) sf[m][n][3] = NEG;
                    }
                }
                float cm0 = -3.0e38f, cm1 = -3.0e38f;
#pragma unroll
                for (int n = 0; n < 4; n++) {
                    cm0 = fmaxf(cm0, fmaxf(sf[m][n][0], sf[m][n][1]));
                    cm1 = fmaxf(cm1, fmaxf(sf[m][n][2], sf[m][n][3]));
                }
                cm0 = qmax(cm0); cm1 = qmax(cm1);
                float nm0 = fmaxf(mx[m][0], cm0), nm1 = fmaxf(mx[m][1], cm1);
                float sc0 = ex2(mx[m][0] - nm0), sc1 = ex2(mx[m][1] - nm1);
                mx[m][0] = nm0; mx[m][1] = nm1;
                float p[4][4];
                float rs0 = 0.f, rs1 = 0.f;
#pragma unroll
                for (int n = 0; n < 4; n++) {
                    p[n][0] = ex2(sf[m][n][0] - nm0);
                    p[n][1] = ex2(sf[m][n][1] - nm0);
                    p[n][2] = ex2(sf[m][n][2] - nm1);
                    p[n][3] = ex2(sf[m][n][3] - nm1);
                    rs0 += p[n][0] + p[n][1]; rs1 += p[n][2] + p[n][3];
                }
                l[m][0] = l[m][0] * sc0 + qsum(rs0);
                l[m][1] = l[m][1] * sc1 + qsum(rs1);
#pragma unroll
                for (int n = 0; n < 4; n++) {
                    of[m][n][0] *= sc0; of[m][n][1] *= sc0;
                    of[m][n][2] *= sc1; of[m][n][3] *= sc1;
                }
                unsigned pa[2][4];
#pragma unroll
                for (int kk = 0; kk < 2; kk++) {
                    pa[kk][0] = pk2(p[2 * kk][0], p[2 * kk][1]);
                    pa[kk][1] = pk2(p[2 * kk][2], p[2 * kk][3]);
                    pa[kk][2] = pk2(p[2 * kk + 1][0], p[2 * kk + 1][1]);
                    pa[kk][3] = pk2(p[2 * kk + 1][2], p[2 * kk + 1][3]);
                }
#pragma unroll
                for (int n = 0; n < 4; n++) {
#pragma unroll
                    for (int kk = 0; kk < 2; kk++) {
                        const unsigned* vbp = &sVb[(n * 8 + grp) * XP + c * 16 + kk * 8 + tig];
                        unsigned vb[2] = { vbp[0], vbp[4] };
                        mma16(of[m][n], pa[kk], vb);
                    }
                }
            }
        }
    }
#pragma unroll
    for (int m = 0; m < 2; m++) {
        int ql = qbase + w * 32 + m * 16 + grp;
        float r0 = 1.0f / l[m][0], r1 = 1.0f / l[m][1];
        float* d0 = &g_M[base + ql * C4];
        float* d1 = &g_M[base + (ql + 8) * C4];
#pragma unroll
        for (int n = 0; n < 4; n++) {
            int ch = n * 8 + 2 * tig;
            *(float2*)&d0[ch] = make_float2(of[m][n][0] * r0, of[m][n][1] * r0);
            *(float2*)&d1[ch] = make_float2(of[m][n][2] * r1, of[m][n][3] * r1);
        }
    }
}

// ---------------------------------------------------------------------------
// Final pointwise conv (+BN +PReLU) + residual via tf32 mma (unchanged R14)
// ---------------------------------------------------------------------------
__global__ void __launch_bounds__(128) final_kernel(const float* __restrict__ x,
                                                    const float* __restrict__ a3p,
                                                    float* __restrict__ out) {
    __shared__ unsigned sw3[C * WP];
    __shared__ unsigned sM[32 * XP];

    int tid = threadIdx.x, w = tid >> 5, lane = tid & 31;
    int grp = lane >> 2, tig = lane & 3;
    int s0 = blockIdx.x * 128;
    int b = s0 >> 17;
    int sb = s0 & (TF - 1);
    int t0 = sb >> 8;
    int f0 = sb & 255;

#pragma unroll
    for (int j = 0; j < 32; j++) {
        int i = tid + j * 128;
        int o = i >> 5, c = i & 31;
        sw3[o * WP + c] = g_w3t[i];
    }
    {
        const float4* ms = (const float4*)&g_M[((b * Fd + f0 + tid) * T + t0) * C4];
#pragma unroll
        for (int c4 = 0; c4 < 8; c4++) {
            float4 m = ms[c4];
            sM[(c4 * 4 + 0) * XP + tid] = f2tf(m.x);
            sM[(c4 * 4 + 1) * XP + tid] = f2tf(m.y);
            sM[(c4 * 4 + 2) * XP + tid] = f2tf(m.z);
            sM[(c4 * 4 + 3) * XP + tid] = f2tf(m.w);
        }
    }
    __syncthreads();

    float a3 = a3p[0];
#pragma unroll
    for (int op = 0; op < 2; op++) {
        int o0 = op * 64 + w * 16 + grp;
        float bi0 = g_b3s[o0];
        float bi1 = g_b3s[o0 + 8];
        float of[16][4];
#pragma unroll
        for (int nt = 0; nt < 16; nt++) {
            of[nt][0] = bi0; of[nt][1] = bi0;
            of[nt][2] = bi1; of[nt][3] = bi1;
        }
#pragma unroll
        for (int ks = 0; ks < 4; ks++) {
            unsigned af[4];
            af[0] = sw3[o0 * WP + ks * 8 + tig];
            af[1] = sw3[(o0 + 8) * WP + ks * 8 + tig];
            af[2] = sw3[o0 * WP + ks * 8 + tig + 4];
            af[3] = sw3[(o0 + 8) * WP + ks * 8 + tig + 4];
#pragma unroll
            for (int nt = 0; nt < 16; nt++) {
                unsigned bf[2];
                bf[0] = sM[(ks * 8 + tig) * XP + nt * 8 + grp];
                bf[1] = sM[(ks * 8 + tig + 4) * XP + nt * 8 + grp];
                mma8(of[nt], af, bf);
            }
        }
#pragma unroll
        for (int nt = 0; nt < 16; nt++) {
            int lpos = sb + nt * 8 + 2 * tig;
            int idx0 = (b * C + o0) * TF + lpos;
            int idx1 = (b * C + o0 + 8) * TF + lpos;
            float2 x0 = *(const float2*)&x[idx0];
            float2 x1 = *(const float2*)&x[idx1];
            float y0 = of[nt][0], y1 = of[nt][1], y2 = of[nt][2], y3 = of[nt][3];
            y0 = y0 >= 0.f ? y0 : a3 * y0;
            y1 = y1 >= 0.f ? y1 : a3 * y1;
            y2 = y2 >= 0.f ? y2 : a3 * y2;
            y3 = y3 >= 0.f ? y3 : a3 * y3;
            *(float2*)&out[idx0] = make_float2(y0 + x0.x, y1 + x0.y);
            *(float2*)&out[idx1] = make_float2(y2 + x1.x, y3 + x1.y);
        }
    }
}

// ---------------------------------------------------------------------------
extern "C" void kernel_launch(void* const* d_in, const int* in_sizes, int n_in,
                              void* d_out, int out_size) {
    const float* x  = (const float*)d_in[0];
    const float* w1 = (const float*)d_in[1];
    const float* g1 = (const float*)d_in[2];
    const float* b1 = (const float*)d_in[3];
    const float* m1 = (const float*)d_in[4];
    const float* v1 = (const float*)d_in[5];
    const float* a1 = (const float*)d_in[6];
    const float* w2 = (const float*)d_in[7];
    const float* g2 = (const float*)d_in[8];
    const float* b2 = (const float*)d_in[9];
    const float* m2 = (const float*)d_in[10];
    const float* v2 = (const float*)d_in[11];
    const float* a2 = (const float*)d_in[12];
    const float* w3 = (const float*)d_in[13];
    const float* g3 = (const float*)d_in[14];
    const float* b3 = (const float*)d_in[15];
    const float* m3 = (const float*)d_in[16];
    const float* v3 = (const float*)d_in[17];
    const float* a3 = (const float*)d_in[18];
    float* out = (float*)d_out;

    prep_kernel<<<16, 256>>>(w1, g1, b1, m1, v1, w2, g2, b2, m2, v2,
                             w3, g3, b3, m3, v3);
    conv12_kernel<<<(B * T * Fd) / 128, 128>>>(x, a1, a2);
    freq_attn_kernel<<<B * T, 256>>>();
    time_attn_kernel<<<B * Fd * 2, 256>>>();
    final_kernel<<<(B * T * Fd) / 128, 128>>>(x, a3, out);
}

// round 16
// speedup vs baseline: 5.2315x; 1.1096x over previous
#include <cuda_runtime.h>
#include <math.h>

#define B  2
#define C  128
#define C4 32
#define T  512
#define Fd 256
#define TF (T * Fd)
#define EPS 1e-5f
#define KBP 20    // K tile row pad (words): banks 20*grp+tig all distinct
#define WP  36
#define XP  136   // V tile / conv row pad: banks 8*tig+grp all distinct
#define NEG -1.0e30f
#define LOG2E 1.4426950408889634f

// ---- scratch (static device memory; no allocation allowed) ----
__device__ unsigned g_w12t[64 * C];   // fused+scaled w1|w2, tf32, layout [o][c]
__device__ float g_b12s[64];
__device__ unsigned g_w3t[C * C4];    // fused+scaled w3, tf32, layout [o][c]
__device__ float g_b3s[C];
__device__ float g_x1[B * T * Fd * C4];   // [b][t][f][c]
__device__ float g_x2[B * Fd * T * C4];   // [b][f][t][c]
__device__ float g_of[B * Fd * T * C4];   // [b][f][t][c]
__device__ float g_M [B * Fd * T * C4];   // [b][f][t][c]

// ---------------------------------------------------------------------------
__device__ __forceinline__ unsigned f2tf(float f) {
    unsigned u;
    asm("cvt.rna.tf32.f32 %0, %1;" : "=r"(u) : "f"(f));
    return u;
}

__device__ __forceinline__ unsigned pk2(float lo, float hi) {
    unsigned r;
    asm("cvt.rn.bf16x2.f32 %0, %1, %2;" : "=r"(r) : "f"(hi), "f"(lo));
    return r;
}

__device__ __forceinline__ float ex2(float x) {
    float r;
    asm("ex2.approx.f32 %0, %1;" : "=f"(r) : "f"(x));
    return r;
}

__device__ __forceinline__ void mma8(float d[4], const unsigned a[4], const unsigned b[2]) {
    asm volatile(
        "mma.sync.aligned.m16n8k8.row.col.f32.tf32.tf32.f32 "
        "{%0,%1,%2,%3},{%4,%5,%6,%7},{%8,%9},{%0,%1,%2,%3};"
        : "+f"(d[0]), "+f"(d[1]), "+f"(d[2]), "+f"(d[3])
        : "r"(a[0]), "r"(a[1]), "r"(a[2]), "r"(a[3]), "r"(b[0]), "r"(b[1]));
}

__device__ __forceinline__ void mma16(float d[4], const unsigned a[4], const unsigned b[2]) {
    asm volatile(
        "mma.sync.aligned.m16n8k16.row.col.f32.bf16.bf16.f32 "
        "{%0,%1,%2,%3},{%4,%5,%6,%7},{%8,%9},{%0,%1,%2,%3};"
        : "+f"(d[0]), "+f"(d[1]), "+f"(d[2]), "+f"(d[3])
        : "r"(a[0]), "r"(a[1]), "r"(a[2]), "r"(a[3]), "r"(b[0]), "r"(b[1]));
}

__device__ __forceinline__ float qsum(float v) {
    v += __shfl_xor_sync(0xffffffffu, v, 1);
    v += __shfl_xor_sync(0xffffffffu, v, 2);
    return v;
}

// ---------------------------------------------------------------------------
// Prep (unchanged)
// ---------------------------------------------------------------------------
__global__ void prep_kernel(const float* __restrict__ w1, const float* __restrict__ g1,
                            const float* __restrict__ b1, const float* __restrict__ m1,
                            const float* __restrict__ v1,
                            const float* __restrict__ w2, const float* __restrict__ g2,
                            const float* __restrict__ b2, const float* __restrict__ m2,
                            const float* __restrict__ v2,
                            const float* __restrict__ w3, const float* __restrict__ g3,
                            const float* __restrict__ b3, const float* __restrict__ m3,
                            const float* __restrict__ v3) {
    int total = 64 * C + C * C4 + 64 + C;
    for (int i = blockIdx.x * blockDim.x + threadIdx.x; i < total;
         i += gridDim.x * blockDim.x) {
        if (i < 64 * C) {
            int o = i >> 7, c = i & 127;
            float s, w;
            if (o < 32) { s = g1[o] * rsqrtf(v1[o] + EPS); w = w1[o * C + c]; }
            else        { int o2 = o - 32; s = g2[o2] * rsqrtf(v2[o2] + EPS); w = w2[o2 * C + c]; }
            g_w12t[o * C + c] = f2tf(w * s);
        } else if (i < 64 * C + C * C4) {
            int j = i - 64 * C;
            int o = j >> 5, c = j & 31;
            float s = g3[o] * rsqrtf(v3[o] + EPS);
            g_w3t[o * C4 + c] = f2tf(w3[o * C4 + c] * s);
        } else if (i < 64 * C + C * C4 + 64) {
            int o = i - 64 * C - C * C4;
            if (o < 32) { float s = g1[o] * rsqrtf(v1[o] + EPS); g_b12s[o] = b1[o] - m1[o] * s; }
            else        { int o2 = o - 32; float s = g2[o2] * rsqrtf(v2[o2] + EPS); g_b12s[o] = b2[o2] - m2[o2] * s; }
        } else {
            int o = i - 64 * C - C * C4 - 64;
            float s = g3[o] * rsqrtf(v3[o] + EPS);
            g_b3s[o] = b3[o] - m3[o] * s;
        }
    }
}

// ---------------------------------------------------------------------------
// Fused pointwise conv 1+2 via tf32 mma (unchanged)
// ---------------------------------------------------------------------------
__global__ void __launch_bounds__(128) conv12_kernel(const float* __restrict__ x,
                                                     const float* __restrict__ a1p,
                                                     const float* __restrict__ a2p) {
    __shared__ unsigned sw[64 * WP];
    __shared__ unsigned xs[32 * XP];

    int tid = threadIdx.x, w = tid >> 5, lane = tid & 31;
    int grp = lane >> 2, tig = lane & 3;
    int s0 = blockIdx.x * 128;
    int b = s0 >> 17;
    int sb = s0 & (TF - 1);
    const float* xb = x + (size_t)b * C * TF + sb;

    float of[16][4];
    {
        float bi0 = g_b12s[w * 16 + grp];
        float bi1 = g_b12s[w * 16 + grp + 8];
#pragma unroll
        for (int nt = 0; nt < 16; nt++) {
            of[nt][0] = bi0; of[nt][1] = bi0;
            of[nt][2] = bi1; of[nt][3] = bi1;
        }
    }

    for (int ch = 0; ch < 4; ch++) {
        __syncthreads();
#pragma unroll
        for (int j = 0; j < 16; j++) {
            int i = tid + j * 128;
            int o = i >> 5, kk = i & 31;
            sw[o * WP + kk] = g_w12t[o * C + ch * 32 + kk];
        }
#pragma unroll
        for (int j = 0; j < 8; j++) {
            int i = tid + j * 128;
            int cc = i >> 5, p4 = i & 31;
            float4 v = *(const float4*)(xb + (size_t)(ch * 32 + cc) * TF + p4 * 4);
            uint4 u;
            u.x = f2tf(v.x); u.y = f2tf(v.y); u.z = f2tf(v.z); u.w = f2tf(v.w);
            *(uint4*)&xs[cc * XP + p4 * 4] = u;
        }
        __syncthreads();

#pragma unroll
        for (int ks = 0; ks < 4; ks++) {
            unsigned af[4];
            af[0] = sw[(w * 16 + grp) * WP + ks * 8 + tig];
            af[1] = sw[(w * 16 + grp + 8) * WP + ks * 8 + tig];
            af[2] = sw[(w * 16 + grp) * WP + ks * 8 + tig + 4];
            af[3] = sw[(w * 16 + grp + 8) * WP + ks * 8 + tig + 4];
#pragma unroll
            for (int nt = 0; nt < 16; nt++) {
                unsigned bf[2];
                bf[0] = xs[(ks * 8 + tig) * XP + nt * 8 + grp];
                bf[1] = xs[(ks * 8 + tig + 4) * XP + nt * 8 + grp];
                mma8(of[nt], af, bf);
            }
        }
    }

    float a = (w < 2) ? a1p[0] : a2p[0];
    int ch0 = w * 16 + grp;
    if (w < 2) {
#pragma unroll
        for (int nt = 0; nt < 16; nt++) {
            int pos = s0 + nt * 8 + 2 * tig;
            float y;
            y = of[nt][0]; y = y >= 0.f ? y : a * y; g_x1[(size_t)pos * 32 + ch0] = y;
            y = of[nt][1]; y = y >= 0.f ? y : a * y; g_x1[(size_t)(pos + 1) * 32 + ch0] = y;
            y = of[nt][2]; y = y >= 0.f ? y : a * y; g_x1[(size_t)pos * 32 + ch0 + 8] = y;
            y = of[nt][3]; y = y >= 0.f ? y : a * y; g_x1[(size_t)(pos + 1) * 32 + ch0 + 8] = y;
        }
    } else {
        int o2 = ch0 - 32;
#pragma unroll
        for (int nt = 0; nt < 16; nt++) {
            int pos = s0 + nt * 8 + 2 * tig;
            int t0 = (pos >> 8) & 511, f0 = pos & 255;
            int i0 = ((b * Fd + f0) * T + t0) * 32;
            int t1 = ((pos + 1) >> 8) & 511, f1 = (pos + 1) & 255;
            int i1 = ((b * Fd + f1) * T + t1) * 32;
            float y;
            y = of[nt][0]; y = y >= 0.f ? y : a * y; g_x2[i0 + o2] = y;
            y = of[nt][1]; y = y >= 0.f ? y : a * y; g_x2[i1 + o2] = y;
            y = of[nt][2]; y = y >= 0.f ? y : a * y; g_x2[i0 + o2 + 8] = y;
            y = of[nt][3]; y = y >= 0.f ? y : a * y; g_x2[i1 + o2 + 8] = y;
        }
    }
}

// ---------------------------------------------------------------------------
// Frequency attention v3: whole-tile smem, 256 threads, ONE barrier,
// NO-MAX softmax (scores analytically bounded; shift-invariant => exact).
// ---------------------------------------------------------------------------
__global__ void __launch_bounds__(256, 2) freq_attn_kernel() {
    __shared__ unsigned sKb[256 * KBP];   // 20 KB
    __shared__ unsigned sVb[32 * XP];     // 17.4 KB

    int blk = blockIdx.x;                 // b*T + t
    int tid = threadIdx.x, w = tid >> 5, lane = tid & 31;
    int grp = lane >> 2, tig = lane & 3;
    int base = blk * (Fd * C4);
    const float inv = (1.0f / 128.0f) * LOG2E;

    unsigned qf[2][2][4];
#pragma unroll
    for (int m = 0; m < 2; m++) {
        const float* q0 = &g_x1[base + (w * 32 + m * 16 + grp) * C4];
        const float* q1 = q0 + 8 * C4;
#pragma unroll
        for (int ks = 0; ks < 2; ks++) {
            int cb = ks * 16 + 2 * tig;
            qf[m][ks][0] = pk2(q0[cb] * inv, q0[cb + 1] * inv);
            qf[m][ks][1] = pk2(q1[cb] * inv, q1[cb + 1] * inv);
            qf[m][ks][2] = pk2(q0[cb + 8] * inv, q0[cb + 9] * inv);
            qf[m][ks][3] = pk2(q1[cb + 8] * inv, q1[cb + 9] * inv);
        }
    }
    float of[2][4][4];
#pragma unroll
    for (int m = 0; m < 2; m++)
#pragma unroll
        for (int n = 0; n < 4; n++)
#pragma unroll
            for (int r = 0; r < 4; r++) of[m][n][r] = 0.f;
    float l[2][2];
#pragma unroll
    for (int m = 0; m < 2; m++) { l[m][0] = 0.f; l[m][1] = 0.f; }

    {
        const float4* src = (const float4*)&g_x1[base];
#pragma unroll
        for (int j = 0; j < 8; j++) {
            int i = tid + j * 256;
            float4 v = src[i];
            int row = i >> 3, c4 = i & 7;
            sKb[row * KBP + c4 * 2]     = pk2(v.x, v.y);
            sKb[row * KBP + c4 * 2 + 1] = pk2(v.z, v.w);
        }
#pragma unroll
        for (int it = 0; it < 4; it++) {
            int idx = tid + it * 256;
            int pr = idx & 127, cg4 = idx >> 7;
            const float* v0 = &g_x1[base + (2 * pr) * C4 + cg4 * 4];
            float4 va = *(const float4*)v0;
            float4 vb = *(const float4*)(v0 + C4);
            sVb[(cg4 * 4 + 0) * XP + pr] = pk2(va.x, vb.x);
            sVb[(cg4 * 4 + 1) * XP + pr] = pk2(va.y, vb.y);
            sVb[(cg4 * 4 + 2) * XP + pr] = pk2(va.z, vb.z);
            sVb[(cg4 * 4 + 3) * XP + pr] = pk2(va.w, vb.w);
        }
    }
    __syncthreads();

    for (int c = 0; c < 8; c++) {
        float sf[2][4][4];
#pragma unroll
        for (int m = 0; m < 2; m++)
#pragma unroll
            for (int n = 0; n < 4; n++)
#pragma unroll
                for (int r = 0; r < 4; r++) sf[m][n][r] = 0.f;
#pragma unroll
        for (int n = 0; n < 4; n++) {
#pragma unroll
            for (int ks = 0; ks < 2; ks++) {
                const unsigned* kb = &sKb[(c * 32 + n * 8 + grp) * KBP + ks * 8 + tig];
                unsigned bfr[2] = { kb[0], kb[4] };
                mma16(sf[0][n], qf[0][ks], bfr);
                mma16(sf[1][n], qf[1][ks], bfr);
            }
        }
#pragma unroll
        for (int m = 0; m < 2; m++) {
            float p[4][4];
            float rs0 = 0.f, rs1 = 0.f;
#pragma unroll
            for (int n = 0; n < 4; n++) {
                p[n][0] = ex2(sf[m][n][0]);
                p[n][1] = ex2(sf[m][n][1]);
                p[n][2] = ex2(sf[m][n][2]);
                p[n][3] = ex2(sf[m][n][3]);
                rs0 += p[n][0] + p[n][1]; rs1 += p[n][2] + p[n][3];
            }
            l[m][0] += rs0;
            l[m][1] += rs1;
            unsigned pa[2][4];
#pragma unroll
            for (int kk = 0; kk < 2; kk++) {
                pa[kk][0] = pk2(p[2 * kk][0], p[2 * kk][1]);
                pa[kk][1] = pk2(p[2 * kk][2], p[2 * kk][3]);
                pa[kk][2] = pk2(p[2 * kk + 1][0], p[2 * kk + 1][1]);
                pa[kk][3] = pk2(p[2 * kk + 1][2], p[2 * kk + 1][3]);
            }
#pragma unroll
            for (int n = 0; n < 4; n++) {
#pragma unroll
                for (int kk = 0; kk < 2; kk++) {
                    const unsigned* vbp = &sVb[(n * 8 + grp) * XP + c * 16 + kk * 8 + tig];
                    unsigned vb[2] = { vbp[0], vbp[4] };
                    mma16(of[m][n], pa[kk], vb);
                }
            }
        }
    }
    int b = blk / T, t = blk % T;
#pragma unroll
    for (int m = 0; m < 2; m++) {
        int ql = w * 32 + m * 16 + grp;
        float r0 = 1.0f / qsum(l[m][0]);
        float r1 = 1.0f / qsum(l[m][1]);
        float* d0 = &g_of[((b * Fd + ql) * T + t) * C4];
        float* d1 = &g_of[((b * Fd + ql + 8) * T + t) * C4];
#pragma unroll
        for (int n = 0; n < 4; n++) {
            int ch = n * 8 + 2 * tig;
            *(float2*)&d0[ch] = make_float2(of[m][n][0] * r0, of[m][n][1] * r0);
            *(float2*)&d1[ch] = make_float2(of[m][n][2] * r1, of[m][n][3] * r1);
        }
    }
}

// ---------------------------------------------------------------------------
// Causal time attention v3: staged whole-tile smem, 256 threads, NO-MAX softmax.
// ---------------------------------------------------------------------------
__global__ void __launch_bounds__(256, 2) time_attn_kernel() {
    __shared__ unsigned sKb[256 * KBP];   // 20 KB
    __shared__ unsigned sVb[32 * XP];     // 17.4 KB

    int blk = blockIdx.x;
    int half = blk & 1, bf = blk >> 1;
    int tid = threadIdx.x, w = tid >> 5, lane = tid & 31;
    int grp = lane >> 2, tig = lane & 3;
    int base = bf * (T * C4);
    int qbase = half * 256;
    int qblk = half * 8 + w;
    const float inv = 0.005524271728019903f * LOG2E;

    unsigned qf[2][2][4];
#pragma unroll
    for (int m = 0; m < 2; m++) {
        const float* q0 = &g_x2[base + (qbase + w * 32 + m * 16 + grp) * C4];
        const float* q1 = q0 + 8 * C4;
#pragma unroll
        for (int ks = 0; ks < 2; ks++) {
            int cb = ks * 16 + 2 * tig;
            qf[m][ks][0] = pk2(q0[cb] * inv, q0[cb + 1] * inv);
            qf[m][ks][1] = pk2(q1[cb] * inv, q1[cb + 1] * inv);
            qf[m][ks][2] = pk2(q0[cb + 8] * inv, q0[cb + 9] * inv);
            qf[m][ks][3] = pk2(q1[cb + 8] * inv, q1[cb + 9] * inv);
        }
    }
    float of[2][4][4];
#pragma unroll
    for (int m = 0; m < 2; m++)
#pragma unroll
        for (int n = 0; n < 4; n++)
#pragma unroll
            for (int r = 0; r < 4; r++) of[m][n][r] = 0.f;
    float l[2][2];
#pragma unroll
    for (int m = 0; m < 2; m++) { l[m][0] = 0.f; l[m][1] = 0.f; }

    for (int stage = 0; stage <= half; stage++) {
        if (stage) __syncthreads();
        {
            const float4* ks4 = (const float4*)&g_x2[base + stage * 256 * C4];
#pragma unroll
            for (int j = 0; j < 8; j++) {
                int i = tid + j * 256;
                float4 v = ks4[i];
                int row = i >> 3, c4 = i & 7;
                sKb[row * KBP + c4 * 2]     = pk2(v.x, v.y);
                sKb[row * KBP + c4 * 2 + 1] = pk2(v.z, v.w);
            }
#pragma unroll
            for (int it = 0; it < 4; it++) {
                int idx = tid + it * 256;
                int pr = idx & 127, cg4 = idx >> 7;
                const float* v0 = &g_of[base + stage * 256 * C4 + (2 * pr) * C4 + cg4 * 4];
                float4 va = *(const float4*)v0;
                float4 vb = *(const float4*)(v0 + C4);
                sVb[(cg4 * 4 + 0) * XP + pr] = pk2(va.x, vb.x);
                sVb[(cg4 * 4 + 1) * XP + pr] = pk2(va.y, vb.y);
                sVb[(cg4 * 4 + 2) * XP + pr] = pk2(va.z, vb.z);
                sVb[(cg4 * 4 + 3) * XP + pr] = pk2(va.w, vb.w);
            }
        }
        __syncthreads();

        for (int c = 0; c < 8; c++) {
            int kb32 = stage * 8 + c;
            if (kb32 > qblk) continue;
            float sf[2][4][4];
#pragma unroll
            for (int m = 0; m < 2; m++)
#pragma unroll
                for (int n = 0; n < 4; n++)
#pragma unroll
                    for (int r = 0; r < 4; r++) sf[m][n][r] = 0.f;
#pragma unroll
            for (int n = 0; n < 4; n++) {
#pragma unroll
                for (int ks = 0; ks < 2; ks++) {
                    const unsigned* kb = &sKb[(c * 32 + n * 8 + grp) * KBP + ks * 8 + tig];
                    unsigned bfr[2] = { kb[0], kb[4] };
                    mma16(sf[0][n], qf[0][ks], bfr);
                    mma16(sf[1][n], qf[1][ks], bfr);
                }
            }
            bool diag = (kb32 == qblk);
#pragma unroll
            for (int m = 0; m < 2; m++) {
                if (diag) {
                    int R0 = qbase + w * 32 + m * 16 + grp;
                    int R1 = R0 + 8;
#pragma unroll
                    for (int n = 0; n < 4; n++) {
                        int cb = stage * 256 + c * 32 + n * 8 + 2 * tig;
                        if (cb > R0)     sf[m][n][0] = NEG;
                        if (cb + 1 > R0) sf[m][n][1] = NEG;
                        if (cb > R1)     sf[m][n][2] = NEG;
                        if (cb + 1 > R1) sf[m][n][3] = NEG;
                    }
                }
                float p[4][4];
                float rs0 = 0.f, rs1 = 0.f;
#pragma unroll
                for (int n = 0; n < 4; n++) {
                    p[n][0] = ex2(sf[m][n][0]);
                    p[n][1] = ex2(sf[m][n][1]);
                    p[n][2] = ex2(sf[m][n][2]);
                    p[n][3] = ex2(sf[m][n][3]);
                    rs0 += p[n][0] + p[n][1]; rs1 += p[n][2] + p[n][3];
                }
                l[m][0] += rs0;
                l[m][1] += rs1;
                unsigned pa[2][4];
#pragma unroll
                for (int kk = 0; kk < 2; kk++) {
                    pa[kk][0] = pk2(p[2 * kk][0], p[2 * kk][1]);
                    pa[kk][1] = pk2(p[2 * kk][2], p[2 * kk][3]);
                    pa[kk][2] = pk2(p[2 * kk + 1][0], p[2 * kk + 1][1]);
                    pa[kk][3] = pk2(p[2 * kk + 1][2], p[2 * kk + 1][3]);
                }
#pragma unroll
                for (int n = 0; n < 4; n++) {
#pragma unroll
                    for (int kk = 0; kk < 2; kk++) {
                        const unsigned* vbp = &sVb[(n * 8 + grp) * XP + c * 16 + kk * 8 + tig];
                        unsigned vb[2] = { vbp[0], vbp[4] };
                        mma16(of[m][n], pa[kk], vb);
                    }
                }
            }
        }
    }
#pragma unroll
    for (int m = 0; m < 2; m++) {
        int ql = qbase + w * 32 + m * 16 + grp;
        float r0 = 1.0f / qsum(l[m][0]);
        float r1 = 1.0f / qsum(l[m][1]);
        float* d0 = &g_M[base + ql * C4];
        float* d1 = &g_M[base + (ql + 8) * C4];
#pragma unroll
        for (int n = 0; n < 4; n++) {
            int ch = n * 8 + 2 * tig;
            *(float2*)&d0[ch] = make_float2(of[m][n][0] * r0, of[m][n][1] * r0);
            *(float2*)&d1[ch] = make_float2(of[m][n][2] * r1, of[m][n][3] * r1);
        }
    }
}

// ---------------------------------------------------------------------------
// Final pointwise conv (+BN +PReLU) + residual via tf32 mma (unchanged)
// ---------------------------------------------------------------------------
__global__ void __launch_bounds__(128) final_kernel(const float* __restrict__ x,
                                                    const float* __restrict__ a3p,
                                                    float* __restrict__ out) {
    __shared__ unsigned sw3[C * WP];
    __shared__ unsigned sM[32 * XP];

    int tid = threadIdx.x, w = tid >> 5, lane = tid & 31;
    int grp = lane >> 2, tig = lane & 3;
    int s0 = blockIdx.x * 128;
    int b = s0 >> 17;
    int sb = s0 & (TF - 1);
    int t0 = sb >> 8;
    int f0 = sb & 255;

#pragma unroll
    for (int j = 0; j < 32; j++) {
        int i = tid + j * 128;
        int o = i >> 5, c = i & 31;
        sw3[o * WP + c] = g_w3t[i];
    }
    {
        const float4* ms = (const float4*)&g_M[((b * Fd + f0 + tid) * T + t0) * C4];
#pragma unroll
        for (int c4 = 0; c4 < 8; c4++) {
            float4 m = ms[c4];
            sM[(c4 * 4 + 0) * XP + tid] = f2tf(m.x);
            sM[(c4 * 4 + 1) * XP + tid] = f2tf(m.y);
            sM[(c4 * 4 + 2) * XP + tid] = f2tf(m.z);
            sM[(c4 * 4 + 3) * XP + tid] = f2tf(m.w);
        }
    }
    __syncthreads();

    float a3 = a3p[0];
#pragma unroll
    for (int op = 0; op < 2; op++) {
        int o0 = op * 64 + w * 16 + grp;
        float bi0 = g_b3s[o0];
        float bi1 = g_b3s[o0 + 8];
        float of[16][4];
#pragma unroll
        for (int nt = 0; nt < 16; nt++) {
            of[nt][0] = bi0; of[nt][1] = bi0;
            of[nt][2] = bi1; of[nt][3] = bi1;
        }
#pragma unroll
        for (int ks = 0; ks < 4; ks++) {
            unsigned af[4];
            af[0] = sw3[o0 * WP + ks * 8 + tig];
            af[1] = sw3[(o0 + 8) * WP + ks * 8 + tig];
            af[2] = sw3[o0 * WP + ks * 8 + tig + 4];
            af[3] = sw3[(o0 + 8) * WP + ks * 8 + tig + 4];
#pragma unroll
            for (int nt = 0; nt < 16; nt++) {
                unsigned bf[2];
                bf[0] = sM[(ks * 8 + tig) * XP + nt * 8 + grp];
                bf[1] = sM[(ks * 8 + tig + 4) * XP + nt * 8 + grp];
                mma8(of[nt], af, bf);
            }
        }
#pragma unroll
        for (int nt = 0; nt < 16; nt++) {
            int lpos = sb + nt * 8 + 2 * tig;
            int idx0 = (b * C + o0) * TF + lpos;
            int idx1 = (b * C + o0 + 8) * TF + lpos;
            float2 x0 = *(const float2*)&x[idx0];
            float2 x1 = *(const float2*)&x[idx1];
            float y0 = of[nt][0], y1 = of[nt][1], y2 = of[nt][2], y3 = of[nt][3];
            y0 = y0 >= 0.f ? y0 : a3 * y0;
            y1 = y1 >= 0.f ? y1 : a3 * y1;
            y2 = y2 >= 0.f ? y2 : a3 * y2;
            y3 = y3 >= 0.f ? y3 : a3 * y3;
            *(float2*)&out[idx0] = make_float2(y0 + x0.x, y1 + x0.y);
            *(float2*)&out[idx1] = make_float2(y2 + x1.x, y3 + x1.y);
        }
    }
}

// ---------------------------------------------------------------------------
extern "C" void kernel_launch(void* const* d_in, const int* in_sizes, int n_in,
                              void* d_out, int out_size) {
    const float* x  = (const float*)d_in[0];
    const float* w1 = (const float*)d_in[1];
    const float* g1 = (const float*)d_in[2];
    const float* b1 = (const float*)d_in[3];
    const float* m1 = (const float*)d_in[4];
    const float* v1 = (const float*)d_in[5];
    const float* a1 = (const float*)d_in[6];
    const float* w2 = (const float*)d_in[7];
    const float* g2 = (const float*)d_in[8];
    const float* b2 = (const float*)d_in[9];
    const float* m2 = (const float*)d_in[10];
    const float* v2 = (const float*)d_in[11];
    const float* a2 = (const float*)d_in[12];
    const float* w3 = (const float*)d_in[13];
    const float* g3 = (const float*)d_in[14];
    const float* b3 = (const float*)d_in[15];
    const float* m3 = (const float*)d_in[16];
    const float* v3 = (const float*)d_in[17];
    const float* a3 = (const float*)d_in[18];
    float* out = (float*)d_out;

    prep_kernel<<<16, 256>>>(w1, g1, b1, m1, v1, w2, g2, b2, m2, v2,
                             w3, g3, b3, m3, v3);
    conv12_kernel<<<(B * T * Fd) / 128, 128>>>(x, a1, a2);
    freq_attn_kernel<<<B * T, 256>>>();
    time_attn_kernel<<<B * Fd * 2, 256>>>();
    final_kernel<<<(B * T * Fd) / 128, 128>>>(x, a3, out);
}

// round 17
// speedup vs baseline: 5.5432x; 1.0596x over previous
#include <cuda_runtime.h>
#include <math.h>

#define B  2
#define C  128
#define C4 32
#define T  512
#define Fd 256
#define TF (T * Fd)
#define EPS 1e-5f
#define KBP 20    // K tile row pad (words): banks 20*grp+tig all distinct
#define WP  36
#define XP  136   // V tile / conv row pad: banks 8*tig+grp all distinct
#define NEG -1.0e30f
#define LOG2E 1.4426950408889634f

// ---- scratch (static device memory; no allocation allowed) ----
__device__ unsigned g_w12t[64 * C];   // fused+scaled w1|w2, tf32, layout [o][c]
__device__ float g_b12s[64];
__device__ unsigned g_w3t[C * C4];    // fused+scaled w3, tf32, layout [o][c]
__device__ float g_b3s[C];
__device__ float g_x1[B * T * Fd * C4];   // [b][t][f][c]
__device__ float g_x2[B * Fd * T * C4];   // [b][f][t][c]
__device__ float g_of[B * Fd * T * C4];   // [b][f][t][c]
__device__ float g_M [B * Fd * T * C4];   // [b][f][t][c]

// ---------------------------------------------------------------------------
__device__ __forceinline__ unsigned f2tf(float f) {
    unsigned u;
    asm("cvt.rna.tf32.f32 %0, %1;" : "=r"(u) : "f"(f));
    return u;
}

__device__ __forceinline__ unsigned pk2(float lo, float hi) {
    unsigned r;
    asm("cvt.rn.bf16x2.f32 %0, %1, %2;" : "=r"(r) : "f"(hi), "f"(lo));
    return r;
}

__device__ __forceinline__ float ex2(float x) {
    float r;
    asm("ex2.approx.f32 %0, %1;" : "=f"(r) : "f"(x));
    return r;
}

__device__ __forceinline__ void mma8(float d[4], const unsigned a[4], const unsigned b[2]) {
    asm volatile(
        "mma.sync.aligned.m16n8k8.row.col.f32.tf32.tf32.f32 "
        "{%0,%1,%2,%3},{%4,%5,%6,%7},{%8,%9},{%0,%1,%2,%3};"
        : "+f"(d[0]), "+f"(d[1]), "+f"(d[2]), "+f"(d[3])
        : "r"(a[0]), "r"(a[1]), "r"(a[2]), "r"(a[3]), "r"(b[0]), "r"(b[1]));
}

__device__ __forceinline__ void mma16(float d[4], const unsigned a[4], const unsigned b[2]) {
    asm volatile(
        "mma.sync.aligned.m16n8k16.row.col.f32.bf16.bf16.f32 "
        "{%0,%1,%2,%3},{%4,%5,%6,%7},{%8,%9},{%0,%1,%2,%3};"
        : "+f"(d[0]), "+f"(d[1]), "+f"(d[2]), "+f"(d[3])
        : "r"(a[0]), "r"(a[1]), "r"(a[2]), "r"(a[3]), "r"(b[0]), "r"(b[1]));
}

__device__ __forceinline__ float qsum(float v) {
    v += __shfl_xor_sync(0xffffffffu, v, 1);
    v += __shfl_xor_sync(0xffffffffu, v, 2);
    return v;
}

// ---------------------------------------------------------------------------
// Shared attention chunk: S-mma (32 keys at tile chunk c) + no-max softmax
// + PV-mma. Diagonal mask uses LOCAL coords (kb*32 == qb*32 cancels).
// ---------------------------------------------------------------------------
__device__ __forceinline__ void attn_chunk(
    const unsigned* __restrict__ sKb, const unsigned* __restrict__ sVb,
    int c, bool diag,
    const unsigned (&qf)[2][2][4], float (&of)[2][4][4], float (&l)[2][2],
    int grp, int tig)
{
    float sf[2][4][4];
#pragma unroll
    for (int m = 0; m < 2; m++)
#pragma unroll
        for (int n = 0; n < 4; n++)
#pragma unroll
            for (int r = 0; r < 4; r++) sf[m][n][r] = 0.f;
#pragma unroll
    for (int n = 0; n < 4; n++) {
#pragma unroll
        for (int ks = 0; ks < 2; ks++) {
            const unsigned* kb = &sKb[(c * 32 + n * 8 + grp) * KBP + ks * 8 + tig];
            unsigned bfr[2] = { kb[0], kb[4] };
            mma16(sf[0][n], qf[0][ks], bfr);
            mma16(sf[1][n], qf[1][ks], bfr);
        }
    }
#pragma unroll
    for (int m = 0; m < 2; m++) {
        if (diag) {
            int R0 = m * 16 + grp;
            int R1 = R0 + 8;
#pragma unroll
            for (int n = 0; n < 4; n++) {
                int cb = n * 8 + 2 * tig;
                if (cb > R0)     sf[m][n][0] = NEG;
                if (cb + 1 > R0) sf[m][n][1] = NEG;
                if (cb > R1)     sf[m][n][2] = NEG;
                if (cb + 1 > R1) sf[m][n][3] = NEG;
            }
        }
        float p[4][4];
        float rs0 = 0.f, rs1 = 0.f;
#pragma unroll
        for (int n = 0; n < 4; n++) {
            p[n][0] = ex2(sf[m][n][0]);
            p[n][1] = ex2(sf[m][n][1]);
            p[n][2] = ex2(sf[m][n][2]);
            p[n][3] = ex2(sf[m][n][3]);
            rs0 += p[n][0] + p[n][1]; rs1 += p[n][2] + p[n][3];
        }
        l[m][0] += rs0;
        l[m][1] += rs1;
        unsigned pa[2][4];
#pragma unroll
        for (int kk = 0; kk < 2; kk++) {
            pa[kk][0] = pk2(p[2 * kk][0], p[2 * kk][1]);
            pa[kk][1] = pk2(p[2 * kk][2], p[2 * kk][3]);
            pa[kk][2] = pk2(p[2 * kk + 1][0], p[2 * kk + 1][1]);
            pa[kk][3] = pk2(p[2 * kk + 1][2], p[2 * kk + 1][3]);
        }
#pragma unroll
        for (int n = 0; n < 4; n++) {
#pragma unroll
            for (int kk = 0; kk < 2; kk++) {
                const unsigned* vbp = &sVb[(n * 8 + grp) * XP + c * 16 + kk * 8 + tig];
                unsigned vb[2] = { vbp[0], vbp[4] };
                mma16(of[m][n], pa[kk], vb);
            }
        }
    }
}

// ---------------------------------------------------------------------------
// Prep (unchanged)
// ---------------------------------------------------------------------------
__global__ void prep_kernel(const float* __restrict__ w1, const float* __restrict__ g1,
                            const float* __restrict__ b1, const float* __restrict__ m1,
                            const float* __restrict__ v1,
                            const float* __restrict__ w2, const float* __restrict__ g2,
                            const float* __restrict__ b2, const float* __restrict__ m2,
                            const float* __restrict__ v2,
                            const float* __restrict__ w3, const float* __restrict__ g3,
                            const float* __restrict__ b3, const float* __restrict__ m3,
                            const float* __restrict__ v3) {
    int total = 64 * C + C * C4 + 64 + C;
    for (int i = blockIdx.x * blockDim.x + threadIdx.x; i < total;
         i += gridDim.x * blockDim.x) {
        if (i < 64 * C) {
            int o = i >> 7, c = i & 127;
            float s, w;
            if (o < 32) { s = g1[o] * rsqrtf(v1[o] + EPS); w = w1[o * C + c]; }
            else        { int o2 = o - 32; s = g2[o2] * rsqrtf(v2[o2] + EPS); w = w2[o2 * C + c]; }
            g_w12t[o * C + c] = f2tf(w * s);
        } else if (i < 64 * C + C * C4) {
            int j = i - 64 * C;
            int o = j >> 5, c = j & 31;
            float s = g3[o] * rsqrtf(v3[o] + EPS);
            g_w3t[o * C4 + c] = f2tf(w3[o * C4 + c] * s);
        } else if (i < 64 * C + C * C4 + 64) {
            int o = i - 64 * C - C * C4;
            if (o < 32) { float s = g1[o] * rsqrtf(v1[o] + EPS); g_b12s[o] = b1[o] - m1[o] * s; }
            else        { int o2 = o - 32; float s = g2[o2] * rsqrtf(v2[o2] + EPS); g_b12s[o] = b2[o2] - m2[o2] * s; }
        } else {
            int o = i - 64 * C - C * C4 - 64;
            float s = g3[o] * rsqrtf(v3[o] + EPS);
            g_b3s[o] = b3[o] - m3[o] * s;
        }
    }
}

// ---------------------------------------------------------------------------
// Fused pointwise conv 1+2 via tf32 mma (unchanged)
// ---------------------------------------------------------------------------
__global__ void __launch_bounds__(128) conv12_kernel(const float* __restrict__ x,
                                                     const float* __restrict__ a1p,
                                                     const float* __restrict__ a2p) {
    __shared__ unsigned sw[64 * WP];
    __shared__ unsigned xs[32 * XP];

    int tid = threadIdx.x, w = tid >> 5, lane = tid & 31;
    int grp = lane >> 2, tig = lane & 3;
    int s0 = blockIdx.x * 128;
    int b = s0 >> 17;
    int sb = s0 & (TF - 1);
    const float* xb = x + (size_t)b * C * TF + sb;

    float of[16][4];
    {
        float bi0 = g_b12s[w * 16 + grp];
        float bi1 = g_b12s[w * 16 + grp + 8];
#pragma unroll
        for (int nt = 0; nt < 16; nt++) {
            of[nt][0] = bi0; of[nt][1] = bi0;
            of[nt][2] = bi1; of[nt][3] = bi1;
        }
    }

    for (int ch = 0; ch < 4; ch++) {
        __syncthreads();
#pragma unroll
        for (int j = 0; j < 16; j++) {
            int i = tid + j * 128;
            int o = i >> 5, kk = i & 31;
            sw[o * WP + kk] = g_w12t[o * C + ch * 32 + kk];
        }
#pragma unroll
        for (int j = 0; j < 8; j++) {
            int i = tid + j * 128;
            int cc = i >> 5, p4 = i & 31;
            float4 v = *(const float4*)(xb + (size_t)(ch * 32 + cc) * TF + p4 * 4);
            uint4 u;
            u.x = f2tf(v.x); u.y = f2tf(v.y); u.z = f2tf(v.z); u.w = f2tf(v.w);
            *(uint4*)&xs[cc * XP + p4 * 4] = u;
        }
        __syncthreads();

#pragma unroll
        for (int ks = 0; ks < 4; ks++) {
            unsigned af[4];
            af[0] = sw[(w * 16 + grp) * WP + ks * 8 + tig];
            af[1] = sw[(w * 16 + grp + 8) * WP + ks * 8 + tig];
            af[2] = sw[(w * 16 + grp) * WP + ks * 8 + tig + 4];
            af[3] = sw[(w * 16 + grp + 8) * WP + ks * 8 + tig + 4];
#pragma unroll
            for (int nt = 0; nt < 16; nt++) {
                unsigned bf[2];
                bf[0] = xs[(ks * 8 + tig) * XP + nt * 8 + grp];
                bf[1] = xs[(ks * 8 + tig + 4) * XP + nt * 8 + grp];
                mma8(of[nt], af, bf);
            }
        }
    }

    float a = (w < 2) ? a1p[0] : a2p[0];
    int ch0 = w * 16 + grp;
    if (w < 2) {
#pragma unroll
        for (int nt = 0; nt < 16; nt++) {
            int pos = s0 + nt * 8 + 2 * tig;
            float y;
            y = of[nt][0]; y = y >= 0.f ? y : a * y; g_x1[(size_t)pos * 32 + ch0] = y;
            y = of[nt][1]; y = y >= 0.f ? y : a * y; g_x1[(size_t)(pos + 1) * 32 + ch0] = y;
            y = of[nt][2]; y = y >= 0.f ? y : a * y; g_x1[(size_t)pos * 32 + ch0 + 8] = y;
            y = of[nt][3]; y = y >= 0.f ? y : a * y; g_x1[(size_t)(pos + 1) * 32 + ch0 + 8] = y;
        }
    } else {
        int o2 = ch0 - 32;
#pragma unroll
        for (int nt = 0; nt < 16; nt++) {
            int pos = s0 + nt * 8 + 2 * tig;
            int t0 = (pos >> 8) & 511, f0 = pos & 255;
            int i0 = ((b * Fd + f0) * T + t0) * 32;
            int t1 = ((pos + 1) >> 8) & 511, f1 = (pos + 1) & 255;
            int i1 = ((b * Fd + f1) * T + t1) * 32;
            float y;
            y = of[nt][0]; y = y >= 0.f ? y : a * y; g_x2[i0 + o2] = y;
            y = of[nt][1]; y = y >= 0.f ? y : a * y; g_x2[i1 + o2] = y;
            y = of[nt][2]; y = y >= 0.f ? y : a * y; g_x2[i0 + o2 + 8] = y;
            y = of[nt][3]; y = y >= 0.f ? y : a * y; g_x2[i1 + o2 + 8] = y;
        }
    }
}

// ---------------------------------------------------------------------------
// Frequency attention (unchanged from R16): whole-tile smem, no-max softmax.
// ---------------------------------------------------------------------------
__global__ void __launch_bounds__(256, 2) freq_attn_kernel() {
    __shared__ unsigned sKb[256 * KBP];   // 20 KB
    __shared__ unsigned sVb[32 * XP];     // 17.4 KB

    int blk = blockIdx.x;                 // b*T + t
    int tid = threadIdx.x, w = tid >> 5, lane = tid & 31;
    int grp = lane >> 2, tig = lane & 3;
    int base = blk * (Fd * C4);
    const float inv = (1.0f / 128.0f) * LOG2E;

    unsigned qf[2][2][4];
#pragma unroll
    for (int m = 0; m < 2; m++) {
        const float* q0 = &g_x1[base + (w * 32 + m * 16 + grp) * C4];
        const float* q1 = q0 + 8 * C4;
#pragma unroll
        for (int ks = 0; ks < 2; ks++) {
            int cb = ks * 16 + 2 * tig;
            qf[m][ks][0] = pk2(q0[cb] * inv, q0[cb + 1] * inv);
            qf[m][ks][1] = pk2(q1[cb] * inv, q1[cb + 1] * inv);
            qf[m][ks][2] = pk2(q0[cb + 8] * inv, q0[cb + 9] * inv);
            qf[m][ks][3] = pk2(q1[cb + 8] * inv, q1[cb + 9] * inv);
        }
    }
    float of[2][4][4];
#pragma unroll
    for (int m = 0; m < 2; m++)
#pragma unroll
        for (int n = 0; n < 4; n++)
#pragma unroll
            for (int r = 0; r < 4; r++) of[m][n][r] = 0.f;
    float l[2][2];
#pragma unroll
    for (int m = 0; m < 2; m++) { l[m][0] = 0.f; l[m][1] = 0.f; }

    {
        const float4* src = (const float4*)&g_x1[base];
#pragma unroll
        for (int j = 0; j < 8; j++) {
            int i = tid + j * 256;
            float4 v = src[i];
            int row = i >> 3, c4 = i & 7;
            sKb[row * KBP + c4 * 2]     = pk2(v.x, v.y);
            sKb[row * KBP + c4 * 2 + 1] = pk2(v.z, v.w);
        }
#pragma unroll
        for (int it = 0; it < 4; it++) {
            int idx = tid + it * 256;
            int pr = idx & 127, cg4 = idx >> 7;
            const float* v0 = &g_x1[base + (2 * pr) * C4 + cg4 * 4];
            float4 va = *(const float4*)v0;
            float4 vb = *(const float4*)(v0 + C4);
            sVb[(cg4 * 4 + 0) * XP + pr] = pk2(va.x, vb.x);
            sVb[(cg4 * 4 + 1) * XP + pr] = pk2(va.y, vb.y);
            sVb[(cg4 * 4 + 2) * XP + pr] = pk2(va.z, vb.z);
            sVb[(cg4 * 4 + 3) * XP + pr] = pk2(va.w, vb.w);
        }
    }
    __syncthreads();

    for (int c = 0; c < 8; c++)
        attn_chunk(sKb, sVb, c, false, qf, of, l, grp, tig);

    int b = blk / T, t = blk % T;
#pragma unroll
    for (int m = 0; m < 2; m++) {
        int ql = w * 32 + m * 16 + grp;
        float r0 = 1.0f / qsum(l[m][0]);
        float r1 = 1.0f / qsum(l[m][1]);
        float* d0 = &g_of[((b * Fd + ql) * T + t) * C4];
        float* d1 = &g_of[((b * Fd + ql + 8) * T + t) * C4];
#pragma unroll
        for (int n = 0; n < 4; n++) {
            int ch = n * 8 + 2 * tig;
            *(float2*)&d0[ch] = make_float2(of[m][n][0] * r0, of[m][n][1] * r0);
            *(float2*)&d1[ch] = make_float2(of[m][n][2] * r1, of[m][n][3] * r1);
        }
    }
}

// ---------------------------------------------------------------------------
// Causal time attention v4: BALANCED warp pairing. One block per (b,f).
// Warp w handles q-block w (pass B, stage-0 keys) then q-block 15-w (pass A,
// stage-0 then stage-1 keys). Work = 17 chunks per warp, uniform.
// ---------------------------------------------------------------------------
__global__ void __launch_bounds__(256, 2) time_attn_kernel() {
    __shared__ unsigned sKb[256 * KBP];   // 20 KB
    __shared__ unsigned sVb[32 * XP];     // 17.4 KB

    int bf = blockIdx.x;
    int tid = threadIdx.x, w = tid >> 5, lane = tid & 31;
    int grp = lane >> 2, tig = lane & 3;
    int base = bf * (T * C4);
    const float inv = 0.005524271728019903f * LOG2E;

    // ---- load stage 0 tile (keys 0..255)
    {
        const float4* ks4 = (const float4*)&g_x2[base];
#pragma unroll
        for (int j = 0; j < 8; j++) {
            int i = tid + j * 256;
            float4 v = ks4[i];
            int row = i >> 3, c4 = i & 7;
            sKb[row * KBP + c4 * 2]     = pk2(v.x, v.y);
            sKb[row * KBP + c4 * 2 + 1] = pk2(v.z, v.w);
        }
#pragma unroll
        for (int it = 0; it < 4; it++) {
            int idx = tid + it * 256;
            int pr = idx & 127, cg4 = idx >> 7;
            const float* v0 = &g_of[base + (2 * pr) * C4 + cg4 * 4];
            float4 va = *(const float4*)v0;
            float4 vb = *(const float4*)(v0 + C4);
            sVb[(cg4 * 4 + 0) * XP + pr] = pk2(va.x, vb.x);
            sVb[(cg4 * 4 + 1) * XP + pr] = pk2(va.y, vb.y);
            sVb[(cg4 * 4 + 2) * XP + pr] = pk2(va.z, vb.z);
            sVb[(cg4 * 4 + 3) * XP + pr] = pk2(va.w, vb.w);
        }
    }
    __syncthreads();

    unsigned qf[2][2][4];
    float of[2][4][4];
    float l[2][2];

    // ======== pass B: q-block w (rows w*32..+31), chunks 0..w, diag at c==w
    {
        int qb = w;
#pragma unroll
        for (int m = 0; m < 2; m++) {
            const float* q0 = &g_x2[base + (qb * 32 + m * 16 + grp) * C4];
            const float* q1 = q0 + 8 * C4;
#pragma unroll
            for (int ks = 0; ks < 2; ks++) {
                int cb = ks * 16 + 2 * tig;
                qf[m][ks][0] = pk2(q0[cb] * inv, q0[cb + 1] * inv);
                qf[m][ks][1] = pk2(q1[cb] * inv, q1[cb + 1] * inv);
                qf[m][ks][2] = pk2(q0[cb + 8] * inv, q0[cb + 9] * inv);
                qf[m][ks][3] = pk2(q1[cb + 8] * inv, q1[cb + 9] * inv);
            }
        }
#pragma unroll
        for (int m = 0; m < 2; m++) {
#pragma unroll
            for (int n = 0; n < 4; n++)
#pragma unroll
                for (int r = 0; r < 4; r++) of[m][n][r] = 0.f;
            l[m][0] = 0.f; l[m][1] = 0.f;
        }
        for (int c = 0; c <= w; c++)
            attn_chunk(sKb, sVb, c, c == w, qf, of, l, grp, tig);
#pragma unroll
        for (int m = 0; m < 2; m++) {
            int ql = qb * 32 + m * 16 + grp;
            float r0 = 1.0f / qsum(l[m][0]);
            float r1 = 1.0f / qsum(l[m][1]);
            float* d0 = &g_M[base + ql * C4];
            float* d1 = &g_M[base + (ql + 8) * C4];
#pragma unroll
            for (int n = 0; n < 4; n++) {
                int ch = n * 8 + 2 * tig;
                *(float2*)&d0[ch] = make_float2(of[m][n][0] * r0, of[m][n][1] * r0);
                *(float2*)&d1[ch] = make_float2(of[m][n][2] * r1, of[m][n][3] * r1);
            }
        }
    }

    // ======== pass A: q-block 15-w (rows (15-w)*32..+31)
    int qbA = 15 - w;
#pragma unroll
    for (int m = 0; m < 2; m++) {
        const float* q0 = &g_x2[base + (qbA * 32 + m * 16 + grp) * C4];
        const float* q1 = q0 + 8 * C4;
#pragma unroll
        for (int ks = 0; ks < 2; ks++) {
            int cb = ks * 16 + 2 * tig;
            qf[m][ks][0] = pk2(q0[cb] * inv, q0[cb + 1] * inv);
            qf[m][ks][1] = pk2(q1[cb] * inv, q1[cb + 1] * inv);
            qf[m][ks][2] = pk2(q0[cb + 8] * inv, q0[cb + 9] * inv);
            qf[m][ks][3] = pk2(q1[cb + 8] * inv, q1[cb + 9] * inv);
        }
    }
#pragma unroll
    for (int m = 0; m < 2; m++) {
#pragma unroll
        for (int n = 0; n < 4; n++)
#pragma unroll
            for (int r = 0; r < 4; r++) of[m][n][r] = 0.f;
        l[m][0] = 0.f; l[m][1] = 0.f;
    }
    // stage-0 chunks: kb 0..7, all < qbA (>=8) -> never diagonal
    for (int c = 0; c < 8; c++)
        attn_chunk(sKb, sVb, c, false, qf, of, l, grp, tig);

    __syncthreads();
    // ---- load stage 1 tile (keys 256..511)
    {
        const float4* ks4 = (const float4*)&g_x2[base + 256 * C4];
#pragma unroll
        for (int j = 0; j < 8; j++) {
            int i = tid + j * 256;
            float4 v = ks4[i];
            int row = i >> 3, c4 = i & 7;
            sKb[row * KBP + c4 * 2]     = pk2(v.x, v.y);
            sKb[row * KBP + c4 * 2 + 1] = pk2(v.z, v.w);
        }
#pragma unroll
        for (int it = 0; it < 4; it++) {
            int idx = tid + it * 256;
            int pr = idx & 127, cg4 = idx >> 7;
            const float* v0 = &g_of[base + 256 * C4 + (2 * pr) * C4 + cg4 * 4];
            float4 va = *(const float4*)v0;
            float4 vb = *(const float4*)(v0 + C4);
            sVb[(cg4 * 4 + 0) * XP + pr] = pk2(va.x, vb.x);
            sVb[(cg4 * 4 + 1) * XP + pr] = pk2(va.y, vb.y);
            sVb[(cg4 * 4 + 2) * XP + pr] = pk2(va.z, vb.z);
            sVb[(cg4 * 4 + 3) * XP + pr] = pk2(va.w, vb.w);
        }
    }
    __syncthreads();
    // stage-1 chunks: kb 8..qbA, diag at kb==qbA (chunk index kb-8)
    for (int kb = 8; kb <= qbA; kb++)
        attn_chunk(sKb, sVb, kb - 8, kb == qbA, qf, of, l, grp, tig);

#pragma unroll
    for (int m = 0; m < 2; m++) {
        int ql = qbA * 32 + m * 16 + grp;
        float r0 = 1.0f / qsum(l[m][0]);
        float r1 = 1.0f / qsum(l[m][1]);
        float* d0 = &g_M[base + ql * C4];
        float* d1 = &g_M[base + (ql + 8) * C4];
#pragma unroll
        for (int n = 0; n < 4; n++) {
            int ch = n * 8 + 2 * tig;
            *(float2*)&d0[ch] = make_float2(of[m][n][0] * r0, of[m][n][1] * r0);
            *(float2*)&d1[ch] = make_float2(of[m][n][2] * r1, of[m][n][3] * r1);
        }
    }
}

// ---------------------------------------------------------------------------
// Final pointwise conv (+BN +PReLU) + residual via tf32 mma (unchanged)
// ---------------------------------------------------------------------------
__global__ void __launch_bounds__(128) final_kernel(const float* __restrict__ x,
                                                    const float* __restrict__ a3p,
                                                    float* __restrict__ out) {
    __shared__ unsigned sw3[C * WP];
    __shared__ unsigned sM[32 * XP];

    int tid = threadIdx.x, w = tid >> 5, lane = tid & 31;
    int grp = lane >> 2, tig = lane & 3;
    int s0 = blockIdx.x * 128;
    int b = s0 >> 17;
    int sb = s0 & (TF - 1);
    int t0 = sb >> 8;
    int f0 = sb & 255;

#pragma unroll
    for (int j = 0; j < 32; j++) {
        int i = tid + j * 128;
        int o = i >> 5, c = i & 31;
        sw3[o * WP + c] = g_w3t[i];
    }
    {
        const float4* ms = (const float4*)&g_M[((b * Fd + f0 + tid) * T + t0) * C4];
#pragma unroll
        for (int c4 = 0; c4 < 8; c4++) {
            float4 m = ms[c4];
            sM[(c4 * 4 + 0) * XP + tid] = f2tf(m.x);
            sM[(c4 * 4 + 1) * XP + tid] = f2tf(m.y);
            sM[(c4 * 4 + 2) * XP + tid] = f2tf(m.z);
            sM[(c4 * 4 + 3) * XP + tid] = f2tf(m.w);
        }
    }
    __syncthreads();

    float a3 = a3p[0];
#pragma unroll
    for (int op = 0; op < 2; op++) {
        int o0 = op * 64 + w * 16 + grp;
        float bi0 = g_b3s[o0];
        float bi1 = g_b3s[o0 + 8];
        float of[16][4];
#pragma unroll
        for (int nt = 0; nt < 16; nt++) {
            of[nt][0] = bi0; of[nt][1] = bi0;
            of[nt][2] = bi1; of[nt][3] = bi1;
        }
#pragma unroll
        for (int ks = 0; ks < 4; ks++) {
            unsigned af[4];
            af[0] = sw3[o0 * WP + ks * 8 + tig];
            af[1] = sw3[(o0 + 8) * WP + ks * 8 + tig];
            af[2] = sw3[o0 * WP + ks * 8 + tig + 4];
            af[3] = sw3[(o0 + 8) * WP + ks * 8 + tig + 4];
#pragma unroll
            for (int nt = 0; nt < 16; nt++) {
                unsigned bf[2];
                bf[0] = sM[(ks * 8 + tig) * XP + nt * 8 + grp];
                bf[1] = sM[(ks * 8 + tig + 4) * XP + nt * 8 + grp];
                mma8(of[nt], af, bf);
            }
        }
#pragma unroll
        for (int nt = 0; nt < 16; nt++) {
            int lpos = sb + nt * 8 + 2 * tig;
            int idx0 = (b * C + o0) * TF + lpos;
            int idx1 = (b * C + o0 + 8) * TF + lpos;
            float2 x0 = *(const float2*)&x[idx0];
            float2 x1 = *(const float2*)&x[idx1];
            float y0 = of[nt][0], y1 = of[nt][1], y2 = of[nt][2], y3 = of[nt][3];
            y0 = y0 >= 0.f ? y0 : a3 * y0;
            y1 = y1 >= 0.f ? y1 : a3 * y1;
            y2 = y2 >= 0.f ? y2 : a3 * y2;
            y3 = y3 >= 0.f ? y3 : a3 * y3;
            *(float2*)&out[idx0] = make_float2(y0 + x0.x, y1 + x0.y);
            *(float2*)&out[idx1] = make_float2(y2 + x1.x, y3 + x1.y);
        }
    }
}

// ---------------------------------------------------------------------------
extern "C" void kernel_launch(void* const* d_in, const int* in_sizes, int n_in,
                              void* d_out, int out_size) {
    const float* x  = (const float*)d_in[0];
    const float* w1 = (const float*)d_in[1];
    const float* g1 = (const float*)d_in[2];
    const float* b1 = (const float*)d_in[3];
    const float* m1 = (const float*)d_in[4];
    const float* v1 = (const float*)d_in[5];
    const float* a1 = (const float*)d_in[6];
    const float* w2 = (const float*)d_in[7];
    const float* g2 = (const float*)d_in[8];
    const float* b2 = (const float*)d_in[9];
    const float* m2 = (const float*)d_in[10];
    const float* v2 = (const float*)d_in[11];
    const float* a2 = (const float*)d_in[12];
    const float* w3 = (const float*)d_in[13];
    const float* g3 = (const float*)d_in[14];
    const float* b3 = (const float*)d_in[15];
    const float* m3 = (const float*)d_in[16];
    const float* v3 = (const float*)d_in[17];
    const float* a3 = (const float*)d_in[18];
    float* out = (float*)d_out;

    prep_kernel<<<16, 256>>>(w1, g1, b1, m1, v1, w2, g2, b2, m2, v2,
                             w3, g3, b3, m3, v3);
    conv12_kernel<<<(B * T * Fd) / 128, 128>>>(x, a1, a2);
    freq_attn_kernel<<<B * T, 256>>>();
    time_attn_kernel<<<B * Fd, 256>>>();
    final_kernel<<<(B * T * Fd) / 128, 128>>>(x, a3, out);
}